// round 1
// baseline (speedup 1.0000x reference)
#include <cuda_runtime.h>
#include <cstddef>

// Problem constants
#define BB 16
#define LT 128
#define LV 4096
#define DD 1024
#define HH 16
#define HD 64
static constexpr float QSCALE = 0.125f;  // 64^-0.5

// ---------------------------------------------------------------------------
// Scratch (device globals — no allocations allowed)
// ---------------------------------------------------------------------------
__device__ float g_Q[(size_t)BB * LT * DD];        //   8 MB  (B*Lt, D) flat
__device__ float g_K[(size_t)BB * LV * DD];        // 256 MB  (B, Lv, D)
__device__ float g_V[(size_t)BB * LV * DD];        // 256 MB
__device__ float g_P[(size_t)BB * HH * LT * LV];   // 134 MB  (b,h,t,s)
__device__ float g_T[(size_t)BB * HH * LT * HD];   //   8 MB  (b,h,t,d)
__device__ float g_O[(size_t)BB * LV * DD];        // 256 MB  (b,s,D)

// ---------------------------------------------------------------------------
// Generic SGEMM:  C[M,N] = alpha * (A[M,K] @ B[K,N] + bias[N])
// A,B,C row-major. M%128==0, N%128==0, K%16==0.
// Block tile 128x128, BK=16, 256 threads, 8x8 microtile.
// ---------------------------------------------------------------------------
__global__ __launch_bounds__(256) void sgemm_bias(
    const float* __restrict__ A, const float* __restrict__ B,
    const float* __restrict__ bias, float* __restrict__ C,
    int M, int N, int K, float alpha)
{
    __shared__ float As[16][128];
    __shared__ float Bs[16][128];

    const int bx = blockIdx.x;   // N tile
    const int by = blockIdx.y;   // M tile
    const int tid = threadIdx.x;
    const int trow = (tid >> 4) * 8;   // 0..120
    const int tcol = (tid & 15) * 8;   // 0..120

    float acc[8][8];
#pragma unroll
    for (int i = 0; i < 8; i++)
#pragma unroll
        for (int j = 0; j < 8; j++) acc[i][j] = 0.f;

    const float* Ablk = A + (size_t)by * 128 * K;
    const float* Bblk = B + (size_t)bx * 128;

    for (int k0 = 0; k0 < K; k0 += 16) {
        // A tile: 128 rows x 16 cols = 512 float4, 2 per thread, store transposed
#pragma unroll
        for (int i = 0; i < 2; i++) {
            int id = tid + i * 256;
            int r  = id >> 2;          // 0..127
            int c4 = (id & 3) * 4;     // 0,4,8,12
            float4 v = *(const float4*)(Ablk + (size_t)r * K + k0 + c4);
            As[c4 + 0][r] = v.x; As[c4 + 1][r] = v.y;
            As[c4 + 2][r] = v.z; As[c4 + 3][r] = v.w;
        }
        // B tile: 16 rows x 128 cols = 512 float4, 2 per thread, direct
#pragma unroll
        for (int i = 0; i < 2; i++) {
            int id = tid + i * 256;
            int r  = id >> 5;          // 0..15
            int c4 = (id & 31) * 4;    // 0..124
            *(float4*)&Bs[r][c4] = *(const float4*)(Bblk + (size_t)(k0 + r) * N + c4);
        }
        __syncthreads();

#pragma unroll
        for (int kk = 0; kk < 16; kk++) {
            float a[8], b[8];
            *(float4*)&a[0] = *(float4*)&As[kk][trow];
            *(float4*)&a[4] = *(float4*)&As[kk][trow + 4];
            *(float4*)&b[0] = *(float4*)&Bs[kk][tcol];
            *(float4*)&b[4] = *(float4*)&Bs[kk][tcol + 4];
#pragma unroll
            for (int i = 0; i < 8; i++)
#pragma unroll
                for (int j = 0; j < 8; j++) acc[i][j] += a[i] * b[j];
        }
        __syncthreads();
    }

#pragma unroll
    for (int i = 0; i < 8; i++) {
        float* Crow = C + (size_t)(by * 128 + trow + i) * N + bx * 128 + tcol;
#pragma unroll
        for (int j = 0; j < 8; j += 4) {
            float4 o;
            o.x = alpha * (acc[i][j + 0] + bias[bx * 128 + tcol + j + 0]);
            o.y = alpha * (acc[i][j + 1] + bias[bx * 128 + tcol + j + 1]);
            o.z = alpha * (acc[i][j + 2] + bias[bx * 128 + tcol + j + 2]);
            o.w = alpha * (acc[i][j + 3] + bias[bx * 128 + tcol + j + 3]);
            *(float4*)&Crow[j] = o;
        }
    }
}

// ---------------------------------------------------------------------------
// Attention scores: S[b,h,t,s] = sum_d Q[b*LT+t, h*HD+d] * K[b,s, h*HD+d]
// Block tile: 128 t x 64 s, K=64 in 16-chunks. grid (LV/64, H, B)
// ---------------------------------------------------------------------------
__global__ __launch_bounds__(256) void attn_scores(
    const float* __restrict__ Q, const float* __restrict__ Km,
    float* __restrict__ P)
{
    const int st = blockIdx.x;
    const int h  = blockIdx.y;
    const int b  = blockIdx.z;

    __shared__ float Qs[16][128];   // [d][t]
    __shared__ float Ks[16][64];    // [d][s]

    const int tid = threadIdx.x;
    const int trow = (tid >> 4) * 8;   // t
    const int tcol = (tid & 15) * 4;   // s

    float acc[8][4];
#pragma unroll
    for (int i = 0; i < 8; i++)
#pragma unroll
        for (int j = 0; j < 4; j++) acc[i][j] = 0.f;

    const float* Qb = Q + (size_t)b * LT * DD + h * HD;            // rows t, ld DD
    const float* Kb = Km + ((size_t)b * LV + st * 64) * DD + h * HD; // rows s, ld DD

    for (int d0 = 0; d0 < HD; d0 += 16) {
        // Q chunk: 128 x 16 = 512 f4 -> 2/thread (transposed)
#pragma unroll
        for (int i = 0; i < 2; i++) {
            int id = tid + i * 256;
            int r  = id >> 2;
            int c4 = (id & 3) * 4;
            float4 v = *(const float4*)(Qb + (size_t)r * DD + d0 + c4);
            Qs[c4 + 0][r] = v.x; Qs[c4 + 1][r] = v.y;
            Qs[c4 + 2][r] = v.z; Qs[c4 + 3][r] = v.w;
        }
        // K chunk: 64 x 16 = 256 f4 -> 1/thread (transposed)
        {
            int r  = tid >> 2;           // 0..63
            int c4 = (tid & 3) * 4;
            float4 v = *(const float4*)(Kb + (size_t)r * DD + d0 + c4);
            Ks[c4 + 0][r] = v.x; Ks[c4 + 1][r] = v.y;
            Ks[c4 + 2][r] = v.z; Ks[c4 + 3][r] = v.w;
        }
        __syncthreads();
#pragma unroll
        for (int kk = 0; kk < 16; kk++) {
            float a[8], bv[4];
            *(float4*)&a[0] = *(float4*)&Qs[kk][trow];
            *(float4*)&a[4] = *(float4*)&Qs[kk][trow + 4];
            *(float4*)&bv[0] = *(float4*)&Ks[kk][tcol];
#pragma unroll
            for (int i = 0; i < 8; i++)
#pragma unroll
                for (int j = 0; j < 4; j++) acc[i][j] += a[i] * bv[j];
        }
        __syncthreads();
    }

    float* Pb = P + ((size_t)(b * HH + h) * LT) * LV + st * 64;
#pragma unroll
    for (int i = 0; i < 8; i++)
        *(float4*)&Pb[(size_t)(trow + i) * LV + tcol] = *(float4*)&acc[i][0];
}

// ---------------------------------------------------------------------------
// Row softmax over the last dim (LV=4096). One block per row.
// ---------------------------------------------------------------------------
__global__ __launch_bounds__(256) void softmax_rows(float* __restrict__ P)
{
    float4* p = (float4*)(P + (size_t)blockIdx.x * LV);
    const int tid = threadIdx.x;
    __shared__ float red[256];

    float mx = -1e30f;
#pragma unroll
    for (int i = 0; i < 4; i++) {
        float4 v = p[tid + i * 256];
        mx = fmaxf(mx, fmaxf(fmaxf(v.x, v.y), fmaxf(v.z, v.w)));
    }
    red[tid] = mx; __syncthreads();
    for (int s = 128; s > 0; s >>= 1) {
        if (tid < s) red[tid] = fmaxf(red[tid], red[tid + s]);
        __syncthreads();
    }
    mx = red[0]; __syncthreads();

    float sum = 0.f;
#pragma unroll
    for (int i = 0; i < 4; i++) {
        float4 v = p[tid + i * 256];
        v.x = __expf(v.x - mx); v.y = __expf(v.y - mx);
        v.z = __expf(v.z - mx); v.w = __expf(v.w - mx);
        p[tid + i * 256] = v;
        sum += v.x + v.y + v.z + v.w;
    }
    red[tid] = sum; __syncthreads();
    for (int s = 128; s > 0; s >>= 1) {
        if (tid < s) red[tid] += red[tid + s];
        __syncthreads();
    }
    const float inv = 1.f / red[0];
#pragma unroll
    for (int i = 0; i < 4; i++) {
        float4 v = p[tid + i * 256];
        v.x *= inv; v.y *= inv; v.z *= inv; v.w *= inv;
        p[tid + i * 256] = v;
    }
}

// ---------------------------------------------------------------------------
// tgv = P @ V : per (b,h): (128 x 4096) @ (4096 x 64).  grid (H, B)
// ---------------------------------------------------------------------------
__global__ __launch_bounds__(256) void attn_pv(
    const float* __restrict__ P, const float* __restrict__ V,
    float* __restrict__ T)
{
    const int h = blockIdx.x;
    const int b = blockIdx.y;

    __shared__ float Ps[16][128];   // [s][t]
    __shared__ float Vs[16][64];    // [s][d]

    const int tid = threadIdx.x;
    const int trow = (tid >> 4) * 8;   // t
    const int tcol = (tid & 15) * 4;   // d

    float acc[8][4];
#pragma unroll
    for (int i = 0; i < 8; i++)
#pragma unroll
        for (int j = 0; j < 4; j++) acc[i][j] = 0.f;

    const float* Pb = P + ((size_t)(b * HH + h) * LT) * LV;  // rows t, ld LV
    const float* Vb = V + (size_t)b * LV * DD + h * HD;      // rows s, ld DD

    for (int s0 = 0; s0 < LV; s0 += 16) {
        // P chunk: 128 x 16 = 512 f4 -> 2/thread (transposed)
#pragma unroll
        for (int i = 0; i < 2; i++) {
            int id = tid + i * 256;
            int r  = id >> 2;
            int c4 = (id & 3) * 4;
            float4 v = *(const float4*)(Pb + (size_t)r * LV + s0 + c4);
            Ps[c4 + 0][r] = v.x; Ps[c4 + 1][r] = v.y;
            Ps[c4 + 2][r] = v.z; Ps[c4 + 3][r] = v.w;
        }
        // V chunk: 16 x 64 = 256 f4 -> 1/thread (direct)
        {
            int r  = tid >> 4;           // 0..15
            int c4 = (tid & 15) * 4;
            *(float4*)&Vs[r][c4] = *(const float4*)(Vb + (size_t)(s0 + r) * DD + c4);
        }
        __syncthreads();
#pragma unroll
        for (int kk = 0; kk < 16; kk++) {
            float a[8], bv[4];
            *(float4*)&a[0] = *(float4*)&Ps[kk][trow];
            *(float4*)&a[4] = *(float4*)&Ps[kk][trow + 4];
            *(float4*)&bv[0] = *(float4*)&Vs[kk][tcol];
#pragma unroll
            for (int i = 0; i < 8; i++)
#pragma unroll
                for (int j = 0; j < 4; j++) acc[i][j] += a[i] * bv[j];
        }
        __syncthreads();
    }

    float* Tb = T + ((size_t)(b * HH + h) * LT) * HD;
#pragma unroll
    for (int i = 0; i < 8; i++)
        *(float4*)&Tb[(size_t)(trow + i) * HD + tcol] = *(float4*)&acc[i][0];
}

// ---------------------------------------------------------------------------
// O[b, s, h*HD+d] = sum_t P[b,h,t,s] * T[b,h,t,d].  grid (LV/64, H, B)
// Block tile: 64 s x 64 d, K=128 in 16-chunks.
// ---------------------------------------------------------------------------
__global__ __launch_bounds__(256) void attn_out(
    const float* __restrict__ P, const float* __restrict__ T,
    float* __restrict__ O)
{
    const int st = blockIdx.x;
    const int h  = blockIdx.y;
    const int b  = blockIdx.z;

    __shared__ float Ps[16][64];    // [t][s]
    __shared__ float Ts[16][64];    // [t][d]

    const int tid = threadIdx.x;
    const int srow = (tid >> 4) * 4;   // s
    const int dcol = (tid & 15) * 4;   // d

    float acc[4][4];
#pragma unroll
    for (int i = 0; i < 4; i++)
#pragma unroll
        for (int j = 0; j < 4; j++) acc[i][j] = 0.f;

    const float* Pb = P + ((size_t)(b * HH + h) * LT) * LV + st * 64;  // row t, ld LV
    const float* Tb = T + ((size_t)(b * HH + h) * LT) * HD;            // row t, ld HD

    for (int t0 = 0; t0 < LT; t0 += 16) {
        {
            int r  = tid >> 4;           // 0..15
            int c4 = (tid & 15) * 4;
            *(float4*)&Ps[r][c4] = *(const float4*)(Pb + (size_t)(t0 + r) * LV + c4);
            *(float4*)&Ts[r][c4] = *(const float4*)(Tb + (size_t)(t0 + r) * HD + c4);
        }
        __syncthreads();
#pragma unroll
        for (int kk = 0; kk < 16; kk++) {
            float a[4], bv[4];
            *(float4*)&a[0]  = *(float4*)&Ps[kk][srow];
            *(float4*)&bv[0] = *(float4*)&Ts[kk][dcol];
#pragma unroll
            for (int i = 0; i < 4; i++)
#pragma unroll
                for (int j = 0; j < 4; j++) acc[i][j] += a[i] * bv[j];
        }
        __syncthreads();
    }

    // write into (b, s, D) with channel offset h*HD
#pragma unroll
    for (int i = 0; i < 4; i++) {
        float* Orow = O + ((size_t)b * LV + st * 64 + srow + i) * DD + h * HD + dcol;
        *(float4*)Orow = *(float4*)&acc[i][0];
    }
}

// ---------------------------------------------------------------------------
// Launch
// ---------------------------------------------------------------------------
extern "C" void kernel_launch(void* const* d_in, const int* in_sizes, int n_in,
                              void* d_out, int out_size)
{
    const float* hidden = (const float*)d_in[0];  // (B, LV, D)
    const float* text   = (const float*)d_in[1];  // (LT, B, D) -> flat (2048, D)
    const float* Wq = (const float*)d_in[2];
    const float* bq = (const float*)d_in[3];
    const float* Wk = (const float*)d_in[4];
    const float* bk = (const float*)d_in[5];
    const float* Wv = (const float*)d_in[6];
    const float* bv = (const float*)d_in[7];
    const float* Wo = (const float*)d_in[8];
    const float* bo = (const float*)d_in[9];
    float* out = (float*)d_out;

    float *Q, *K, *V, *P, *T, *O;
    cudaGetSymbolAddress((void**)&Q, g_Q);
    cudaGetSymbolAddress((void**)&K, g_K);
    cudaGetSymbolAddress((void**)&V, g_V);
    cudaGetSymbolAddress((void**)&P, g_P);
    cudaGetSymbolAddress((void**)&T, g_T);
    cudaGetSymbolAddress((void**)&O, g_O);

    // Q projection (scale folded in). Note: the reference's .view-based
    // (Ltext,B)->(B,Ltext) reshape is an identity permutation on the flat
    // 2048-row matrix, so batch b simply reads rows [128b, 128b+128).
    dim3 gq(DD / 128, (BB * LT) / 128);
    sgemm_bias<<<gq, 256>>>(text, Wq, bq, Q, BB * LT, DD, DD, QSCALE);

    dim3 gkv(DD / 128, (BB * LV) / 128);
    sgemm_bias<<<gkv, 256>>>(hidden, Wk, bk, K, BB * LV, DD, DD, 1.0f);
    sgemm_bias<<<gkv, 256>>>(hidden, Wv, bv, V, BB * LV, DD, DD, 1.0f);

    attn_scores<<<dim3(LV / 64, HH, BB), 256>>>(Q, K, P);
    softmax_rows<<<BB * HH * LT, 256>>>(P);
    attn_pv<<<dim3(HH, BB), 256>>>(P, V, T);
    attn_out<<<dim3(LV / 64, HH, BB), 256>>>(P, T, O);

    sgemm_bias<<<gkv, 256>>>(O, Wo, bo, out, BB * LV, DD, DD, 1.0f);
}

// round 3
// speedup vs baseline: 1.8566x; 1.8566x over previous
#include <cuda_runtime.h>
#include <cuda_bf16.h>
#include <cstdint>
#include <cstddef>

// Problem constants
#define BB 16
#define LT 128
#define LV 4096
#define DD 1024
#define HH 16
#define HD 64
static constexpr float QSCALE = 0.125f;  // 64^-0.5

// ===========================================================================
// Scratch (device globals)
// ===========================================================================
__device__ __nv_bfloat16 g_txh[(size_t)BB * LT * DD];
__device__ __nv_bfloat16 g_txl[(size_t)BB * LT * DD];
__device__ __nv_bfloat16 g_hdh[(size_t)BB * LV * DD];
__device__ __nv_bfloat16 g_hdl[(size_t)BB * LV * DD];
__device__ __nv_bfloat16 g_Wh[4][(size_t)DD * DD];   // W^T hi  (N,K) layout
__device__ __nv_bfloat16 g_Wl[4][(size_t)DD * DD];   // W^T lo
__device__ float g_Q[(size_t)BB * LT * DD];
__device__ float g_K[(size_t)BB * LV * DD];
__device__ float g_V[(size_t)BB * LV * DD];
__device__ float g_P[(size_t)BB * HH * LT * LV];
__device__ float g_T[(size_t)BB * HH * LT * HD];
__device__ float g_Tp[8][(size_t)BB * HH * LT * HD];
__device__ __nv_bfloat16 g_Ohi[(size_t)BB * LV * DD];
__device__ __nv_bfloat16 g_Olo[(size_t)BB * LV * DD];

// ===========================================================================
// PTX helpers (arch-portable: sm_80-class instructions only)
// ===========================================================================
__device__ __forceinline__ uint32_t smem_u32(const void* p) {
    uint32_t a;
    asm("{ .reg .u64 t; cvta.to.shared.u64 t, %1; cvt.u32.u64 %0, t; }" : "=r"(a) : "l"(p));
    return a;
}
__device__ __forceinline__ void cp_async16(uint32_t dst, const void* src) {
    asm volatile("cp.async.cg.shared.global [%0], [%1], 16;" :: "r"(dst), "l"(src));
}
__device__ __forceinline__ void cp_commit() { asm volatile("cp.async.commit_group;"); }
template <int N>
__device__ __forceinline__ void cp_wait() { asm volatile("cp.async.wait_group %0;" :: "n"(N)); }

__device__ __forceinline__ void ldm_x4(uint32_t* r, uint32_t addr) {
    asm volatile("ldmatrix.sync.aligned.m8n8.x4.shared.b16 {%0,%1,%2,%3}, [%4];"
                 : "=r"(r[0]), "=r"(r[1]), "=r"(r[2]), "=r"(r[3]) : "r"(addr));
}
__device__ __forceinline__ void mma16816(float* c, const uint32_t* a, const uint32_t* b) {
    asm volatile(
        "mma.sync.aligned.m16n8k16.row.col.f32.bf16.bf16.f32 "
        "{%0,%1,%2,%3}, {%4,%5,%6,%7}, {%8,%9}, {%0,%1,%2,%3};"
        : "+f"(c[0]), "+f"(c[1]), "+f"(c[2]), "+f"(c[3])
        : "r"(a[0]), "r"(a[1]), "r"(a[2]), "r"(a[3]), "r"(b[0]), "r"(b[1]));
}

// ===========================================================================
// fp32 -> bf16 hi/lo split (elementwise)
// ===========================================================================
__global__ __launch_bounds__(256) void split_hl(
    const float* __restrict__ in, __nv_bfloat16* __restrict__ hi,
    __nv_bfloat16* __restrict__ lo, size_t n)
{
    size_t i = ((size_t)blockIdx.x * 256 + threadIdx.x) * 4;
    if (i >= n) return;
    float4 v = *(const float4*)(in + i);
    __nv_bfloat16 h0 = __float2bfloat16(v.x), h1 = __float2bfloat16(v.y);
    __nv_bfloat16 h2 = __float2bfloat16(v.z), h3 = __float2bfloat16(v.w);
    __nv_bfloat16 l0 = __float2bfloat16(v.x - __bfloat162float(h0));
    __nv_bfloat16 l1 = __float2bfloat16(v.y - __bfloat162float(h1));
    __nv_bfloat16 l2 = __float2bfloat16(v.z - __bfloat162float(h2));
    __nv_bfloat16 l3 = __float2bfloat16(v.w - __bfloat162float(h3));
    __nv_bfloat162* hp = (__nv_bfloat162*)(hi + i);
    __nv_bfloat162* lp = (__nv_bfloat162*)(lo + i);
    hp[0] = __nv_bfloat162(h0, h1); hp[1] = __nv_bfloat162(h2, h3);
    lp[0] = __nv_bfloat162(l0, l1); lp[1] = __nv_bfloat162(l2, l3);
}

// ===========================================================================
// Weight transpose + split: W [K=DD][N=DD] fp32 -> Wt hi/lo [N][K] bf16
// ===========================================================================
__global__ __launch_bounds__(256) void wsplit_t(
    const float* __restrict__ W, __nv_bfloat16* __restrict__ Th,
    __nv_bfloat16* __restrict__ Tl)
{
    __shared__ float t[32][33];
    int bx = blockIdx.x, by = blockIdx.y;
    int x = threadIdx.x, y = threadIdx.y;  // 32 x 8
#pragma unroll
    for (int i = 0; i < 32; i += 8)
        t[y + i][x] = W[(size_t)(by * 32 + y + i) * DD + bx * 32 + x];
    __syncthreads();
#pragma unroll
    for (int i = 0; i < 32; i += 8) {
        float v = t[x][y + i];   // = W[by*32+x][bx*32+y+i]
        __nv_bfloat16 h = __float2bfloat16(v);
        __nv_bfloat16 l = __float2bfloat16(v - __bfloat162float(h));
        size_t o = (size_t)(bx * 32 + y + i) * DD + by * 32 + x;
        Th[o] = h; Tl[o] = l;
    }
}

// ===========================================================================
// HMMA bf16x3 GEMM: C[M,N] = alpha*((Ah+Al) @ (Bh+Bl)^T + bias)
// Ah/Al: [M,K] bf16 row-major (lda). Bh/Bl: [N,K] bf16 row-major (ldb).
// Tile 128x128, BK=32, 8 warps (4m x 2n), warp tile 32x64.
// Double-buffered cp.async. Rows padded to 40 bf16 (80 B) = conflict-free.
// ===========================================================================
#define ROWB 80                       // padded row bytes (40 bf16)
#define TILE_T (128 * ROWB)           // 10240 B per operand tile
#define STAGE_B (4 * TILE_T)          // Ah, Al, Bh, Bl
#define SMEM_GEMM (2 * STAGE_B)       // 81920 B

__global__ __launch_bounds__(256) void gemm_bf16x3(
    const __nv_bfloat16* __restrict__ Ah, const __nv_bfloat16* __restrict__ Al,
    const __nv_bfloat16* __restrict__ Bh, const __nv_bfloat16* __restrict__ Bl,
    const float* __restrict__ bias, float* __restrict__ C,
    int M, int N, int K, int lda, int ldb, int ldc, float alpha)
{
    extern __shared__ char smem[];
    const uint32_t sb = smem_u32(smem);
    const int tid = threadIdx.x;
    const int wid = tid >> 5, lane = tid & 31;
    const int m0 = blockIdx.y * 128, n0 = blockIdx.x * 128;
    const int wm = (wid >> 1) * 32;        // warp m offset in tile
    const int wn = (wid & 1) * 64;         // warp n offset in tile

    const char* gA[4] = { (const char*)(Ah + (size_t)m0 * lda),
                          (const char*)(Al + (size_t)m0 * lda),
                          (const char*)(Bh + (size_t)n0 * ldb),
                          (const char*)(Bl + (size_t)n0 * ldb) };
    const int glds[4] = { lda, lda, ldb, ldb };

    float acc[2][8][4];
#pragma unroll
    for (int i = 0; i < 2; i++)
#pragma unroll
        for (int j = 0; j < 8; j++)
#pragma unroll
            for (int k = 0; k < 4; k++) acc[i][j][k] = 0.f;

    const int NT = K / 32;

    // stage copy: per operand 128 rows x 4 x 16B chunks = 512 cp.async
    auto issue = [&](int kt, int s) {
        const uint32_t st0 = sb + s * STAGE_B;
#pragma unroll
        for (int t = 0; t < 4; t++) {
            const char* g = gA[t] + (size_t)kt * 64;   // 32 bf16 = 64 B
            const int ldbytes = glds[t] * 2;
            const uint32_t tb = st0 + t * TILE_T;
#pragma unroll
            for (int i = 0; i < 2; i++) {
                int id = tid + i * 256;     // 0..511
                int r = id >> 2;            // 0..127
                int c = id & 3;             // 16B chunk
                cp_async16(tb + r * ROWB + c * 16, g + (size_t)r * ldbytes + c * 16);
            }
        }
        cp_commit();
    };

    issue(0, 0);

    for (int kt = 0; kt < NT; kt++) {
        if (kt + 1 < NT) issue(kt + 1, (kt + 1) & 1);
        if (kt + 1 < NT) cp_wait<1>(); else cp_wait<0>();
        __syncthreads();

        const uint32_t st0 = sb + (kt & 1) * STAGE_B;
        const uint32_t Ahs = st0 + 0 * TILE_T;
        const uint32_t Als = st0 + 1 * TILE_T;
        const uint32_t Bhs = st0 + 2 * TILE_T;
        const uint32_t Bls = st0 + 3 * TILE_T;

#pragma unroll
        for (int ks = 0; ks < 2; ks++) {       // two k16 steps
            const int k16 = ks * 16;
            // A fragments: lanes 0-15 -> rows, lanes 16-31 -> +8 cols
            uint32_t ah[2][4], al[2][4];
#pragma unroll
            for (int mi = 0; mi < 2; mi++) {
                int row = wm + mi * 16 + (lane & 15);
                int col = k16 + ((lane >> 4) << 3);
                ldm_x4(ah[mi], Ahs + row * ROWB + col * 2);
                ldm_x4(al[mi], Als + row * ROWB + col * 2);
            }
            // B fragments: 4 x ldmatrix.x4, each covers 16 n-rows x 16 k
            uint32_t bh[4][4], bl[4][4];
#pragma unroll
            for (int bi = 0; bi < 4; bi++) {
                int nrow = wn + bi * 16 + (lane & 7) + ((lane >> 4) << 3);
                int col = k16 + (((lane >> 3) & 1) << 3);
                ldm_x4(bh[bi], Bhs + nrow * ROWB + col * 2);
                ldm_x4(bl[bi], Bls + nrow * ROWB + col * 2);
            }
#pragma unroll
            for (int mi = 0; mi < 2; mi++)
#pragma unroll
                for (int nb = 0; nb < 8; nb++) {
                    const uint32_t* bhp = &bh[nb >> 1][(nb & 1) * 2];
                    const uint32_t* blp = &bl[nb >> 1][(nb & 1) * 2];
                    mma16816(acc[mi][nb], ah[mi], bhp);
                    mma16816(acc[mi][nb], ah[mi], blp);
                    mma16816(acc[mi][nb], al[mi], bhp);
                }
        }
        __syncthreads();
    }

    // epilogue
    const int gid = lane >> 2, tig = lane & 3;
#pragma unroll
    for (int mi = 0; mi < 2; mi++) {
        int r0 = m0 + wm + mi * 16 + gid;
#pragma unroll
        for (int nb = 0; nb < 8; nb++) {
            int c = n0 + wn + nb * 8 + tig * 2;
            float b0 = __ldg(&bias[c]), b1 = __ldg(&bias[c + 1]);
            float2 o0, o1;
            o0.x = alpha * (acc[mi][nb][0] + b0);
            o0.y = alpha * (acc[mi][nb][1] + b1);
            o1.x = alpha * (acc[mi][nb][2] + b0);
            o1.y = alpha * (acc[mi][nb][3] + b1);
            *(float2*)(C + (size_t)r0 * ldc + c) = o0;
            *(float2*)(C + (size_t)(r0 + 8) * ldc + c) = o1;
        }
    }
}

// ===========================================================================
// Attention scores (fp32): S[b,h,t,s] = Q . K  (128t x 64s tile)
// ===========================================================================
__global__ __launch_bounds__(256) void attn_scores(
    const float* __restrict__ Q, const float* __restrict__ Km, float* __restrict__ P)
{
    const int st = blockIdx.x, h = blockIdx.y, b = blockIdx.z;
    __shared__ float Qs[16][128];
    __shared__ float Ks[16][64];
    const int tid = threadIdx.x;
    const int trow = (tid >> 4) * 8;
    const int tcol = (tid & 15) * 4;

    float acc[8][4];
#pragma unroll
    for (int i = 0; i < 8; i++)
#pragma unroll
        for (int j = 0; j < 4; j++) acc[i][j] = 0.f;

    const float* Qb = Q + (size_t)b * LT * DD + h * HD;
    const float* Kb = Km + ((size_t)b * LV + st * 64) * DD + h * HD;

    for (int d0 = 0; d0 < HD; d0 += 16) {
#pragma unroll
        for (int i = 0; i < 2; i++) {
            int id = tid + i * 256;
            int r = id >> 2, c4 = (id & 3) * 4;
            float4 v = *(const float4*)(Qb + (size_t)r * DD + d0 + c4);
            Qs[c4 + 0][r] = v.x; Qs[c4 + 1][r] = v.y;
            Qs[c4 + 2][r] = v.z; Qs[c4 + 3][r] = v.w;
        }
        {
            int r = tid >> 2, c4 = (tid & 3) * 4;
            float4 v = *(const float4*)(Kb + (size_t)r * DD + d0 + c4);
            Ks[c4 + 0][r] = v.x; Ks[c4 + 1][r] = v.y;
            Ks[c4 + 2][r] = v.z; Ks[c4 + 3][r] = v.w;
        }
        __syncthreads();
#pragma unroll
        for (int kk = 0; kk < 16; kk++) {
            float a[8], bv[4];
            *(float4*)&a[0] = *(float4*)&Qs[kk][trow];
            *(float4*)&a[4] = *(float4*)&Qs[kk][trow + 4];
            *(float4*)&bv[0] = *(float4*)&Ks[kk][tcol];
#pragma unroll
            for (int i = 0; i < 8; i++)
#pragma unroll
                for (int j = 0; j < 4; j++) acc[i][j] += a[i] * bv[j];
        }
        __syncthreads();
    }
    float* Pb = P + ((size_t)(b * HH + h) * LT) * LV + st * 64;
#pragma unroll
    for (int i = 0; i < 8; i++)
        *(float4*)&Pb[(size_t)(trow + i) * LV + tcol] = *(float4*)&acc[i][0];
}

// ===========================================================================
// Fused single-pass softmax over last dim (LV), 16 elems/thread in registers
// ===========================================================================
__global__ __launch_bounds__(256) void softmax_fused(float* __restrict__ P)
{
    float4* p = (float4*)(P + (size_t)blockIdx.x * LV);
    const int tid = threadIdx.x;
    __shared__ float red[256];

    float4 v[4];
    float mx = -1e30f;
#pragma unroll
    for (int i = 0; i < 4; i++) {
        v[i] = p[tid + i * 256];
        mx = fmaxf(mx, fmaxf(fmaxf(v[i].x, v[i].y), fmaxf(v[i].z, v[i].w)));
    }
    red[tid] = mx; __syncthreads();
    for (int s = 128; s > 0; s >>= 1) {
        if (tid < s) red[tid] = fmaxf(red[tid], red[tid + s]);
        __syncthreads();
    }
    mx = red[0]; __syncthreads();

    float sum = 0.f;
#pragma unroll
    for (int i = 0; i < 4; i++) {
        v[i].x = __expf(v[i].x - mx); v[i].y = __expf(v[i].y - mx);
        v[i].z = __expf(v[i].z - mx); v[i].w = __expf(v[i].w - mx);
        sum += v[i].x + v[i].y + v[i].z + v[i].w;
    }
    red[tid] = sum; __syncthreads();
    for (int s = 128; s > 0; s >>= 1) {
        if (tid < s) red[tid] += red[tid + s];
        __syncthreads();
    }
    const float inv = 1.f / red[0];
#pragma unroll
    for (int i = 0; i < 4; i++) {
        v[i].x *= inv; v[i].y *= inv; v[i].z *= inv; v[i].w *= inv;
        p[tid + i * 256] = v[i];
    }
}

// ===========================================================================
// tgv partial = P @ V over s-segment. grid (8, H, B). 512 s per segment.
// ===========================================================================
__global__ __launch_bounds__(256) void attn_pv_seg(
    const float* __restrict__ P, const float* __restrict__ V, float* __restrict__ Tp)
{
    const int seg = blockIdx.x, h = blockIdx.y, b = blockIdx.z;
    __shared__ float Ps[16][128];
    __shared__ float Vs[16][64];
    const int tid = threadIdx.x;
    const int trow = (tid >> 4) * 8;
    const int tcol = (tid & 15) * 4;

    float acc[8][4];
#pragma unroll
    for (int i = 0; i < 8; i++)
#pragma unroll
        for (int j = 0; j < 4; j++) acc[i][j] = 0.f;

    const float* Pb = P + ((size_t)(b * HH + h) * LT) * LV;
    const float* Vb = V + (size_t)b * LV * DD + h * HD;

    for (int s0 = seg * 512; s0 < (seg + 1) * 512; s0 += 16) {
#pragma unroll
        for (int i = 0; i < 2; i++) {
            int id = tid + i * 256;
            int r = id >> 2, c4 = (id & 3) * 4;
            float4 v = *(const float4*)(Pb + (size_t)r * LV + s0 + c4);
            Ps[c4 + 0][r] = v.x; Ps[c4 + 1][r] = v.y;
            Ps[c4 + 2][r] = v.z; Ps[c4 + 3][r] = v.w;
        }
        {
            int r = tid >> 4, c4 = (tid & 15) * 4;
            *(float4*)&Vs[r][c4] = *(const float4*)(Vb + (size_t)(s0 + r) * DD + c4);
        }
        __syncthreads();
#pragma unroll
        for (int kk = 0; kk < 16; kk++) {
            float a[8], bv[4];
            *(float4*)&a[0] = *(float4*)&Ps[kk][trow];
            *(float4*)&a[4] = *(float4*)&Ps[kk][trow + 4];
            *(float4*)&bv[0] = *(float4*)&Vs[kk][tcol];
#pragma unroll
            for (int i = 0; i < 8; i++)
#pragma unroll
                for (int j = 0; j < 4; j++) acc[i][j] += a[i] * bv[j];
        }
        __syncthreads();
    }
    float* Tb = Tp + (size_t)seg * (BB * HH * LT * HD) + ((size_t)(b * HH + h) * LT) * HD;
#pragma unroll
    for (int i = 0; i < 8; i++)
        *(float4*)&Tb[(size_t)(trow + i) * HD + tcol] = *(float4*)&acc[i][0];
}

__global__ __launch_bounds__(256) void reduce_T(const float* __restrict__ Tp, float* __restrict__ T)
{
    size_t i = (size_t)blockIdx.x * 256 + threadIdx.x;
    float s = 0.f;
#pragma unroll
    for (int g = 0; g < 8; g++) s += Tp[(size_t)g * (BB * HH * LT * HD) + i];
    T[i] = s;
}

// ===========================================================================
// O[b,s,h*HD+d] = sum_t P[b,h,t,s] * T[b,h,t,d]  -> bf16 hi/lo output
// ===========================================================================
__global__ __launch_bounds__(256) void attn_out(
    const float* __restrict__ P, const float* __restrict__ T,
    __nv_bfloat16* __restrict__ Ohi, __nv_bfloat16* __restrict__ Olo)
{
    const int st = blockIdx.x, h = blockIdx.y, b = blockIdx.z;
    __shared__ float Ps[16][64];
    __shared__ float Ts[16][64];
    const int tid = threadIdx.x;
    const int srow = (tid >> 4) * 4;
    const int dcol = (tid & 15) * 4;

    float acc[4][4];
#pragma unroll
    for (int i = 0; i < 4; i++)
#pragma unroll
        for (int j = 0; j < 4; j++) acc[i][j] = 0.f;

    const float* Pb = P + ((size_t)(b * HH + h) * LT) * LV + st * 64;
    const float* Tb = T + ((size_t)(b * HH + h) * LT) * HD;

    for (int t0 = 0; t0 < LT; t0 += 16) {
        {
            int r = tid >> 4, c4 = (tid & 15) * 4;
            *(float4*)&Ps[r][c4] = *(const float4*)(Pb + (size_t)(t0 + r) * LV + c4);
            *(float4*)&Ts[r][c4] = *(const float4*)(Tb + (size_t)(t0 + r) * HD + c4);
        }
        __syncthreads();
#pragma unroll
        for (int kk = 0; kk < 16; kk++) {
            float a[4], bv[4];
            *(float4*)&a[0] = *(float4*)&Ps[kk][srow];
            *(float4*)&bv[0] = *(float4*)&Ts[kk][dcol];
#pragma unroll
            for (int i = 0; i < 4; i++)
#pragma unroll
                for (int j = 0; j < 4; j++) acc[i][j] += a[i] * bv[j];
        }
        __syncthreads();
    }
#pragma unroll
    for (int i = 0; i < 4; i++) {
        size_t base = ((size_t)b * LV + st * 64 + srow + i) * DD + h * HD + dcol;
        __nv_bfloat16 hv[4], lv[4];
#pragma unroll
        for (int j = 0; j < 4; j++) {
            hv[j] = __float2bfloat16(acc[i][j]);
            lv[j] = __float2bfloat16(acc[i][j] - __bfloat162float(hv[j]));
        }
        *(__nv_bfloat162*)(Ohi + base)     = __nv_bfloat162(hv[0], hv[1]);
        *(__nv_bfloat162*)(Ohi + base + 2) = __nv_bfloat162(hv[2], hv[3]);
        *(__nv_bfloat162*)(Olo + base)     = __nv_bfloat162(lv[0], lv[1]);
        *(__nv_bfloat162*)(Olo + base + 2) = __nv_bfloat162(lv[2], lv[3]);
    }
}

// ===========================================================================
// Launch
// ===========================================================================
extern "C" void kernel_launch(void* const* d_in, const int* in_sizes, int n_in,
                              void* d_out, int out_size)
{
    const float* hidden = (const float*)d_in[0];
    const float* text   = (const float*)d_in[1];
    const float* Wq = (const float*)d_in[2];
    const float* bq = (const float*)d_in[3];
    const float* Wk = (const float*)d_in[4];
    const float* bk = (const float*)d_in[5];
    const float* Wv = (const float*)d_in[6];
    const float* bv = (const float*)d_in[7];
    const float* Wo = (const float*)d_in[8];
    const float* bo = (const float*)d_in[9];
    float* out = (float*)d_out;

    __nv_bfloat16 *txh, *txl, *hdh, *hdl, *Wh, *Wl, *Ohi, *Olo;
    float *Q, *K, *V, *P, *T, *Tp;
    cudaGetSymbolAddress((void**)&txh, g_txh);
    cudaGetSymbolAddress((void**)&txl, g_txl);
    cudaGetSymbolAddress((void**)&hdh, g_hdh);
    cudaGetSymbolAddress((void**)&hdl, g_hdl);
    cudaGetSymbolAddress((void**)&Wh, g_Wh);
    cudaGetSymbolAddress((void**)&Wl, g_Wl);
    cudaGetSymbolAddress((void**)&Q, g_Q);
    cudaGetSymbolAddress((void**)&K, g_K);
    cudaGetSymbolAddress((void**)&V, g_V);
    cudaGetSymbolAddress((void**)&P, g_P);
    cudaGetSymbolAddress((void**)&T, g_T);
    cudaGetSymbolAddress((void**)&Tp, g_Tp);
    cudaGetSymbolAddress((void**)&Ohi, g_Ohi);
    cudaGetSymbolAddress((void**)&Olo, g_Olo);

    cudaFuncSetAttribute(gemm_bf16x3, cudaFuncAttributeMaxDynamicSharedMemorySize, SMEM_GEMM);

    const size_t WSZ = (size_t)DD * DD;

    // 1. input splits
    split_hl<<<(BB * LT * DD) / 1024, 256>>>(text, txh, txl, (size_t)BB * LT * DD);
    split_hl<<<(BB * LV * DD) / 1024, 256>>>(hidden, hdh, hdl, (size_t)BB * LV * DD);

    // 2. weight transpose + split
    dim3 wt(32, 32);
    wsplit_t<<<wt, dim3(32, 8)>>>(Wq, Wh + 0 * WSZ, Wl + 0 * WSZ);
    wsplit_t<<<wt, dim3(32, 8)>>>(Wk, Wh + 1 * WSZ, Wl + 1 * WSZ);
    wsplit_t<<<wt, dim3(32, 8)>>>(Wv, Wh + 2 * WSZ, Wl + 2 * WSZ);
    wsplit_t<<<wt, dim3(32, 8)>>>(Wo, Wh + 3 * WSZ, Wl + 3 * WSZ);

    // 3. projections (HMMA tensor cores)
    gemm_bf16x3<<<dim3(DD / 128, (BB * LT) / 128), 256, SMEM_GEMM>>>(
        txh, txl, Wh + 0 * WSZ, Wl + 0 * WSZ, bq, Q, BB * LT, DD, DD, DD, DD, DD, QSCALE);
    gemm_bf16x3<<<dim3(DD / 128, (BB * LV) / 128), 256, SMEM_GEMM>>>(
        hdh, hdl, Wh + 1 * WSZ, Wl + 1 * WSZ, bk, K, BB * LV, DD, DD, DD, DD, DD, 1.0f);
    gemm_bf16x3<<<dim3(DD / 128, (BB * LV) / 128), 256, SMEM_GEMM>>>(
        hdh, hdl, Wh + 2 * WSZ, Wl + 2 * WSZ, bv, V, BB * LV, DD, DD, DD, DD, DD, 1.0f);

    // 4. attention (fp32 this round)
    attn_scores<<<dim3(LV / 64, HH, BB), 256>>>(Q, K, P);
    softmax_fused<<<BB * HH * LT, 256>>>(P);
    attn_pv_seg<<<dim3(8, HH, BB), 256>>>(P, V, Tp);
    reduce_T<<<(BB * HH * LT * HD) / 256, 256>>>(Tp, T);
    attn_out<<<dim3(LV / 64, HH, BB), 256>>>(P, T, Ohi, Olo);

    // 5. output projection (HMMA tensor cores)
    gemm_bf16x3<<<dim3(DD / 128, (BB * LV) / 128), 256, SMEM_GEMM>>>(
        Ohi, Olo, Wh + 3 * WSZ, Wl + 3 * WSZ, bo, out, BB * LV, DD, DD, DD, DD, DD, 1.0f);
}

// round 5
// speedup vs baseline: 2.0789x; 1.1197x over previous
#include <cuda_runtime.h>
#include <cuda_bf16.h>
#include <cstdint>
#include <cstddef>

// Problem constants
#define BB 16
#define LT 128
#define LV 4096
#define DD 1024
#define HH 16
#define HD 64
static constexpr float QSCALE = 0.125f;  // 64^-0.5

// ===========================================================================
// Scratch (device globals)
// ===========================================================================
__device__ __nv_bfloat16 g_txh[(size_t)BB * LT * DD];
__device__ __nv_bfloat16 g_txl[(size_t)BB * LT * DD];
__device__ __nv_bfloat16 g_hdh[(size_t)BB * LV * DD];
__device__ __nv_bfloat16 g_hdl[(size_t)BB * LV * DD];
__device__ __nv_bfloat16 g_Wh[4][(size_t)DD * DD];   // W^T hi  (N,K) layout
__device__ __nv_bfloat16 g_Wl[4][(size_t)DD * DD];   // W^T lo
__device__ __nv_bfloat16 g_Qh[(size_t)BB * LT * DD];
__device__ __nv_bfloat16 g_Ql[(size_t)BB * LT * DD];
__device__ __nv_bfloat16 g_Kh[(size_t)BB * LV * DD];
__device__ __nv_bfloat16 g_Kl[(size_t)BB * LV * DD];
__device__ __nv_bfloat16 g_Vh[(size_t)BB * LV * DD];
__device__ __nv_bfloat16 g_Vl[(size_t)BB * LV * DD];
__device__ float g_S[(size_t)BB * HH * LT * LV];              // scores fp32
__device__ __nv_bfloat16 g_Ph[(size_t)BB * HH * LT * LV];     // softmax hi
__device__ __nv_bfloat16 g_Pl[(size_t)BB * HH * LT * LV];     // softmax lo
__device__ float g_Tp[8][(size_t)BB * HH * LT * HD];          // PV partials
__device__ __nv_bfloat16 g_Th[(size_t)BB * HH * LT * HD];
__device__ __nv_bfloat16 g_Tl[(size_t)BB * HH * LT * HD];
__device__ __nv_bfloat16 g_Ohi[(size_t)BB * LV * DD];
__device__ __nv_bfloat16 g_Olo[(size_t)BB * LV * DD];

// ===========================================================================
// PTX helpers (arch-portable)
// ===========================================================================
__device__ __forceinline__ uint32_t smem_u32(const void* p) {
    uint32_t a;
    asm("{ .reg .u64 t; cvta.to.shared.u64 t, %1; cvt.u32.u64 %0, t; }" : "=r"(a) : "l"(p));
    return a;
}
__device__ __forceinline__ void cp_async16(uint32_t dst, const void* src) {
    asm volatile("cp.async.cg.shared.global [%0], [%1], 16;" :: "r"(dst), "l"(src));
}
__device__ __forceinline__ void cp_commit() { asm volatile("cp.async.commit_group;"); }
template <int N>
__device__ __forceinline__ void cp_wait() { asm volatile("cp.async.wait_group %0;" :: "n"(N)); }

__device__ __forceinline__ void ldm_x4(uint32_t* r, uint32_t addr) {
    asm volatile("ldmatrix.sync.aligned.m8n8.x4.shared.b16 {%0,%1,%2,%3}, [%4];"
                 : "=r"(r[0]), "=r"(r[1]), "=r"(r[2]), "=r"(r[3]) : "r"(addr));
}
__device__ __forceinline__ void ldm_x4_t(uint32_t* r, uint32_t addr) {
    asm volatile("ldmatrix.sync.aligned.m8n8.x4.trans.shared.b16 {%0,%1,%2,%3}, [%4];"
                 : "=r"(r[0]), "=r"(r[1]), "=r"(r[2]), "=r"(r[3]) : "r"(addr));
}
__device__ __forceinline__ void mma16816(float* c, const uint32_t* a, const uint32_t* b) {
    asm volatile(
        "mma.sync.aligned.m16n8k16.row.col.f32.bf16.bf16.f32 "
        "{%0,%1,%2,%3}, {%4,%5,%6,%7}, {%8,%9}, {%0,%1,%2,%3};"
        : "+f"(c[0]), "+f"(c[1]), "+f"(c[2]), "+f"(c[3])
        : "r"(a[0]), "r"(a[1]), "r"(a[2]), "r"(a[3]), "r"(b[0]), "r"(b[1]));
}
// variant with separate b regs (for trans-loaded B where k-halves are regs j, j+2)
__device__ __forceinline__ void mma16816v(float* c, const uint32_t* a, uint32_t b0, uint32_t b1) {
    asm volatile(
        "mma.sync.aligned.m16n8k16.row.col.f32.bf16.bf16.f32 "
        "{%0,%1,%2,%3}, {%4,%5,%6,%7}, {%8,%9}, {%0,%1,%2,%3};"
        : "+f"(c[0]), "+f"(c[1]), "+f"(c[2]), "+f"(c[3])
        : "r"(a[0]), "r"(a[1]), "r"(a[2]), "r"(a[3]), "r"(b0), "r"(b1));
}
__device__ __forceinline__ void split1(float v, __nv_bfloat16& h, __nv_bfloat16& l) {
    h = __float2bfloat16(v);
    l = __float2bfloat16(v - __bfloat162float(h));
}

// ===========================================================================
// fp32 -> bf16 hi/lo split (elementwise)
// ===========================================================================
__global__ __launch_bounds__(256) void split_hl(
    const float* __restrict__ in, __nv_bfloat16* __restrict__ hi,
    __nv_bfloat16* __restrict__ lo, size_t n)
{
    size_t i = ((size_t)blockIdx.x * 256 + threadIdx.x) * 4;
    if (i >= n) return;
    float4 v = *(const float4*)(in + i);
    __nv_bfloat16 h0, h1, h2, h3, l0, l1, l2, l3;
    split1(v.x, h0, l0); split1(v.y, h1, l1);
    split1(v.z, h2, l2); split1(v.w, h3, l3);
    __nv_bfloat162* hp = (__nv_bfloat162*)(hi + i);
    __nv_bfloat162* lp = (__nv_bfloat162*)(lo + i);
    hp[0] = __nv_bfloat162(h0, h1); hp[1] = __nv_bfloat162(h2, h3);
    lp[0] = __nv_bfloat162(l0, l1); lp[1] = __nv_bfloat162(l2, l3);
}

// ===========================================================================
// Weight transpose + split: W [K=DD][N=DD] fp32 -> Wt hi/lo [N][K] bf16
// ===========================================================================
__global__ __launch_bounds__(256) void wsplit_t(
    const float* __restrict__ W, __nv_bfloat16* __restrict__ Th,
    __nv_bfloat16* __restrict__ Tl)
{
    __shared__ float t[32][33];
    int bx = blockIdx.x, by = blockIdx.y;
    int x = threadIdx.x, y = threadIdx.y;
#pragma unroll
    for (int i = 0; i < 32; i += 8)
        t[y + i][x] = W[(size_t)(by * 32 + y + i) * DD + bx * 32 + x];
    __syncthreads();
#pragma unroll
    for (int i = 0; i < 32; i += 8) {
        float v = t[x][y + i];
        __nv_bfloat16 h, l; split1(v, h, l);
        size_t o = (size_t)(bx * 32 + y + i) * DD + by * 32 + x;
        Th[o] = h; Tl[o] = l;
    }
}

// ===========================================================================
// HMMA bf16x3 GEMM (projections): C = alpha*((Ah+Al) @ (Bh+Bl)^T + bias)
// Tile 128x128, BK=32, 8 warps 4x2, warp 32x64. 3-stage cp.async.
// OUTMODE 0: fp32 C.  OUTMODE 1: bf16 hi/lo pair Ch/Cl.
// ===========================================================================
#define ROWB 80
#define TILE_T (128 * ROWB)
#define STAGE_B (4 * TILE_T)
#define SMEM_GEMM (3 * STAGE_B)   // 122880

template <int OUTMODE>
__global__ __launch_bounds__(256) void gemm_bf16x3(
    const __nv_bfloat16* __restrict__ Ah, const __nv_bfloat16* __restrict__ Al,
    const __nv_bfloat16* __restrict__ Bh, const __nv_bfloat16* __restrict__ Bl,
    const float* __restrict__ bias, float* __restrict__ C,
    __nv_bfloat16* __restrict__ Ch, __nv_bfloat16* __restrict__ Cl,
    int M, int N, int K, int lda, int ldb, int ldc, float alpha)
{
    extern __shared__ char smem[];
    const uint32_t sb = smem_u32(smem);
    const int tid = threadIdx.x;
    const int wid = tid >> 5, lane = tid & 31;
    const int m0 = blockIdx.y * 128, n0 = blockIdx.x * 128;
    const int wm = (wid >> 1) * 32;
    const int wn = (wid & 1) * 64;

    const char* gA[4] = { (const char*)(Ah + (size_t)m0 * lda),
                          (const char*)(Al + (size_t)m0 * lda),
                          (const char*)(Bh + (size_t)n0 * ldb),
                          (const char*)(Bl + (size_t)n0 * ldb) };
    const int glds[4] = { lda, lda, ldb, ldb };

    float acc[2][8][4];
#pragma unroll
    for (int i = 0; i < 2; i++)
#pragma unroll
        for (int j = 0; j < 8; j++)
#pragma unroll
            for (int k = 0; k < 4; k++) acc[i][j][k] = 0.f;

    const int NT = K / 32;

    auto issue = [&](int kt, int s) {
        const uint32_t st0 = sb + s * STAGE_B;
#pragma unroll
        for (int t = 0; t < 4; t++) {
            const char* g = gA[t] + (size_t)kt * 64;
            const int ldbytes = glds[t] * 2;
            const uint32_t tb = st0 + t * TILE_T;
#pragma unroll
            for (int i = 0; i < 2; i++) {
                int id = tid + i * 256;
                int r = id >> 2, c = id & 3;
                cp_async16(tb + r * ROWB + c * 16, g + (size_t)r * ldbytes + c * 16);
            }
        }
        cp_commit();
    };

    issue(0, 0);
    issue(1, 1);

    for (int kt = 0; kt < NT; kt++) {
        if (kt + 2 < NT) { issue(kt + 2, (kt + 2) % 3); cp_wait<2>(); }
        else if (kt + 1 < NT) cp_wait<1>();
        else cp_wait<0>();
        __syncthreads();

        const uint32_t st0 = sb + (kt % 3) * STAGE_B;
        const uint32_t Ahs = st0 + 0 * TILE_T;
        const uint32_t Als = st0 + 1 * TILE_T;
        const uint32_t Bhs = st0 + 2 * TILE_T;
        const uint32_t Bls = st0 + 3 * TILE_T;

#pragma unroll
        for (int ks = 0; ks < 2; ks++) {
            const int k16 = ks * 16;
            uint32_t ah[2][4], al[2][4];
#pragma unroll
            for (int mi = 0; mi < 2; mi++) {
                int row = wm + mi * 16 + (lane & 15);
                int col = k16 + ((lane >> 4) << 3);
                ldm_x4(ah[mi], Ahs + row * ROWB + col * 2);
                ldm_x4(al[mi], Als + row * ROWB + col * 2);
            }
            uint32_t bh[4][4], bl[4][4];
#pragma unroll
            for (int bi = 0; bi < 4; bi++) {
                int nrow = wn + bi * 16 + (lane & 7) + ((lane >> 4) << 3);
                int col = k16 + (((lane >> 3) & 1) << 3);
                ldm_x4(bh[bi], Bhs + nrow * ROWB + col * 2);
                ldm_x4(bl[bi], Bls + nrow * ROWB + col * 2);
            }
#pragma unroll
            for (int mi = 0; mi < 2; mi++)
#pragma unroll
                for (int nb = 0; nb < 8; nb++) {
                    const uint32_t* bhp = &bh[nb >> 1][(nb & 1) * 2];
                    const uint32_t* blp = &bl[nb >> 1][(nb & 1) * 2];
                    mma16816(acc[mi][nb], ah[mi], bhp);
                    mma16816(acc[mi][nb], ah[mi], blp);
                    mma16816(acc[mi][nb], al[mi], bhp);
                }
        }
        __syncthreads();
    }

    const int gid = lane >> 2, tig = lane & 3;
#pragma unroll
    for (int mi = 0; mi < 2; mi++) {
        int r0 = m0 + wm + mi * 16 + gid;
#pragma unroll
        for (int nb = 0; nb < 8; nb++) {
            int c = n0 + wn + nb * 8 + tig * 2;
            float b0 = __ldg(&bias[c]), b1 = __ldg(&bias[c + 1]);
            float v00 = alpha * (acc[mi][nb][0] + b0);
            float v01 = alpha * (acc[mi][nb][1] + b1);
            float v10 = alpha * (acc[mi][nb][2] + b0);
            float v11 = alpha * (acc[mi][nb][3] + b1);
            if (OUTMODE == 0) {
                *(float2*)(C + (size_t)r0 * ldc + c) = make_float2(v00, v01);
                *(float2*)(C + (size_t)(r0 + 8) * ldc + c) = make_float2(v10, v11);
            } else {
                __nv_bfloat16 h0, h1, h2, h3, l0, l1, l2, l3;
                split1(v00, h0, l0); split1(v01, h1, l1);
                split1(v10, h2, l2); split1(v11, h3, l3);
                *(__nv_bfloat162*)(Ch + (size_t)r0 * ldc + c) = __nv_bfloat162(h0, h1);
                *(__nv_bfloat162*)(Cl + (size_t)r0 * ldc + c) = __nv_bfloat162(l0, l1);
                *(__nv_bfloat162*)(Ch + (size_t)(r0 + 8) * ldc + c) = __nv_bfloat162(h2, h3);
                *(__nv_bfloat162*)(Cl + (size_t)(r0 + 8) * ldc + c) = __nv_bfloat162(l2, l3);
            }
        }
    }
}

// ===========================================================================
// Scores (HMMA): S[b,h,t,s] = (Qh+Ql).(Kh+Kl)  M=128 t, N=128 s-tile, K=64
// ===========================================================================
#define SROWB 144                     // 64 bf16 = 128 B + 16 pad
#define STILE (128 * SROWB)
#define SMEM_SC (4 * STILE)           // 73728

__global__ __launch_bounds__(256) void attn_scores_mma(
    const __nv_bfloat16* __restrict__ Qh, const __nv_bfloat16* __restrict__ Ql,
    const __nv_bfloat16* __restrict__ Kh, const __nv_bfloat16* __restrict__ Kl,
    float* __restrict__ S)
{
    extern __shared__ char smem[];
    const uint32_t sb = smem_u32(smem);
    const int st = blockIdx.x, h = blockIdx.y, b = blockIdx.z;
    const int tid = threadIdx.x;
    const int wid = tid >> 5, lane = tid & 31;
    const int wm = (wid >> 1) * 32, wn = (wid & 1) * 64;

    const char* gp[4] = {
        (const char*)(Qh + ((size_t)b * LT) * DD + h * HD),
        (const char*)(Ql + ((size_t)b * LT) * DD + h * HD),
        (const char*)(Kh + ((size_t)b * LV + st * 128) * DD + h * HD),
        (const char*)(Kl + ((size_t)b * LV + st * 128) * DD + h * HD) };

#pragma unroll
    for (int i = 0; i < 16; i++) {
        int id = tid + i * 256;
        int t = id >> 10;
        int r = (id >> 3) & 127;
        int c = id & 7;
        cp_async16(sb + t * STILE + r * SROWB + c * 16,
                   gp[t] + (size_t)r * DD * 2 + c * 16);
    }
    cp_commit();
    cp_wait<0>();
    __syncthreads();

    float acc[2][8][4];
#pragma unroll
    for (int i = 0; i < 2; i++)
#pragma unroll
        for (int j = 0; j < 8; j++)
#pragma unroll
            for (int k = 0; k < 4; k++) acc[i][j][k] = 0.f;

    const uint32_t Ahs = sb, Als = sb + STILE, Bhs = sb + 2 * STILE, Bls = sb + 3 * STILE;

#pragma unroll
    for (int ks = 0; ks < 4; ks++) {
        const int k16 = ks * 16;
        uint32_t ah[2][4], al[2][4];
#pragma unroll
        for (int mi = 0; mi < 2; mi++) {
            int row = wm + mi * 16 + (lane & 15);
            int col = k16 + ((lane >> 4) << 3);
            ldm_x4(ah[mi], Ahs + row * SROWB + col * 2);
            ldm_x4(al[mi], Als + row * SROWB + col * 2);
        }
        uint32_t bh[4][4], bl[4][4];
#pragma unroll
        for (int bi = 0; bi < 4; bi++) {
            int nrow = wn + bi * 16 + (lane & 7) + ((lane >> 4) << 3);
            int col = k16 + (((lane >> 3) & 1) << 3);
            ldm_x4(bh[bi], Bhs + nrow * SROWB + col * 2);
            ldm_x4(bl[bi], Bls + nrow * SROWB + col * 2);
        }
#pragma unroll
        for (int mi = 0; mi < 2; mi++)
#pragma unroll
            for (int nb = 0; nb < 8; nb++) {
                const uint32_t* bhp = &bh[nb >> 1][(nb & 1) * 2];
                const uint32_t* blp = &bl[nb >> 1][(nb & 1) * 2];
                mma16816(acc[mi][nb], ah[mi], bhp);
                mma16816(acc[mi][nb], ah[mi], blp);
                mma16816(acc[mi][nb], al[mi], bhp);
            }
    }

    float* Sb = S + ((size_t)(b * HH + h) * LT) * LV + st * 128;
    const int gid = lane >> 2, tig = lane & 3;
#pragma unroll
    for (int mi = 0; mi < 2; mi++) {
        int r0 = wm + mi * 16 + gid;
#pragma unroll
        for (int nb = 0; nb < 8; nb++) {
            int c = wn + nb * 8 + tig * 2;
            *(float2*)(Sb + (size_t)r0 * LV + c) = make_float2(acc[mi][nb][0], acc[mi][nb][1]);
            *(float2*)(Sb + (size_t)(r0 + 8) * LV + c) = make_float2(acc[mi][nb][2], acc[mi][nb][3]);
        }
    }
}

// ===========================================================================
// Softmax over last dim (LV) -> bf16 hi/lo
// ===========================================================================
__global__ __launch_bounds__(256) void softmax_bf(
    const float* __restrict__ S, __nv_bfloat16* __restrict__ Ph,
    __nv_bfloat16* __restrict__ Pl)
{
    const float4* p = (const float4*)(S + (size_t)blockIdx.x * LV);
    __nv_bfloat16* ph = Ph + (size_t)blockIdx.x * LV;
    __nv_bfloat16* pl = Pl + (size_t)blockIdx.x * LV;
    const int tid = threadIdx.x;
    __shared__ float red[256];

    float4 v[4];
    float mx = -1e30f;
#pragma unroll
    for (int i = 0; i < 4; i++) {
        v[i] = p[tid + i * 256];
        mx = fmaxf(mx, fmaxf(fmaxf(v[i].x, v[i].y), fmaxf(v[i].z, v[i].w)));
    }
    red[tid] = mx; __syncthreads();
    for (int s = 128; s > 0; s >>= 1) {
        if (tid < s) red[tid] = fmaxf(red[tid], red[tid + s]);
        __syncthreads();
    }
    mx = red[0]; __syncthreads();

    float sum = 0.f;
#pragma unroll
    for (int i = 0; i < 4; i++) {
        v[i].x = __expf(v[i].x - mx); v[i].y = __expf(v[i].y - mx);
        v[i].z = __expf(v[i].z - mx); v[i].w = __expf(v[i].w - mx);
        sum += v[i].x + v[i].y + v[i].z + v[i].w;
    }
    red[tid] = sum; __syncthreads();
    for (int s = 128; s > 0; s >>= 1) {
        if (tid < s) red[tid] += red[tid + s];
        __syncthreads();
    }
    const float inv = 1.f / red[0];
#pragma unroll
    for (int i = 0; i < 4; i++) {
        int base = (tid + i * 256) * 4;
        __nv_bfloat16 h0, h1, h2, h3, l0, l1, l2, l3;
        split1(v[i].x * inv, h0, l0); split1(v[i].y * inv, h1, l1);
        split1(v[i].z * inv, h2, l2); split1(v[i].w * inv, h3, l3);
        *(__nv_bfloat162*)(ph + base)     = __nv_bfloat162(h0, h1);
        *(__nv_bfloat162*)(ph + base + 2) = __nv_bfloat162(h2, h3);
        *(__nv_bfloat162*)(pl + base)     = __nv_bfloat162(l0, l1);
        *(__nv_bfloat162*)(pl + base + 2) = __nv_bfloat162(l2, l3);
    }
}

// ===========================================================================
// PV (HMMA): Tpart = P[128t, 512s-seg] @ V[512s, 64d]. grid (8, HH, BB)
// ===========================================================================
#define PV_AROW 80                      // 32 bf16 + pad
#define PV_ATILE (128 * PV_AROW)        // 10240
#define PV_BROW 144                     // 64 bf16 + pad
#define PV_BTILE (32 * PV_BROW)         // 4608
#define PV_STAGE (2 * PV_ATILE + 2 * PV_BTILE)   // 29696
#define SMEM_PV (2 * PV_STAGE)          // 59392

__global__ __launch_bounds__(256) void attn_pv_mma(
    const __nv_bfloat16* __restrict__ Ph, const __nv_bfloat16* __restrict__ Pl,
    const __nv_bfloat16* __restrict__ Vh, const __nv_bfloat16* __restrict__ Vl,
    float* __restrict__ Tp)
{
    extern __shared__ char smem[];
    const uint32_t sb = smem_u32(smem);
    const int seg = blockIdx.x, h = blockIdx.y, b = blockIdx.z;
    const int tid = threadIdx.x;
    const int wid = tid >> 5, lane = tid & 31;
    const int wm = (wid >> 1) * 32, wn = (wid & 1) * 32;

    const char* pA[2] = {
        (const char*)(Ph + ((size_t)(b * HH + h) * LT) * LV + seg * 512),
        (const char*)(Pl + ((size_t)(b * HH + h) * LT) * LV + seg * 512) };
    const char* pB[2] = {
        (const char*)(Vh + ((size_t)b * LV + seg * 512) * DD + h * HD),
        (const char*)(Vl + ((size_t)b * LV + seg * 512) * DD + h * HD) };

    auto issue = [&](int kt, int s) {
        const uint32_t st0 = sb + s * PV_STAGE;
#pragma unroll
        for (int i = 0; i < 4; i++) {
            int id = tid + i * 256;
            int t = id >> 9, r = (id >> 2) & 127, c = id & 3;
            cp_async16(st0 + t * PV_ATILE + r * PV_AROW + c * 16,
                       pA[t] + (size_t)r * LV * 2 + (size_t)kt * 64 + c * 16);
        }
        {
            int id = tid + 1024;
            int t = (id >> 8) & 1, r = (id >> 3) & 31, c = id & 7;
            cp_async16(st0 + 2 * PV_ATILE + t * PV_BTILE + r * PV_BROW + c * 16,
                       pB[t] + ((size_t)kt * 32 + r) * DD * 2 + c * 16);
            id = tid + 1280;
            t = (id >> 8) & 1; r = (id >> 3) & 31; c = id & 7;
            cp_async16(st0 + 2 * PV_ATILE + t * PV_BTILE + r * PV_BROW + c * 16,
                       pB[t] + ((size_t)kt * 32 + r) * DD * 2 + c * 16);
        }
        cp_commit();
    };

    float acc[2][4][4];
#pragma unroll
    for (int i = 0; i < 2; i++)
#pragma unroll
        for (int j = 0; j < 4; j++)
#pragma unroll
            for (int k = 0; k < 4; k++) acc[i][j][k] = 0.f;

    issue(0, 0);
    for (int kt = 0; kt < 16; kt++) {
        if (kt + 1 < 16) { issue(kt + 1, (kt + 1) & 1); cp_wait<1>(); }
        else cp_wait<0>();
        __syncthreads();

        const uint32_t st0 = sb + (kt & 1) * PV_STAGE;
        const uint32_t Ahs = st0, Als = st0 + PV_ATILE;
        const uint32_t Bhs = st0 + 2 * PV_ATILE, Bls = Bhs + PV_BTILE;

#pragma unroll
        for (int ks = 0; ks < 2; ks++) {
            const int k16 = ks * 16;
            uint32_t ah[2][4], al[2][4];
#pragma unroll
            for (int mi = 0; mi < 2; mi++) {
                int row = wm + mi * 16 + (lane & 15);
                int col = k16 + ((lane >> 4) << 3);
                ldm_x4(ah[mi], Ahs + row * PV_AROW + col * 2);
                ldm_x4(al[mi], Als + row * PV_AROW + col * 2);
            }
            uint32_t bh[2][4], bl[2][4];
#pragma unroll
            for (int bi = 0; bi < 2; bi++) {
                int srow = k16 + ((lane >> 4) << 3) + (lane & 7);
                int dcol = wn + bi * 16 + (((lane >> 3) & 1) << 3);
                ldm_x4_t(bh[bi], Bhs + srow * PV_BROW + dcol * 2);
                ldm_x4_t(bl[bi], Bls + srow * PV_BROW + dcol * 2);
            }
            // trans-loaded B: reg j = (n-half j, k0-7), reg j+2 = (n-half j, k8-15)
#pragma unroll
            for (int mi = 0; mi < 2; mi++)
#pragma unroll
                for (int nb = 0; nb < 4; nb++) {
                    const int bi = nb >> 1, j = nb & 1;
                    mma16816v(acc[mi][nb], ah[mi], bh[bi][j], bh[bi][j + 2]);
                    mma16816v(acc[mi][nb], ah[mi], bl[bi][j], bl[bi][j + 2]);
                    mma16816v(acc[mi][nb], al[mi], bh[bi][j], bh[bi][j + 2]);
                }
        }
        __syncthreads();
    }

    float* Tb = Tp + (size_t)seg * (BB * HH * LT * HD) + ((size_t)(b * HH + h) * LT) * HD;
    const int gid = lane >> 2, tig = lane & 3;
#pragma unroll
    for (int mi = 0; mi < 2; mi++) {
        int r0 = wm + mi * 16 + gid;
#pragma unroll
        for (int nb = 0; nb < 4; nb++) {
            int c = wn + nb * 8 + tig * 2;
            *(float2*)(Tb + (size_t)r0 * HD + c) = make_float2(acc[mi][nb][0], acc[mi][nb][1]);
            *(float2*)(Tb + (size_t)(r0 + 8) * HD + c) = make_float2(acc[mi][nb][2], acc[mi][nb][3]);
        }
    }
}

__global__ __launch_bounds__(256) void reduce_T(
    const float* __restrict__ Tp, __nv_bfloat16* __restrict__ Th,
    __nv_bfloat16* __restrict__ Tl)
{
    size_t i = (size_t)blockIdx.x * 256 + threadIdx.x;
    float s = 0.f;
#pragma unroll
    for (int g = 0; g < 8; g++) s += Tp[(size_t)g * (BB * HH * LT * HD) + i];
    __nv_bfloat16 h, l; split1(s, h, l);
    Th[i] = h; Tl[i] = l;
}

// ===========================================================================
// OUT (HMMA): O[128s-tile, 64d] = P^T[128s, 128t] @ T[128t, 64d]
// ===========================================================================
#define AO_AROW 272                     // 128 bf16 + pad
#define AO_ATILE (32 * AO_AROW)         // 8704
#define AO_BROW 144
#define AO_BTILE (32 * AO_BROW)         // 4608
#define AO_STAGE (2 * AO_ATILE + 2 * AO_BTILE)   // 26624
#define SMEM_AO (2 * AO_STAGE)          // 53248

__global__ __launch_bounds__(256) void attn_out_mma(
    const __nv_bfloat16* __restrict__ Ph, const __nv_bfloat16* __restrict__ Pl,
    const __nv_bfloat16* __restrict__ Th, const __nv_bfloat16* __restrict__ Tl,
    __nv_bfloat16* __restrict__ Ohi, __nv_bfloat16* __restrict__ Olo)
{
    extern __shared__ char smem[];
    const uint32_t sb = smem_u32(smem);
    const int st = blockIdx.x, h = blockIdx.y, b = blockIdx.z;
    const int tid = threadIdx.x;
    const int wid = tid >> 5, lane = tid & 31;
    const int wm = (wid >> 1) * 32, wn = (wid & 1) * 32;

    const char* pA[2] = {
        (const char*)(Ph + ((size_t)(b * HH + h) * LT) * LV + st * 128),
        (const char*)(Pl + ((size_t)(b * HH + h) * LT) * LV + st * 128) };
    const char* pB[2] = {
        (const char*)(Th + ((size_t)(b * HH + h) * LT) * HD),
        (const char*)(Tl + ((size_t)(b * HH + h) * LT) * HD) };

    auto issue = [&](int kt, int s) {
        const uint32_t st0 = sb + s * AO_STAGE;
#pragma unroll
        for (int i = 0; i < 4; i++) {
            int id = tid + i * 256;
            int t = id >> 9, r = (id >> 4) & 31, c = id & 15;
            cp_async16(st0 + t * AO_ATILE + r * AO_AROW + c * 16,
                       pA[t] + ((size_t)kt * 32 + r) * LV * 2 + c * 16);
        }
        {
            int id = tid + 1024;
            int t = (id >> 8) & 1, r = (id >> 3) & 31, c = id & 7;
            cp_async16(st0 + 2 * AO_ATILE + t * AO_BTILE + r * AO_BROW + c * 16,
                       pB[t] + ((size_t)kt * 32 + r) * HD * 2 + c * 16);
            id = tid + 1280;
            t = (id >> 8) & 1; r = (id >> 3) & 31; c = id & 7;
            cp_async16(st0 + 2 * AO_ATILE + t * AO_BTILE + r * AO_BROW + c * 16,
                       pB[t] + ((size_t)kt * 32 + r) * HD * 2 + c * 16);
        }
        cp_commit();
    };

    float acc[2][4][4];
#pragma unroll
    for (int i = 0; i < 2; i++)
#pragma unroll
        for (int j = 0; j < 4; j++)
#pragma unroll
            for (int k = 0; k < 4; k++) acc[i][j][k] = 0.f;

    issue(0, 0);
    for (int kt = 0; kt < 4; kt++) {
        if (kt + 1 < 4) { issue(kt + 1, (kt + 1) & 1); cp_wait<1>(); }
        else cp_wait<0>();
        __syncthreads();

        const uint32_t st0 = sb + (kt & 1) * AO_STAGE;
        const uint32_t Ahs = st0, Als = st0 + AO_ATILE;
        const uint32_t Bhs = st0 + 2 * AO_ATILE, Bls = Bhs + AO_BTILE;

#pragma unroll
        for (int ks = 0; ks < 2; ks++) {
            const int k16 = ks * 16;
            // A = P^T via trans: matrix i maps to a_i exactly (verified)
            uint32_t ah[2][4], al[2][4];
#pragma unroll
            for (int mi = 0; mi < 2; mi++) {
                int trow = k16 + ((lane >> 4) << 3) + (lane & 7);
                int scol = wm + mi * 16 + (((lane >> 3) & 1) << 3);
                ldm_x4_t(ah[mi], Ahs + trow * AO_AROW + scol * 2);
                ldm_x4_t(al[mi], Als + trow * AO_AROW + scol * 2);
            }
            uint32_t bh[2][4], bl[2][4];
#pragma unroll
            for (int bi = 0; bi < 2; bi++) {
                int trow = k16 + ((lane >> 4) << 3) + (lane & 7);
                int dcol = wn + bi * 16 + (((lane >> 3) & 1) << 3);
                ldm_x4_t(bh[bi], Bhs + trow * AO_BROW + dcol * 2);
                ldm_x4_t(bl[bi], Bls + trow * AO_BROW + dcol * 2);
            }
            // trans-loaded B: pair regs {j, j+2}
#pragma unroll
            for (int mi = 0; mi < 2; mi++)
#pragma unroll
                for (int nb = 0; nb < 4; nb++) {
                    const int bi = nb >> 1, j = nb & 1;
                    mma16816v(acc[mi][nb], ah[mi], bh[bi][j], bh[bi][j + 2]);
                    mma16816v(acc[mi][nb], ah[mi], bl[bi][j], bl[bi][j + 2]);
                    mma16816v(acc[mi][nb], al[mi], bh[bi][j], bh[bi][j + 2]);
                }
        }
        __syncthreads();
    }

    const int gid = lane >> 2, tig = lane & 3;
#pragma unroll
    for (int mi = 0; mi < 2; mi++) {
        int srow = st * 128 + wm + mi * 16 + gid;
#pragma unroll
        for (int nb = 0; nb < 4; nb++) {
            int c = h * HD + wn + nb * 8 + tig * 2;
            size_t o0 = ((size_t)b * LV + srow) * DD + c;
            size_t o1 = ((size_t)b * LV + srow + 8) * DD + c;
            __nv_bfloat16 h0, h1, h2, h3, l0, l1, l2, l3;
            split1(acc[mi][nb][0], h0, l0); split1(acc[mi][nb][1], h1, l1);
            split1(acc[mi][nb][2], h2, l2); split1(acc[mi][nb][3], h3, l3);
            *(__nv_bfloat162*)(Ohi + o0) = __nv_bfloat162(h0, h1);
            *(__nv_bfloat162*)(Olo + o0) = __nv_bfloat162(l0, l1);
            *(__nv_bfloat162*)(Ohi + o1) = __nv_bfloat162(h2, h3);
            *(__nv_bfloat162*)(Olo + o1) = __nv_bfloat162(l2, l3);
        }
    }
}

// ===========================================================================
// Launch
// ===========================================================================
extern "C" void kernel_launch(void* const* d_in, const int* in_sizes, int n_in,
                              void* d_out, int out_size)
{
    const float* hidden = (const float*)d_in[0];
    const float* text   = (const float*)d_in[1];
    const float* Wq = (const float*)d_in[2];
    const float* bq = (const float*)d_in[3];
    const float* Wk = (const float*)d_in[4];
    const float* bk = (const float*)d_in[5];
    const float* Wv = (const float*)d_in[6];
    const float* bv = (const float*)d_in[7];
    const float* Wo = (const float*)d_in[8];
    const float* bo = (const float*)d_in[9];
    float* out = (float*)d_out;

    __nv_bfloat16 *txh, *txl, *hdh, *hdl, *Wh, *Wl;
    __nv_bfloat16 *Qh, *Ql, *Kh, *Kl, *Vh, *Vl, *Ph, *Pl, *Th, *Tl, *Ohi, *Olo;
    float *S, *Tp;
    cudaGetSymbolAddress((void**)&txh, g_txh);
    cudaGetSymbolAddress((void**)&txl, g_txl);
    cudaGetSymbolAddress((void**)&hdh, g_hdh);
    cudaGetSymbolAddress((void**)&hdl, g_hdl);
    cudaGetSymbolAddress((void**)&Wh, g_Wh);
    cudaGetSymbolAddress((void**)&Wl, g_Wl);
    cudaGetSymbolAddress((void**)&Qh, g_Qh);
    cudaGetSymbolAddress((void**)&Ql, g_Ql);
    cudaGetSymbolAddress((void**)&Kh, g_Kh);
    cudaGetSymbolAddress((void**)&Kl, g_Kl);
    cudaGetSymbolAddress((void**)&Vh, g_Vh);
    cudaGetSymbolAddress((void**)&Vl, g_Vl);
    cudaGetSymbolAddress((void**)&S, g_S);
    cudaGetSymbolAddress((void**)&Ph, g_Ph);
    cudaGetSymbolAddress((void**)&Pl, g_Pl);
    cudaGetSymbolAddress((void**)&Tp, g_Tp);
    cudaGetSymbolAddress((void**)&Th, g_Th);
    cudaGetSymbolAddress((void**)&Tl, g_Tl);
    cudaGetSymbolAddress((void**)&Ohi, g_Ohi);
    cudaGetSymbolAddress((void**)&Olo, g_Olo);

    cudaFuncSetAttribute(gemm_bf16x3<0>, cudaFuncAttributeMaxDynamicSharedMemorySize, SMEM_GEMM);
    cudaFuncSetAttribute(gemm_bf16x3<1>, cudaFuncAttributeMaxDynamicSharedMemorySize, SMEM_GEMM);
    cudaFuncSetAttribute(attn_scores_mma, cudaFuncAttributeMaxDynamicSharedMemorySize, SMEM_SC);
    cudaFuncSetAttribute(attn_pv_mma, cudaFuncAttributeMaxDynamicSharedMemorySize, SMEM_PV);
    cudaFuncSetAttribute(attn_out_mma, cudaFuncAttributeMaxDynamicSharedMemorySize, SMEM_AO);

    const size_t WSZ = (size_t)DD * DD;

    // 1. input splits
    split_hl<<<(BB * LT * DD) / 1024, 256>>>(text, txh, txl, (size_t)BB * LT * DD);
    split_hl<<<(BB * LV * DD) / 1024, 256>>>(hidden, hdh, hdl, (size_t)BB * LV * DD);

    // 2. weight transpose + split
    dim3 wt(32, 32);
    wsplit_t<<<wt, dim3(32, 8)>>>(Wq, Wh + 0 * WSZ, Wl + 0 * WSZ);
    wsplit_t<<<wt, dim3(32, 8)>>>(Wk, Wh + 1 * WSZ, Wl + 1 * WSZ);
    wsplit_t<<<wt, dim3(32, 8)>>>(Wv, Wh + 2 * WSZ, Wl + 2 * WSZ);
    wsplit_t<<<wt, dim3(32, 8)>>>(Wo, Wh + 3 * WSZ, Wl + 3 * WSZ);

    // 3. projections -> bf16 hi/lo outputs
    gemm_bf16x3<1><<<dim3(DD / 128, (BB * LT) / 128), 256, SMEM_GEMM>>>(
        txh, txl, Wh + 0 * WSZ, Wl + 0 * WSZ, bq, nullptr, Qh, Ql,
        BB * LT, DD, DD, DD, DD, DD, QSCALE);
    gemm_bf16x3<1><<<dim3(DD / 128, (BB * LV) / 128), 256, SMEM_GEMM>>>(
        hdh, hdl, Wh + 1 * WSZ, Wl + 1 * WSZ, bk, nullptr, Kh, Kl,
        BB * LV, DD, DD, DD, DD, DD, 1.0f);
    gemm_bf16x3<1><<<dim3(DD / 128, (BB * LV) / 128), 256, SMEM_GEMM>>>(
        hdh, hdl, Wh + 2 * WSZ, Wl + 2 * WSZ, bv, nullptr, Vh, Vl,
        BB * LV, DD, DD, DD, DD, DD, 1.0f);

    // 4. attention (all HMMA)
    attn_scores_mma<<<dim3(LV / 128, HH, BB), 256, SMEM_SC>>>(Qh, Ql, Kh, Kl, S);
    softmax_bf<<<BB * HH * LT, 256>>>(S, Ph, Pl);
    attn_pv_mma<<<dim3(8, HH, BB), 256, SMEM_PV>>>(Ph, Pl, Vh, Vl, Tp);
    reduce_T<<<(BB * HH * LT * HD) / 256, 256>>>(Tp, Th, Tl);
    attn_out_mma<<<dim3(LV / 128, HH, BB), 256, SMEM_AO>>>(Ph, Pl, Th, Tl, Ohi, Olo);

    // 5. output projection -> fp32 out
    gemm_bf16x3<0><<<dim3(DD / 128, (BB * LV) / 128), 256, SMEM_GEMM>>>(
        Ohi, Olo, Wh + 3 * WSZ, Wl + 3 * WSZ, bo, out, nullptr, nullptr,
        BB * LV, DD, DD, DD, DD, DD, 1.0f);
}

// round 6
// speedup vs baseline: 3.4723x; 1.6703x over previous
#include <cuda_runtime.h>
#include <cuda_fp16.h>
#include <cstdint>
#include <cstddef>

// Problem constants
#define BB 16
#define LT 128
#define LV 4096
#define DD 1024
#define HH 16
#define HD 64
static constexpr float QSCALE = 0.125f;  // 64^-0.5

// ===========================================================================
// Scratch (device globals)
// ===========================================================================
__device__ __half g_txh[(size_t)BB * LT * DD];
__device__ __half g_txl[(size_t)BB * LT * DD];
__device__ __half g_hdh[(size_t)BB * LV * DD];
__device__ __half g_hdl[(size_t)BB * LV * DD];
__device__ __half g_Wt[4][(size_t)DD * DD];      // W^T single fp16 (N,K)
__device__ __half g_Qh[(size_t)BB * LT * DD];
__device__ __half g_Ql[(size_t)BB * LT * DD];
__device__ __half g_Kf[(size_t)BB * LV * DD];    // single
__device__ __half g_Vf[(size_t)BB * LV * DD];    // single
__device__ float  g_S[(size_t)BB * HH * LT * LV];
__device__ __half g_Ph[(size_t)BB * HH * LT * LV];
__device__ __half g_Pl[(size_t)BB * HH * LT * LV];
__device__ float  g_Tp[8][(size_t)BB * HH * LT * HD];
__device__ __half g_Tf[(size_t)BB * HH * LT * HD];   // single
__device__ __half g_Ohi[(size_t)BB * LV * DD];
__device__ __half g_Olo[(size_t)BB * LV * DD];

// ===========================================================================
// PTX helpers (arch-portable)
// ===========================================================================
__device__ __forceinline__ uint32_t smem_u32(const void* p) {
    uint32_t a;
    asm("{ .reg .u64 t; cvta.to.shared.u64 t, %1; cvt.u32.u64 %0, t; }" : "=r"(a) : "l"(p));
    return a;
}
__device__ __forceinline__ void cp_async16(uint32_t dst, const void* src) {
    asm volatile("cp.async.cg.shared.global [%0], [%1], 16;" :: "r"(dst), "l"(src));
}
__device__ __forceinline__ void cp_commit() { asm volatile("cp.async.commit_group;"); }
template <int N>
__device__ __forceinline__ void cp_wait() { asm volatile("cp.async.wait_group %0;" :: "n"(N)); }

__device__ __forceinline__ void ldm_x4(uint32_t* r, uint32_t addr) {
    asm volatile("ldmatrix.sync.aligned.m8n8.x4.shared.b16 {%0,%1,%2,%3}, [%4];"
                 : "=r"(r[0]), "=r"(r[1]), "=r"(r[2]), "=r"(r[3]) : "r"(addr));
}
__device__ __forceinline__ void ldm_x4_t(uint32_t* r, uint32_t addr) {
    asm volatile("ldmatrix.sync.aligned.m8n8.x4.trans.shared.b16 {%0,%1,%2,%3}, [%4];"
                 : "=r"(r[0]), "=r"(r[1]), "=r"(r[2]), "=r"(r[3]) : "r"(addr));
}
// fp16 inputs, fp32 accumulate
__device__ __forceinline__ void mma_h(float* c, const uint32_t* a, const uint32_t* b) {
    asm volatile(
        "mma.sync.aligned.m16n8k16.row.col.f32.f16.f16.f32 "
        "{%0,%1,%2,%3}, {%4,%5,%6,%7}, {%8,%9}, {%0,%1,%2,%3};"
        : "+f"(c[0]), "+f"(c[1]), "+f"(c[2]), "+f"(c[3])
        : "r"(a[0]), "r"(a[1]), "r"(a[2]), "r"(a[3]), "r"(b[0]), "r"(b[1]));
}
__device__ __forceinline__ void mma_hv(float* c, const uint32_t* a, uint32_t b0, uint32_t b1) {
    asm volatile(
        "mma.sync.aligned.m16n8k16.row.col.f32.f16.f16.f32 "
        "{%0,%1,%2,%3}, {%4,%5,%6,%7}, {%8,%9}, {%0,%1,%2,%3};"
        : "+f"(c[0]), "+f"(c[1]), "+f"(c[2]), "+f"(c[3])
        : "r"(a[0]), "r"(a[1]), "r"(a[2]), "r"(a[3]), "r"(b0), "r"(b1));
}
__device__ __forceinline__ void split1h(float v, __half& h, __half& l) {
    h = __float2half_rn(v);
    l = __float2half_rn(v - __half2float(h));
}

// ===========================================================================
// fp32 -> fp16 hi/lo split (elementwise)
// ===========================================================================
__global__ __launch_bounds__(256) void split_hl(
    const float* __restrict__ in, __half* __restrict__ hi,
    __half* __restrict__ lo, size_t n)
{
    size_t i = ((size_t)blockIdx.x * 256 + threadIdx.x) * 4;
    if (i >= n) return;
    float4 v = *(const float4*)(in + i);
    __half h0, h1, h2, h3, l0, l1, l2, l3;
    split1h(v.x, h0, l0); split1h(v.y, h1, l1);
    split1h(v.z, h2, l2); split1h(v.w, h3, l3);
    __half2* hp = (__half2*)(hi + i);
    __half2* lp = (__half2*)(lo + i);
    hp[0] = __halves2half2(h0, h1); hp[1] = __halves2half2(h2, h3);
    lp[0] = __halves2half2(l0, l1); lp[1] = __halves2half2(l2, l3);
}

// ===========================================================================
// Weight transpose to fp16: W [K][N] fp32 -> Wt [N][K] fp16
// ===========================================================================
__global__ __launch_bounds__(256) void wtrans_h(
    const float* __restrict__ W, __half* __restrict__ Wt)
{
    __shared__ float t[32][33];
    int bx = blockIdx.x, by = blockIdx.y;
    int x = threadIdx.x, y = threadIdx.y;
#pragma unroll
    for (int i = 0; i < 32; i += 8)
        t[y + i][x] = W[(size_t)(by * 32 + y + i) * DD + bx * 32 + x];
    __syncthreads();
#pragma unroll
    for (int i = 0; i < 32; i += 8) {
        float v = t[x][y + i];
        Wt[(size_t)(bx * 32 + y + i) * DD + by * 32 + x] = __float2half_rn(v);
    }
}

// ===========================================================================
// HMMA fp16x2 GEMM: C = alpha*((Ah+Al) @ B^T + bias)
// Ah/Al: [M,K] fp16 (lda). B: [N,K] fp16 single (ldb).
// Tile 128x128, BK=32, 8 warps 4x2 (warp 32x64), 3-stage cp.async.
// OUTMODE 0: fp32 C.  1: fp16 hi/lo pair (Ch,Cl).  2: fp16 single (Ch).
// ===========================================================================
#define ROWB 80
#define TILE_T (128 * ROWB)            // 10240
#define STAGE_B (3 * TILE_T)           // 30720 (Ah, Al, B)
#define SMEM_GEMM (3 * STAGE_B)        // 92160

template <int OUTMODE>
__global__ __launch_bounds__(256) void gemm_f16x2(
    const __half* __restrict__ Ah, const __half* __restrict__ Al,
    const __half* __restrict__ B,
    const float* __restrict__ bias, float* __restrict__ C,
    __half* __restrict__ Ch, __half* __restrict__ Cl,
    int M, int N, int K, int lda, int ldb, int ldc, float alpha)
{
    extern __shared__ char smem[];
    const uint32_t sb = smem_u32(smem);
    const int tid = threadIdx.x;
    const int wid = tid >> 5, lane = tid & 31;
    const int m0 = blockIdx.y * 128, n0 = blockIdx.x * 128;
    const int wm = (wid >> 1) * 32;
    const int wn = (wid & 1) * 64;

    const char* gA[3] = { (const char*)(Ah + (size_t)m0 * lda),
                          (const char*)(Al + (size_t)m0 * lda),
                          (const char*)(B + (size_t)n0 * ldb) };
    const int glds[3] = { lda, lda, ldb };

    float acc[2][8][4];
#pragma unroll
    for (int i = 0; i < 2; i++)
#pragma unroll
        for (int j = 0; j < 8; j++)
#pragma unroll
            for (int k = 0; k < 4; k++) acc[i][j][k] = 0.f;

    const int NT = K / 32;

    auto issue = [&](int kt, int s) {
        const uint32_t st0 = sb + s * STAGE_B;
#pragma unroll
        for (int t = 0; t < 3; t++) {
            const char* g = gA[t] + (size_t)kt * 64;
            const int ldbytes = glds[t] * 2;
            const uint32_t tb = st0 + t * TILE_T;
#pragma unroll
            for (int i = 0; i < 2; i++) {
                int id = tid + i * 256;
                int r = id >> 2, c = id & 3;
                cp_async16(tb + r * ROWB + c * 16, g + (size_t)r * ldbytes + c * 16);
            }
        }
        cp_commit();
    };

    issue(0, 0);
    issue(1, 1);

    for (int kt = 0; kt < NT; kt++) {
        if (kt + 2 < NT) { issue(kt + 2, (kt + 2) % 3); cp_wait<2>(); }
        else if (kt + 1 < NT) cp_wait<1>();
        else cp_wait<0>();
        __syncthreads();

        const uint32_t st0 = sb + (kt % 3) * STAGE_B;
        const uint32_t Ahs = st0 + 0 * TILE_T;
        const uint32_t Als = st0 + 1 * TILE_T;
        const uint32_t Bfs = st0 + 2 * TILE_T;

#pragma unroll
        for (int ks = 0; ks < 2; ks++) {
            const int k16 = ks * 16;
            uint32_t ah[2][4], al[2][4];
#pragma unroll
            for (int mi = 0; mi < 2; mi++) {
                int row = wm + mi * 16 + (lane & 15);
                int col = k16 + ((lane >> 4) << 3);
                ldm_x4(ah[mi], Ahs + row * ROWB + col * 2);
                ldm_x4(al[mi], Als + row * ROWB + col * 2);
            }
            uint32_t bf[4][4];
#pragma unroll
            for (int bi = 0; bi < 4; bi++) {
                int nrow = wn + bi * 16 + (lane & 7) + ((lane >> 4) << 3);
                int col = k16 + (((lane >> 3) & 1) << 3);
                ldm_x4(bf[bi], Bfs + nrow * ROWB + col * 2);
            }
#pragma unroll
            for (int mi = 0; mi < 2; mi++)
#pragma unroll
                for (int nb = 0; nb < 8; nb++) {
                    const uint32_t* bp = &bf[nb >> 1][(nb & 1) * 2];
                    mma_h(acc[mi][nb], ah[mi], bp);
                    mma_h(acc[mi][nb], al[mi], bp);
                }
        }
        __syncthreads();
    }

    const int gid = lane >> 2, tig = lane & 3;
#pragma unroll
    for (int mi = 0; mi < 2; mi++) {
        int r0 = m0 + wm + mi * 16 + gid;
#pragma unroll
        for (int nb = 0; nb < 8; nb++) {
            int c = n0 + wn + nb * 8 + tig * 2;
            float b0 = __ldg(&bias[c]), b1 = __ldg(&bias[c + 1]);
            float v00 = alpha * (acc[mi][nb][0] + b0);
            float v01 = alpha * (acc[mi][nb][1] + b1);
            float v10 = alpha * (acc[mi][nb][2] + b0);
            float v11 = alpha * (acc[mi][nb][3] + b1);
            if (OUTMODE == 0) {
                *(float2*)(C + (size_t)r0 * ldc + c) = make_float2(v00, v01);
                *(float2*)(C + (size_t)(r0 + 8) * ldc + c) = make_float2(v10, v11);
            } else if (OUTMODE == 1) {
                __half h0, h1, h2, h3, l0, l1, l2, l3;
                split1h(v00, h0, l0); split1h(v01, h1, l1);
                split1h(v10, h2, l2); split1h(v11, h3, l3);
                *(__half2*)(Ch + (size_t)r0 * ldc + c) = __halves2half2(h0, h1);
                *(__half2*)(Cl + (size_t)r0 * ldc + c) = __halves2half2(l0, l1);
                *(__half2*)(Ch + (size_t)(r0 + 8) * ldc + c) = __halves2half2(h2, h3);
                *(__half2*)(Cl + (size_t)(r0 + 8) * ldc + c) = __halves2half2(l2, l3);
            } else {
                *(__half2*)(Ch + (size_t)r0 * ldc + c) =
                    __halves2half2(__float2half_rn(v00), __float2half_rn(v01));
                *(__half2*)(Ch + (size_t)(r0 + 8) * ldc + c) =
                    __halves2half2(__float2half_rn(v10), __float2half_rn(v11));
            }
        }
    }
}

// ===========================================================================
// Scores: S = (Qh+Ql) . Kf   M=128 t, N=128 s-tile, K=64 single load
// ===========================================================================
#define SROWB 144
#define STILE (128 * SROWB)
#define SMEM_SC (3 * STILE)            // 55296

__global__ __launch_bounds__(256) void attn_scores_mma(
    const __half* __restrict__ Qh, const __half* __restrict__ Ql,
    const __half* __restrict__ Kf, float* __restrict__ S)
{
    extern __shared__ char smem[];
    const uint32_t sb = smem_u32(smem);
    const int st = blockIdx.x, h = blockIdx.y, b = blockIdx.z;
    const int tid = threadIdx.x;
    const int wid = tid >> 5, lane = tid & 31;
    const int wm = (wid >> 1) * 32, wn = (wid & 1) * 64;

    const char* gp[3] = {
        (const char*)(Qh + ((size_t)b * LT) * DD + h * HD),
        (const char*)(Ql + ((size_t)b * LT) * DD + h * HD),
        (const char*)(Kf + ((size_t)b * LV + st * 128) * DD + h * HD) };

#pragma unroll
    for (int i = 0; i < 12; i++) {
        int id = tid + i * 256;           // 0..3071
        int t = id >> 10;
        int r = (id >> 3) & 127;
        int c = id & 7;
        cp_async16(sb + t * STILE + r * SROWB + c * 16,
                   gp[t] + (size_t)r * DD * 2 + c * 16);
    }
    cp_commit();
    cp_wait<0>();
    __syncthreads();

    float acc[2][8][4];
#pragma unroll
    for (int i = 0; i < 2; i++)
#pragma unroll
        for (int j = 0; j < 8; j++)
#pragma unroll
            for (int k = 0; k < 4; k++) acc[i][j][k] = 0.f;

    const uint32_t Ahs = sb, Als = sb + STILE, Bfs = sb + 2 * STILE;

#pragma unroll
    for (int ks = 0; ks < 4; ks++) {
        const int k16 = ks * 16;
        uint32_t ah[2][4], al[2][4];
#pragma unroll
        for (int mi = 0; mi < 2; mi++) {
            int row = wm + mi * 16 + (lane & 15);
            int col = k16 + ((lane >> 4) << 3);
            ldm_x4(ah[mi], Ahs + row * SROWB + col * 2);
            ldm_x4(al[mi], Als + row * SROWB + col * 2);
        }
        uint32_t bf[4][4];
#pragma unroll
        for (int bi = 0; bi < 4; bi++) {
            int nrow = wn + bi * 16 + (lane & 7) + ((lane >> 4) << 3);
            int col = k16 + (((lane >> 3) & 1) << 3);
            ldm_x4(bf[bi], Bfs + nrow * SROWB + col * 2);
        }
#pragma unroll
        for (int mi = 0; mi < 2; mi++)
#pragma unroll
            for (int nb = 0; nb < 8; nb++) {
                const uint32_t* bp = &bf[nb >> 1][(nb & 1) * 2];
                mma_h(acc[mi][nb], ah[mi], bp);
                mma_h(acc[mi][nb], al[mi], bp);
            }
    }

    float* Sb = S + ((size_t)(b * HH + h) * LT) * LV + st * 128;
    const int gid = lane >> 2, tig = lane & 3;
#pragma unroll
    for (int mi = 0; mi < 2; mi++) {
        int r0 = wm + mi * 16 + gid;
#pragma unroll
        for (int nb = 0; nb < 8; nb++) {
            int c = wn + nb * 8 + tig * 2;
            *(float2*)(Sb + (size_t)r0 * LV + c) = make_float2(acc[mi][nb][0], acc[mi][nb][1]);
            *(float2*)(Sb + (size_t)(r0 + 8) * LV + c) = make_float2(acc[mi][nb][2], acc[mi][nb][3]);
        }
    }
}

// ===========================================================================
// Softmax over last dim (LV) -> fp16 hi/lo
// ===========================================================================
__global__ __launch_bounds__(256) void softmax_hf(
    const float* __restrict__ S, __half* __restrict__ Ph, __half* __restrict__ Pl)
{
    const float4* p = (const float4*)(S + (size_t)blockIdx.x * LV);
    __half* ph = Ph + (size_t)blockIdx.x * LV;
    __half* pl = Pl + (size_t)blockIdx.x * LV;
    const int tid = threadIdx.x;
    __shared__ float red[256];

    float4 v[4];
    float mx = -1e30f;
#pragma unroll
    for (int i = 0; i < 4; i++) {
        v[i] = p[tid + i * 256];
        mx = fmaxf(mx, fmaxf(fmaxf(v[i].x, v[i].y), fmaxf(v[i].z, v[i].w)));
    }
    red[tid] = mx; __syncthreads();
    for (int s = 128; s > 0; s >>= 1) {
        if (tid < s) red[tid] = fmaxf(red[tid], red[tid + s]);
        __syncthreads();
    }
    mx = red[0]; __syncthreads();

    float sum = 0.f;
#pragma unroll
    for (int i = 0; i < 4; i++) {
        v[i].x = __expf(v[i].x - mx); v[i].y = __expf(v[i].y - mx);
        v[i].z = __expf(v[i].z - mx); v[i].w = __expf(v[i].w - mx);
        sum += v[i].x + v[i].y + v[i].z + v[i].w;
    }
    red[tid] = sum; __syncthreads();
    for (int s = 128; s > 0; s >>= 1) {
        if (tid < s) red[tid] += red[tid + s];
        __syncthreads();
    }
    const float inv = 1.f / red[0];
#pragma unroll
    for (int i = 0; i < 4; i++) {
        int base = (tid + i * 256) * 4;
        __half h0, h1, h2, h3, l0, l1, l2, l3;
        split1h(v[i].x * inv, h0, l0); split1h(v[i].y * inv, h1, l1);
        split1h(v[i].z * inv, h2, l2); split1h(v[i].w * inv, h3, l3);
        *(__half2*)(ph + base)     = __halves2half2(h0, h1);
        *(__half2*)(ph + base + 2) = __halves2half2(h2, h3);
        *(__half2*)(pl + base)     = __halves2half2(l0, l1);
        *(__half2*)(pl + base + 2) = __halves2half2(l2, l3);
    }
}

// ===========================================================================
// PV: Tpart = (Ph+Pl)[128t, 512s] @ Vf[512s, 64d]. grid (8, HH, BB)
// ===========================================================================
#define PV_AROW 80
#define PV_ATILE (128 * PV_AROW)        // 10240
#define PV_BROW 144
#define PV_BTILE (32 * PV_BROW)         // 4608
#define PV_STAGE (2 * PV_ATILE + PV_BTILE)   // 25088
#define SMEM_PV (2 * PV_STAGE)          // 50176

__global__ __launch_bounds__(256) void attn_pv_mma(
    const __half* __restrict__ Ph, const __half* __restrict__ Pl,
    const __half* __restrict__ Vf, float* __restrict__ Tp)
{
    extern __shared__ char smem[];
    const uint32_t sb = smem_u32(smem);
    const int seg = blockIdx.x, h = blockIdx.y, b = blockIdx.z;
    const int tid = threadIdx.x;
    const int wid = tid >> 5, lane = tid & 31;
    const int wm = (wid >> 1) * 32, wn = (wid & 1) * 32;

    const char* pA[2] = {
        (const char*)(Ph + ((size_t)(b * HH + h) * LT) * LV + seg * 512),
        (const char*)(Pl + ((size_t)(b * HH + h) * LT) * LV + seg * 512) };
    const char* pB = (const char*)(Vf + ((size_t)b * LV + seg * 512) * DD + h * HD);

    auto issue = [&](int kt, int s) {
        const uint32_t st0 = sb + s * PV_STAGE;
#pragma unroll
        for (int i = 0; i < 4; i++) {            // A: 1024 chunks
            int id = tid + i * 256;
            int t = id >> 9, r = (id >> 2) & 127, c = id & 3;
            cp_async16(st0 + t * PV_ATILE + r * PV_AROW + c * 16,
                       pA[t] + (size_t)r * LV * 2 + (size_t)kt * 64 + c * 16);
        }
        {                                         // B: 256 chunks (32 rows x 8)
            int r = tid >> 3, c = tid & 7;
            cp_async16(st0 + 2 * PV_ATILE + r * PV_BROW + c * 16,
                       pB + ((size_t)kt * 32 + r) * DD * 2 + c * 16);
        }
        cp_commit();
    };

    float acc[2][4][4];
#pragma unroll
    for (int i = 0; i < 2; i++)
#pragma unroll
        for (int j = 0; j < 4; j++)
#pragma unroll
            for (int k = 0; k < 4; k++) acc[i][j][k] = 0.f;

    issue(0, 0);
    for (int kt = 0; kt < 16; kt++) {
        if (kt + 1 < 16) { issue(kt + 1, (kt + 1) & 1); cp_wait<1>(); }
        else cp_wait<0>();
        __syncthreads();

        const uint32_t st0 = sb + (kt & 1) * PV_STAGE;
        const uint32_t Ahs = st0, Als = st0 + PV_ATILE;
        const uint32_t Bfs = st0 + 2 * PV_ATILE;

#pragma unroll
        for (int ks = 0; ks < 2; ks++) {
            const int k16 = ks * 16;
            uint32_t ah[2][4], al[2][4];
#pragma unroll
            for (int mi = 0; mi < 2; mi++) {
                int row = wm + mi * 16 + (lane & 15);
                int col = k16 + ((lane >> 4) << 3);
                ldm_x4(ah[mi], Ahs + row * PV_AROW + col * 2);
                ldm_x4(al[mi], Als + row * PV_AROW + col * 2);
            }
            uint32_t bf[2][4];
#pragma unroll
            for (int bi = 0; bi < 2; bi++) {
                int srow = k16 + ((lane >> 4) << 3) + (lane & 7);
                int dcol = wn + bi * 16 + (((lane >> 3) & 1) << 3);
                ldm_x4_t(bf[bi], Bfs + srow * PV_BROW + dcol * 2);
            }
            // trans B: k-halves in regs {j, j+2}
#pragma unroll
            for (int mi = 0; mi < 2; mi++)
#pragma unroll
                for (int nb = 0; nb < 4; nb++) {
                    const int bi = nb >> 1, j = nb & 1;
                    mma_hv(acc[mi][nb], ah[mi], bf[bi][j], bf[bi][j + 2]);
                    mma_hv(acc[mi][nb], al[mi], bf[bi][j], bf[bi][j + 2]);
                }
        }
        __syncthreads();
    }

    float* Tb = Tp + (size_t)seg * (BB * HH * LT * HD) + ((size_t)(b * HH + h) * LT) * HD;
    const int gid = lane >> 2, tig = lane & 3;
#pragma unroll
    for (int mi = 0; mi < 2; mi++) {
        int r0 = wm + mi * 16 + gid;
#pragma unroll
        for (int nb = 0; nb < 4; nb++) {
            int c = wn + nb * 8 + tig * 2;
            *(float2*)(Tb + (size_t)r0 * HD + c) = make_float2(acc[mi][nb][0], acc[mi][nb][1]);
            *(float2*)(Tb + (size_t)(r0 + 8) * HD + c) = make_float2(acc[mi][nb][2], acc[mi][nb][3]);
        }
    }
}

__global__ __launch_bounds__(256) void reduce_T(
    const float* __restrict__ Tp, __half* __restrict__ Tf)
{
    size_t i = (size_t)blockIdx.x * 256 + threadIdx.x;
    float s = 0.f;
#pragma unroll
    for (int g = 0; g < 8; g++) s += Tp[(size_t)g * (BB * HH * LT * HD) + i];
    Tf[i] = __float2half_rn(s);
}

// ===========================================================================
// OUT: O[128s, 64d] = (Ph+Pl)^T[128s,128t] @ Tf[128t, 64d]
// ===========================================================================
#define AO_AROW 272
#define AO_ATILE (32 * AO_AROW)         // 8704
#define AO_BROW 144
#define AO_BTILE (32 * AO_BROW)         // 4608
#define AO_STAGE (2 * AO_ATILE + AO_BTILE)   // 22016
#define SMEM_AO (2 * AO_STAGE)          // 44032

__global__ __launch_bounds__(256) void attn_out_mma(
    const __half* __restrict__ Ph, const __half* __restrict__ Pl,
    const __half* __restrict__ Tf,
    __half* __restrict__ Ohi, __half* __restrict__ Olo)
{
    extern __shared__ char smem[];
    const uint32_t sb = smem_u32(smem);
    const int st = blockIdx.x, h = blockIdx.y, b = blockIdx.z;
    const int tid = threadIdx.x;
    const int wid = tid >> 5, lane = tid & 31;
    const int wm = (wid >> 1) * 32, wn = (wid & 1) * 32;

    const char* pA[2] = {
        (const char*)(Ph + ((size_t)(b * HH + h) * LT) * LV + st * 128),
        (const char*)(Pl + ((size_t)(b * HH + h) * LT) * LV + st * 128) };
    const char* pB = (const char*)(Tf + ((size_t)(b * HH + h) * LT) * HD);

    auto issue = [&](int kt, int s) {
        const uint32_t st0 = sb + s * AO_STAGE;
#pragma unroll
        for (int i = 0; i < 4; i++) {            // A: 1024 chunks
            int id = tid + i * 256;
            int t = id >> 9, r = (id >> 4) & 31, c = id & 15;
            cp_async16(st0 + t * AO_ATILE + r * AO_AROW + c * 16,
                       pA[t] + ((size_t)kt * 32 + r) * LV * 2 + c * 16);
        }
        {                                         // B: 256 chunks
            int r = tid >> 3, c = tid & 7;
            cp_async16(st0 + 2 * AO_ATILE + r * AO_BROW + c * 16,
                       pB + ((size_t)kt * 32 + r) * HD * 2 + c * 16);
        }
        cp_commit();
    };

    float acc[2][4][4];
#pragma unroll
    for (int i = 0; i < 2; i++)
#pragma unroll
        for (int j = 0; j < 4; j++)
#pragma unroll
            for (int k = 0; k < 4; k++) acc[i][j][k] = 0.f;

    issue(0, 0);
    for (int kt = 0; kt < 4; kt++) {
        if (kt + 1 < 4) { issue(kt + 1, (kt + 1) & 1); cp_wait<1>(); }
        else cp_wait<0>();
        __syncthreads();

        const uint32_t st0 = sb + (kt & 1) * AO_STAGE;
        const uint32_t Ahs = st0, Als = st0 + AO_ATILE;
        const uint32_t Bfs = st0 + 2 * AO_ATILE;

#pragma unroll
        for (int ks = 0; ks < 2; ks++) {
            const int k16 = ks * 16;
            uint32_t ah[2][4], al[2][4];
#pragma unroll
            for (int mi = 0; mi < 2; mi++) {
                int trow = k16 + ((lane >> 4) << 3) + (lane & 7);
                int scol = wm + mi * 16 + (((lane >> 3) & 1) << 3);
                ldm_x4_t(ah[mi], Ahs + trow * AO_AROW + scol * 2);
                ldm_x4_t(al[mi], Als + trow * AO_AROW + scol * 2);
            }
            uint32_t bf[2][4];
#pragma unroll
            for (int bi = 0; bi < 2; bi++) {
                int trow = k16 + ((lane >> 4) << 3) + (lane & 7);
                int dcol = wn + bi * 16 + (((lane >> 3) & 1) << 3);
                ldm_x4_t(bf[bi], Bfs + trow * AO_BROW + dcol * 2);
            }
#pragma unroll
            for (int mi = 0; mi < 2; mi++)
#pragma unroll
                for (int nb = 0; nb < 4; nb++) {
                    const int bi = nb >> 1, j = nb & 1;
                    mma_hv(acc[mi][nb], ah[mi], bf[bi][j], bf[bi][j + 2]);
                    mma_hv(acc[mi][nb], al[mi], bf[bi][j], bf[bi][j + 2]);
                }
        }
        __syncthreads();
    }

    const int gid = lane >> 2, tig = lane & 3;
#pragma unroll
    for (int mi = 0; mi < 2; mi++) {
        int srow = st * 128 + wm + mi * 16 + gid;
#pragma unroll
        for (int nb = 0; nb < 4; nb++) {
            int c = h * HD + wn + nb * 8 + tig * 2;
            size_t o0 = ((size_t)b * LV + srow) * DD + c;
            size_t o1 = ((size_t)b * LV + srow + 8) * DD + c;
            __half h0, h1, h2, h3, l0, l1, l2, l3;
            split1h(acc[mi][nb][0], h0, l0); split1h(acc[mi][nb][1], h1, l1);
            split1h(acc[mi][nb][2], h2, l2); split1h(acc[mi][nb][3], h3, l3);
            *(__half2*)(Ohi + o0) = __halves2half2(h0, h1);
            *(__half2*)(Olo + o0) = __halves2half2(l0, l1);
            *(__half2*)(Ohi + o1) = __halves2half2(h2, h3);
            *(__half2*)(Olo + o1) = __halves2half2(l2, l3);
        }
    }
}

// ===========================================================================
// Launch
// ===========================================================================
extern "C" void kernel_launch(void* const* d_in, const int* in_sizes, int n_in,
                              void* d_out, int out_size)
{
    const float* hidden = (const float*)d_in[0];
    const float* text   = (const float*)d_in[1];
    const float* Wq = (const float*)d_in[2];
    const float* bq = (const float*)d_in[3];
    const float* Wk = (const float*)d_in[4];
    const float* bk = (const float*)d_in[5];
    const float* Wv = (const float*)d_in[6];
    const float* bv = (const float*)d_in[7];
    const float* Wo = (const float*)d_in[8];
    const float* bo = (const float*)d_in[9];
    float* out = (float*)d_out;

    __half *txh, *txl, *hdh, *hdl, *Wt;
    __half *Qh, *Ql, *Kf, *Vf, *Ph, *Pl, *Tf, *Ohi, *Olo;
    float *S, *Tp;
    cudaGetSymbolAddress((void**)&txh, g_txh);
    cudaGetSymbolAddress((void**)&txl, g_txl);
    cudaGetSymbolAddress((void**)&hdh, g_hdh);
    cudaGetSymbolAddress((void**)&hdl, g_hdl);
    cudaGetSymbolAddress((void**)&Wt, g_Wt);
    cudaGetSymbolAddress((void**)&Qh, g_Qh);
    cudaGetSymbolAddress((void**)&Ql, g_Ql);
    cudaGetSymbolAddress((void**)&Kf, g_Kf);
    cudaGetSymbolAddress((void**)&Vf, g_Vf);
    cudaGetSymbolAddress((void**)&S, g_S);
    cudaGetSymbolAddress((void**)&Ph, g_Ph);
    cudaGetSymbolAddress((void**)&Pl, g_Pl);
    cudaGetSymbolAddress((void**)&Tp, g_Tp);
    cudaGetSymbolAddress((void**)&Tf, g_Tf);
    cudaGetSymbolAddress((void**)&Ohi, g_Ohi);
    cudaGetSymbolAddress((void**)&Olo, g_Olo);

    cudaFuncSetAttribute(gemm_f16x2<0>, cudaFuncAttributeMaxDynamicSharedMemorySize, SMEM_GEMM);
    cudaFuncSetAttribute(gemm_f16x2<1>, cudaFuncAttributeMaxDynamicSharedMemorySize, SMEM_GEMM);
    cudaFuncSetAttribute(gemm_f16x2<2>, cudaFuncAttributeMaxDynamicSharedMemorySize, SMEM_GEMM);
    cudaFuncSetAttribute(attn_scores_mma, cudaFuncAttributeMaxDynamicSharedMemorySize, SMEM_SC);
    cudaFuncSetAttribute(attn_pv_mma, cudaFuncAttributeMaxDynamicSharedMemorySize, SMEM_PV);
    cudaFuncSetAttribute(attn_out_mma, cudaFuncAttributeMaxDynamicSharedMemorySize, SMEM_AO);

    const size_t WSZ = (size_t)DD * DD;

    // 1. input splits
    split_hl<<<(BB * LT * DD) / 1024, 256>>>(text, txh, txl, (size_t)BB * LT * DD);
    split_hl<<<(BB * LV * DD) / 1024, 256>>>(hidden, hdh, hdl, (size_t)BB * LV * DD);

    // 2. weight transpose -> fp16 single
    dim3 wt(32, 32);
    wtrans_h<<<wt, dim3(32, 8)>>>(Wq, Wt + 0 * WSZ);
    wtrans_h<<<wt, dim3(32, 8)>>>(Wk, Wt + 1 * WSZ);
    wtrans_h<<<wt, dim3(32, 8)>>>(Wv, Wt + 2 * WSZ);
    wtrans_h<<<wt, dim3(32, 8)>>>(Wo, Wt + 3 * WSZ);

    // 3. projections
    gemm_f16x2<1><<<dim3(DD / 128, (BB * LT) / 128), 256, SMEM_GEMM>>>(
        txh, txl, Wt + 0 * WSZ, bq, nullptr, Qh, Ql,
        BB * LT, DD, DD, DD, DD, DD, QSCALE);
    gemm_f16x2<2><<<dim3(DD / 128, (BB * LV) / 128), 256, SMEM_GEMM>>>(
        hdh, hdl, Wt + 1 * WSZ, bk, nullptr, Kf, nullptr,
        BB * LV, DD, DD, DD, DD, DD, 1.0f);
    gemm_f16x2<2><<<dim3(DD / 128, (BB * LV) / 128), 256, SMEM_GEMM>>>(
        hdh, hdl, Wt + 2 * WSZ, bv, nullptr, Vf, nullptr,
        BB * LV, DD, DD, DD, DD, DD, 1.0f);

    // 4. attention
    attn_scores_mma<<<dim3(LV / 128, HH, BB), 256, SMEM_SC>>>(Qh, Ql, Kf, S);
    softmax_hf<<<BB * HH * LT, 256>>>(S, Ph, Pl);
    attn_pv_mma<<<dim3(8, HH, BB), 256, SMEM_PV>>>(Ph, Pl, Vf, Tp);
    reduce_T<<<(BB * HH * LT * HD) / 256, 256>>>(Tp, Tf);
    attn_out_mma<<<dim3(LV / 128, HH, BB), 256, SMEM_AO>>>(Ph, Pl, Tf, Ohi, Olo);

    // 5. output projection -> fp32 out
    gemm_f16x2<0><<<dim3(DD / 128, (BB * LV) / 128), 256, SMEM_GEMM>>>(
        Ohi, Olo, Wt + 3 * WSZ, bo, out, nullptr, nullptr,
        BB * LV, DD, DD, DD, DD, DD, 1.0f);
}

// round 7
// speedup vs baseline: 3.5527x; 1.0232x over previous
#include <cuda_runtime.h>
#include <cuda_fp16.h>
#include <cstdint>
#include <cstddef>

// Problem constants
#define BB 16
#define LT 128
#define LV 4096
#define DD 1024
#define HH 16
#define HD 64
static constexpr float QSCALE = 0.125f;   // 64^-0.5
static constexpr float TSCALE = 65536.f;  // keeps Tf in fp16 normal range

// ===========================================================================
// Scratch (device globals)
// ===========================================================================
__device__ __half g_txh[(size_t)BB * LT * DD];
__device__ __half g_txl[(size_t)BB * LT * DD];
__device__ __half g_hdh[(size_t)BB * LV * DD];
__device__ __half g_hdl[(size_t)BB * LV * DD];
__device__ __half g_Wt[4][(size_t)DD * DD];        // W^T fp16 (N,K); 1=Wk,2=Wv adjacent
__device__ float  g_bkv[2 * DD];
__device__ __half g_Qh[(size_t)BB * LT * DD];
__device__ __half g_Ql[(size_t)BB * LT * DD];
__device__ __half g_Kf[(size_t)BB * LV * DD];
__device__ __half g_Vf[(size_t)BB * LV * DD];
__device__ __half g_Uf[(size_t)BB * HH * LT * LV]; // exp(S) unnormalized, fp16
__device__ float  g_Pp[(size_t)BB * HH * LT * 32]; // row partial sums (32 s-tiles)
__device__ float  g_scale[(size_t)BB * HH * LT];   // 2^16 / D^2
__device__ float  g_Tp[8][(size_t)BB * HH * LT * HD];
__device__ __half g_Tf[(size_t)BB * HH * LT * HD]; // Y/D^2 * 2^16
__device__ __half g_Ohi[(size_t)BB * LV * DD];
__device__ __half g_Olo[(size_t)BB * LV * DD];

// ===========================================================================
// PTX helpers (arch-portable)
// ===========================================================================
__device__ __forceinline__ uint32_t smem_u32(const void* p) {
    uint32_t a;
    asm("{ .reg .u64 t; cvta.to.shared.u64 t, %1; cvt.u32.u64 %0, t; }" : "=r"(a) : "l"(p));
    return a;
}
__device__ __forceinline__ void cp_async16(uint32_t dst, const void* src) {
    asm volatile("cp.async.cg.shared.global [%0], [%1], 16;" :: "r"(dst), "l"(src));
}
__device__ __forceinline__ void cp_commit() { asm volatile("cp.async.commit_group;"); }
template <int N>
__device__ __forceinline__ void cp_wait() { asm volatile("cp.async.wait_group %0;" :: "n"(N)); }

__device__ __forceinline__ void ldm_x4(uint32_t* r, uint32_t addr) {
    asm volatile("ldmatrix.sync.aligned.m8n8.x4.shared.b16 {%0,%1,%2,%3}, [%4];"
                 : "=r"(r[0]), "=r"(r[1]), "=r"(r[2]), "=r"(r[3]) : "r"(addr));
}
__device__ __forceinline__ void ldm_x4_t(uint32_t* r, uint32_t addr) {
    asm volatile("ldmatrix.sync.aligned.m8n8.x4.trans.shared.b16 {%0,%1,%2,%3}, [%4];"
                 : "=r"(r[0]), "=r"(r[1]), "=r"(r[2]), "=r"(r[3]) : "r"(addr));
}
__device__ __forceinline__ void mma_h(float* c, const uint32_t* a, const uint32_t* b) {
    asm volatile(
        "mma.sync.aligned.m16n8k16.row.col.f32.f16.f16.f32 "
        "{%0,%1,%2,%3}, {%4,%5,%6,%7}, {%8,%9}, {%0,%1,%2,%3};"
        : "+f"(c[0]), "+f"(c[1]), "+f"(c[2]), "+f"(c[3])
        : "r"(a[0]), "r"(a[1]), "r"(a[2]), "r"(a[3]), "r"(b[0]), "r"(b[1]));
}
__device__ __forceinline__ void mma_hv(float* c, const uint32_t* a, uint32_t b0, uint32_t b1) {
    asm volatile(
        "mma.sync.aligned.m16n8k16.row.col.f32.f16.f16.f32 "
        "{%0,%1,%2,%3}, {%4,%5,%6,%7}, {%8,%9}, {%0,%1,%2,%3};"
        : "+f"(c[0]), "+f"(c[1]), "+f"(c[2]), "+f"(c[3])
        : "r"(a[0]), "r"(a[1]), "r"(a[2]), "r"(a[3]), "r"(b0), "r"(b1));
}
__device__ __forceinline__ void split1h(float v, __half& h, __half& l) {
    h = __float2half_rn(v);
    l = __float2half_rn(v - __half2float(h));
}

// ===========================================================================
// fp32 -> fp16 hi/lo split
// ===========================================================================
__global__ __launch_bounds__(256) void split_hl(
    const float* __restrict__ in, __half* __restrict__ hi,
    __half* __restrict__ lo, size_t n)
{
    size_t i = ((size_t)blockIdx.x * 256 + threadIdx.x) * 4;
    if (i >= n) return;
    float4 v = *(const float4*)(in + i);
    __half h0, h1, h2, h3, l0, l1, l2, l3;
    split1h(v.x, h0, l0); split1h(v.y, h1, l1);
    split1h(v.z, h2, l2); split1h(v.w, h3, l3);
    __half2* hp = (__half2*)(hi + i);
    __half2* lp = (__half2*)(lo + i);
    hp[0] = __halves2half2(h0, h1); hp[1] = __halves2half2(h2, h3);
    lp[0] = __halves2half2(l0, l1); lp[1] = __halves2half2(l2, l3);
}

// ===========================================================================
// Weight transpose to fp16 + bias concat
// ===========================================================================
__global__ __launch_bounds__(256) void wtrans_h(
    const float* __restrict__ W, __half* __restrict__ Wt)
{
    __shared__ float t[32][33];
    int bx = blockIdx.x, by = blockIdx.y;
    int x = threadIdx.x, y = threadIdx.y;
#pragma unroll
    for (int i = 0; i < 32; i += 8)
        t[y + i][x] = W[(size_t)(by * 32 + y + i) * DD + bx * 32 + x];
    __syncthreads();
#pragma unroll
    for (int i = 0; i < 32; i += 8)
        Wt[(size_t)(bx * 32 + y + i) * DD + by * 32 + x] = __float2half_rn(t[x][y + i]);
}

__global__ __launch_bounds__(256) void concat_bias(
    const float* __restrict__ bk, const float* __restrict__ bv, float* __restrict__ b2)
{
    int i = blockIdx.x * 256 + threadIdx.x;
    if (i < DD) b2[i] = bk[i];
    else if (i < 2 * DD) b2[i] = bv[i - DD];
}

// ===========================================================================
// HMMA fp16x2 GEMM: C = alpha*((Ah+Al) @ B^T + bias)
// Tile 128x128, BK=64, 8 warps 4x2 (warp 32x64), 2-stage cp.async.
// OUTMODE 0: fp32 C.  1: fp16 hi/lo (Ch,Cl).  3: fp16 single split KV (Ch=K,Cl=V).
// ===========================================================================
#define ROWB 144                        // 64 fp16 = 128 B + 16 pad
#define TILE_T (128 * ROWB)             // 18432
#define STAGE_B (3 * TILE_T)            // 55296 (Ah, Al, B)
#define SMEM_GEMM (2 * STAGE_B)         // 110592

template <int OUTMODE>
__global__ __launch_bounds__(256) void gemm_f16x2(
    const __half* __restrict__ Ah, const __half* __restrict__ Al,
    const __half* __restrict__ B,
    const float* __restrict__ bias, float* __restrict__ C,
    __half* __restrict__ Ch, __half* __restrict__ Cl,
    int M, int N, int K, int lda, int ldb, int ldc, float alpha)
{
    extern __shared__ char smem[];
    const uint32_t sb = smem_u32(smem);
    const int tid = threadIdx.x;
    const int wid = tid >> 5, lane = tid & 31;
    const int m0 = blockIdx.y * 128, n0 = blockIdx.x * 128;
    const int wm = (wid >> 1) * 32;
    const int wn = (wid & 1) * 64;

    const char* gA[3] = { (const char*)(Ah + (size_t)m0 * lda),
                          (const char*)(Al + (size_t)m0 * lda),
                          (const char*)(B + (size_t)n0 * ldb) };
    const int glds[3] = { lda, lda, ldb };

    float acc[2][8][4];
#pragma unroll
    for (int i = 0; i < 2; i++)
#pragma unroll
        for (int j = 0; j < 8; j++)
#pragma unroll
            for (int k = 0; k < 4; k++) acc[i][j][k] = 0.f;

    const int NT = K / 64;

    auto issue = [&](int kt, int s) {
        const uint32_t st0 = sb + s * STAGE_B;
#pragma unroll
        for (int t = 0; t < 3; t++) {
            const char* g = gA[t] + (size_t)kt * 128;   // 64 fp16 = 128 B
            const int ldbytes = glds[t] * 2;
            const uint32_t tb = st0 + t * TILE_T;
#pragma unroll
            for (int i = 0; i < 4; i++) {
                int id = tid + i * 256;       // 0..1023
                int r = id >> 3, c = id & 7;
                cp_async16(tb + r * ROWB + c * 16, g + (size_t)r * ldbytes + c * 16);
            }
        }
        cp_commit();
    };

    issue(0, 0);

    for (int kt = 0; kt < NT; kt++) {
        if (kt + 1 < NT) { issue(kt + 1, (kt + 1) & 1); cp_wait<1>(); }
        else cp_wait<0>();
        __syncthreads();

        const uint32_t st0 = sb + (kt & 1) * STAGE_B;
        const uint32_t Ahs = st0 + 0 * TILE_T;
        const uint32_t Als = st0 + 1 * TILE_T;
        const uint32_t Bfs = st0 + 2 * TILE_T;

#pragma unroll
        for (int ks = 0; ks < 4; ks++) {
            const int k16 = ks * 16;
            uint32_t ah[2][4], al[2][4];
#pragma unroll
            for (int mi = 0; mi < 2; mi++) {
                int row = wm + mi * 16 + (lane & 15);
                int col = k16 + ((lane >> 4) << 3);
                ldm_x4(ah[mi], Ahs + row * ROWB + col * 2);
                ldm_x4(al[mi], Als + row * ROWB + col * 2);
            }
            uint32_t bf[4][4];
#pragma unroll
            for (int bi = 0; bi < 4; bi++) {
                int nrow = wn + bi * 16 + (lane & 7) + ((lane >> 4) << 3);
                int col = k16 + (((lane >> 3) & 1) << 3);
                ldm_x4(bf[bi], Bfs + nrow * ROWB + col * 2);
            }
#pragma unroll
            for (int mi = 0; mi < 2; mi++)
#pragma unroll
                for (int nb = 0; nb < 8; nb++) {
                    const uint32_t* bp = &bf[nb >> 1][(nb & 1) * 2];
                    mma_h(acc[mi][nb], ah[mi], bp);
                    mma_h(acc[mi][nb], al[mi], bp);
                }
        }
        __syncthreads();
    }

    const int gid = lane >> 2, tig = lane & 3;
    // OUTMODE 3: whole CTA targets either K (n0<DD) or V (n0>=DD)
    __half* dst3 = (OUTMODE == 3) ? ((n0 < DD) ? Ch : Cl) : nullptr;
    const int ncol3 = (OUTMODE == 3) ? ((n0 < DD) ? n0 : n0 - DD) : 0;

#pragma unroll
    for (int mi = 0; mi < 2; mi++) {
        int r0 = m0 + wm + mi * 16 + gid;
#pragma unroll
        for (int nb = 0; nb < 8; nb++) {
            int c = n0 + wn + nb * 8 + tig * 2;
            float b0 = __ldg(&bias[c]), b1 = __ldg(&bias[c + 1]);
            float v00 = alpha * (acc[mi][nb][0] + b0);
            float v01 = alpha * (acc[mi][nb][1] + b1);
            float v10 = alpha * (acc[mi][nb][2] + b0);
            float v11 = alpha * (acc[mi][nb][3] + b1);
            if (OUTMODE == 0) {
                *(float2*)(C + (size_t)r0 * ldc + c) = make_float2(v00, v01);
                *(float2*)(C + (size_t)(r0 + 8) * ldc + c) = make_float2(v10, v11);
            } else if (OUTMODE == 1) {
                __half h0, h1, h2, h3, l0, l1, l2, l3;
                split1h(v00, h0, l0); split1h(v01, h1, l1);
                split1h(v10, h2, l2); split1h(v11, h3, l3);
                *(__half2*)(Ch + (size_t)r0 * ldc + c) = __halves2half2(h0, h1);
                *(__half2*)(Cl + (size_t)r0 * ldc + c) = __halves2half2(l0, l1);
                *(__half2*)(Ch + (size_t)(r0 + 8) * ldc + c) = __halves2half2(h2, h3);
                *(__half2*)(Cl + (size_t)(r0 + 8) * ldc + c) = __halves2half2(l2, l3);
            } else {
                int cl = ncol3 + wn + nb * 8 + tig * 2;
                *(__half2*)(dst3 + (size_t)r0 * DD + cl) =
                    __halves2half2(__float2half_rn(v00), __float2half_rn(v01));
                *(__half2*)(dst3 + (size_t)(r0 + 8) * DD + cl) =
                    __halves2half2(__float2half_rn(v10), __float2half_rn(v11));
            }
        }
    }
}

// ===========================================================================
// Scores + exp fused: U = exp((Qh+Ql).Kf), write fp16 + per-row partial sums
// M=128 t, N=128 s-tile, K=64. grid (LV/128, HH, BB)
// ===========================================================================
#define SROWB 144
#define STILE (128 * SROWB)
#define SMEM_SC (3 * STILE)            // 55296

__global__ __launch_bounds__(256) void attn_scores_exp(
    const __half* __restrict__ Qh, const __half* __restrict__ Ql,
    const __half* __restrict__ Kf, __half* __restrict__ Uf,
    float* __restrict__ Pp)
{
    extern __shared__ char smem[];
    const uint32_t sb = smem_u32(smem);
    const int st = blockIdx.x, h = blockIdx.y, b = blockIdx.z;
    const int tid = threadIdx.x;
    const int wid = tid >> 5, lane = tid & 31;
    const int wm = (wid >> 1) * 32, wn = (wid & 1) * 64;

    const char* gp[3] = {
        (const char*)(Qh + ((size_t)b * LT) * DD + h * HD),
        (const char*)(Ql + ((size_t)b * LT) * DD + h * HD),
        (const char*)(Kf + ((size_t)b * LV + st * 128) * DD + h * HD) };

#pragma unroll
    for (int i = 0; i < 12; i++) {
        int id = tid + i * 256;
        int t = id >> 10, r = (id >> 3) & 127, c = id & 7;
        cp_async16(sb + t * STILE + r * SROWB + c * 16,
                   gp[t] + (size_t)r * DD * 2 + c * 16);
    }
    cp_commit();
    cp_wait<0>();
    __syncthreads();

    float acc[2][8][4];
#pragma unroll
    for (int i = 0; i < 2; i++)
#pragma unroll
        for (int j = 0; j < 8; j++)
#pragma unroll
            for (int k = 0; k < 4; k++) acc[i][j][k] = 0.f;

    const uint32_t Ahs = sb, Als = sb + STILE, Bfs = sb + 2 * STILE;

#pragma unroll
    for (int ks = 0; ks < 4; ks++) {
        const int k16 = ks * 16;
        uint32_t ah[2][4], al[2][4];
#pragma unroll
        for (int mi = 0; mi < 2; mi++) {
            int row = wm + mi * 16 + (lane & 15);
            int col = k16 + ((lane >> 4) << 3);
            ldm_x4(ah[mi], Ahs + row * SROWB + col * 2);
            ldm_x4(al[mi], Als + row * SROWB + col * 2);
        }
        uint32_t bf[4][4];
#pragma unroll
        for (int bi = 0; bi < 4; bi++) {
            int nrow = wn + bi * 16 + (lane & 7) + ((lane >> 4) << 3);
            int col = k16 + (((lane >> 3) & 1) << 3);
            ldm_x4(bf[bi], Bfs + nrow * SROWB + col * 2);
        }
#pragma unroll
        for (int mi = 0; mi < 2; mi++)
#pragma unroll
            for (int nb = 0; nb < 8; nb++) {
                const uint32_t* bp = &bf[nb >> 1][(nb & 1) * 2];
                mma_h(acc[mi][nb], ah[mi], bp);
                mma_h(acc[mi][nb], al[mi], bp);
            }
    }

    // epilogue: exp, write U, accumulate row partial sums over this 128-s tile
    __half* Ub = Uf + ((size_t)(b * HH + h) * LT) * LV + st * 128;
    const int gid = lane >> 2, tig = lane & 3;
    float ls[4] = {0.f, 0.f, 0.f, 0.f};
#pragma unroll
    for (int mi = 0; mi < 2; mi++) {
        int r0 = wm + mi * 16 + gid;
#pragma unroll
        for (int nb = 0; nb < 8; nb++) {
            int c = wn + nb * 8 + tig * 2;
            float u00 = __expf(acc[mi][nb][0]);
            float u01 = __expf(acc[mi][nb][1]);
            float u10 = __expf(acc[mi][nb][2]);
            float u11 = __expf(acc[mi][nb][3]);
            ls[mi * 2 + 0] += u00 + u01;
            ls[mi * 2 + 1] += u10 + u11;
            *(__half2*)(Ub + (size_t)r0 * LV + c) =
                __halves2half2(__float2half_rn(u00), __float2half_rn(u01));
            *(__half2*)(Ub + (size_t)(r0 + 8) * LV + c) =
                __halves2half2(__float2half_rn(u10), __float2half_rn(u11));
        }
    }
#pragma unroll
    for (int j = 0; j < 4; j++) {
        ls[j] += __shfl_xor_sync(0xFFFFFFFF, ls[j], 1);
        ls[j] += __shfl_xor_sync(0xFFFFFFFF, ls[j], 2);
    }
    __syncthreads();                 // tiles no longer needed; reuse smem
    float* sums = (float*)smem;      // [128][2]
    if (tig == 0) {
#pragma unroll
        for (int j = 0; j < 4; j++) {
            int mi = j >> 1, half = j & 1;
            int row = wm + mi * 16 + gid + 8 * half;
            sums[row * 2 + (wid & 1)] = ls[j];
        }
    }
    __syncthreads();
    if (tid < 128) {
        float d = sums[tid * 2] + sums[tid * 2 + 1];
        Pp[(((size_t)(b * HH + h) * LT) + tid) * 32 + st] = d;
    }
}

// ===========================================================================
// Row scale: scale = 2^16 / D^2
// ===========================================================================
__global__ __launch_bounds__(256) void reduce_scale(
    const float* __restrict__ Pp, float* __restrict__ scale)
{
    int r = blockIdx.x * 256 + threadIdx.x;  // 32768 rows
    float d = 0.f;
#pragma unroll
    for (int j = 0; j < 32; j++) d += Pp[(size_t)r * 32 + j];
    scale[r] = TSCALE / (d * d);
}

// ===========================================================================
// PV: Ypart = Uf[128t, 512s] @ Vf[512s, 64d]. grid (8, HH, BB)
// ===========================================================================
#define PV_AROW 80
#define PV_ATILE (128 * PV_AROW)        // 10240
#define PV_BROW 144
#define PV_BTILE (32 * PV_BROW)         // 4608
#define PV_STAGE (PV_ATILE + PV_BTILE)  // 14848
#define SMEM_PV (2 * PV_STAGE)          // 29696

__global__ __launch_bounds__(256) void attn_pv_mma(
    const __half* __restrict__ Uf, const __half* __restrict__ Vf,
    float* __restrict__ Tp)
{
    extern __shared__ char smem[];
    const uint32_t sb = smem_u32(smem);
    const int seg = blockIdx.x, h = blockIdx.y, b = blockIdx.z;
    const int tid = threadIdx.x;
    const int wid = tid >> 5, lane = tid & 31;
    const int wm = (wid >> 1) * 32, wn = (wid & 1) * 32;

    const char* pA = (const char*)(Uf + ((size_t)(b * HH + h) * LT) * LV + seg * 512);
    const char* pB = (const char*)(Vf + ((size_t)b * LV + seg * 512) * DD + h * HD);

    auto issue = [&](int kt, int s) {
        const uint32_t st0 = sb + s * PV_STAGE;
#pragma unroll
        for (int i = 0; i < 2; i++) {            // A: 512 chunks
            int id = tid + i * 256;
            int r = id >> 2, c = id & 3;
            cp_async16(st0 + r * PV_AROW + c * 16,
                       pA + (size_t)r * LV * 2 + (size_t)kt * 64 + c * 16);
        }
        {                                         // B: 256 chunks
            int r = tid >> 3, c = tid & 7;
            cp_async16(st0 + PV_ATILE + r * PV_BROW + c * 16,
                       pB + ((size_t)kt * 32 + r) * DD * 2 + c * 16);
        }
        cp_commit();
    };

    float acc[2][4][4];
#pragma unroll
    for (int i = 0; i < 2; i++)
#pragma unroll
        for (int j = 0; j < 4; j++)
#pragma unroll
            for (int k = 0; k < 4; k++) acc[i][j][k] = 0.f;

    issue(0, 0);
    for (int kt = 0; kt < 16; kt++) {
        if (kt + 1 < 16) { issue(kt + 1, (kt + 1) & 1); cp_wait<1>(); }
        else cp_wait<0>();
        __syncthreads();

        const uint32_t st0 = sb + (kt & 1) * PV_STAGE;
        const uint32_t Aus = st0, Bfs = st0 + PV_ATILE;

#pragma unroll
        for (int ks = 0; ks < 2; ks++) {
            const int k16 = ks * 16;
            uint32_t au[2][4];
#pragma unroll
            for (int mi = 0; mi < 2; mi++) {
                int row = wm + mi * 16 + (lane & 15);
                int col = k16 + ((lane >> 4) << 3);
                ldm_x4(au[mi], Aus + row * PV_AROW + col * 2);
            }
            uint32_t bf[2][4];
#pragma unroll
            for (int bi = 0; bi < 2; bi++) {
                int srow = k16 + ((lane >> 4) << 3) + (lane & 7);
                int dcol = wn + bi * 16 + (((lane >> 3) & 1) << 3);
                ldm_x4_t(bf[bi], Bfs + srow * PV_BROW + dcol * 2);
            }
#pragma unroll
            for (int mi = 0; mi < 2; mi++)
#pragma unroll
                for (int nb = 0; nb < 4; nb++) {
                    const int bi = nb >> 1, j = nb & 1;
                    mma_hv(acc[mi][nb], au[mi], bf[bi][j], bf[bi][j + 2]);
                }
        }
        __syncthreads();
    }

    float* Tb = Tp + (size_t)seg * (BB * HH * LT * HD) + ((size_t)(b * HH + h) * LT) * HD;
    const int gid = lane >> 2, tig = lane & 3;
#pragma unroll
    for (int mi = 0; mi < 2; mi++) {
        int r0 = wm + mi * 16 + gid;
#pragma unroll
        for (int nb = 0; nb < 4; nb++) {
            int c = wn + nb * 8 + tig * 2;
            *(float2*)(Tb + (size_t)r0 * HD + c) = make_float2(acc[mi][nb][0], acc[mi][nb][1]);
            *(float2*)(Tb + (size_t)(r0 + 8) * HD + c) = make_float2(acc[mi][nb][2], acc[mi][nb][3]);
        }
    }
}

// reduce partials + apply 2^16/D^2
__global__ __launch_bounds__(256) void reduce_T(
    const float* __restrict__ Tp, const float* __restrict__ scale,
    __half* __restrict__ Tf)
{
    size_t i = (size_t)blockIdx.x * 256 + threadIdx.x;
    float s = 0.f;
#pragma unroll
    for (int g = 0; g < 8; g++) s += Tp[(size_t)g * (BB * HH * LT * HD) + i];
    Tf[i] = __float2half_rn(s * scale[i >> 6]);   // row = i / HD
}

// ===========================================================================
// OUT: O[128s, 64d] = 2^-16 * U^T[128s,128t] @ Tf[128t, 64d] -> hi/lo
// ===========================================================================
#define AO_AROW 272
#define AO_ATILE (32 * AO_AROW)         // 8704
#define AO_BROW 144
#define AO_BTILE (32 * AO_BROW)         // 4608
#define AO_STAGE (AO_ATILE + AO_BTILE)  // 13312
#define SMEM_AO (2 * AO_STAGE)          // 26624

__global__ __launch_bounds__(256) void attn_out_mma(
    const __half* __restrict__ Uf, const __half* __restrict__ Tf,
    __half* __restrict__ Ohi, __half* __restrict__ Olo)
{
    extern __shared__ char smem[];
    const uint32_t sb = smem_u32(smem);
    const int st = blockIdx.x, h = blockIdx.y, b = blockIdx.z;
    const int tid = threadIdx.x;
    const int wid = tid >> 5, lane = tid & 31;
    const int wm = (wid >> 1) * 32, wn = (wid & 1) * 32;

    const char* pA = (const char*)(Uf + ((size_t)(b * HH + h) * LT) * LV + st * 128);
    const char* pB = (const char*)(Tf + ((size_t)(b * HH + h) * LT) * HD);

    auto issue = [&](int kt, int s) {
        const uint32_t st0 = sb + s * AO_STAGE;
#pragma unroll
        for (int i = 0; i < 2; i++) {            // A: 512 chunks
            int id = tid + i * 256;
            int r = id >> 4, c = id & 15;
            cp_async16(st0 + r * AO_AROW + c * 16,
                       pA + ((size_t)kt * 32 + r) * LV * 2 + c * 16);
        }
        {                                         // B: 256 chunks
            int r = tid >> 3, c = tid & 7;
            cp_async16(st0 + AO_ATILE + r * AO_BROW + c * 16,
                       pB + ((size_t)kt * 32 + r) * HD * 2 + c * 16);
        }
        cp_commit();
    };

    float acc[2][4][4];
#pragma unroll
    for (int i = 0; i < 2; i++)
#pragma unroll
        for (int j = 0; j < 4; j++)
#pragma unroll
            for (int k = 0; k < 4; k++) acc[i][j][k] = 0.f;

    issue(0, 0);
    for (int kt = 0; kt < 4; kt++) {
        if (kt + 1 < 4) { issue(kt + 1, (kt + 1) & 1); cp_wait<1>(); }
        else cp_wait<0>();
        __syncthreads();

        const uint32_t st0 = sb + (kt & 1) * AO_STAGE;
        const uint32_t Aus = st0, Bfs = st0 + AO_ATILE;

#pragma unroll
        for (int ks = 0; ks < 2; ks++) {
            const int k16 = ks * 16;
            uint32_t au[2][4];
#pragma unroll
            for (int mi = 0; mi < 2; mi++) {
                int trow = k16 + ((lane >> 4) << 3) + (lane & 7);
                int scol = wm + mi * 16 + (((lane >> 3) & 1) << 3);
                ldm_x4_t(au[mi], Aus + trow * AO_AROW + scol * 2);
            }
            uint32_t bf[2][4];
#pragma unroll
            for (int bi = 0; bi < 2; bi++) {
                int trow = k16 + ((lane >> 4) << 3) + (lane & 7);
                int dcol = wn + bi * 16 + (((lane >> 3) & 1) << 3);
                ldm_x4_t(bf[bi], Bfs + trow * AO_BROW + dcol * 2);
            }
#pragma unroll
            for (int mi = 0; mi < 2; mi++)
#pragma unroll
                for (int nb = 0; nb < 4; nb++) {
                    const int bi = nb >> 1, j = nb & 1;
                    mma_hv(acc[mi][nb], au[mi], bf[bi][j], bf[bi][j + 2]);
                }
        }
        __syncthreads();
    }

    const float inv = 1.f / TSCALE;
    const int gid = lane >> 2, tig = lane & 3;
#pragma unroll
    for (int mi = 0; mi < 2; mi++) {
        int srow = st * 128 + wm + mi * 16 + gid;
#pragma unroll
        for (int nb = 0; nb < 4; nb++) {
            int c = h * HD + wn + nb * 8 + tig * 2;
            size_t o0 = ((size_t)b * LV + srow) * DD + c;
            size_t o1 = ((size_t)b * LV + srow + 8) * DD + c;
            __half h0, h1, h2, h3, l0, l1, l2, l3;
            split1h(acc[mi][nb][0] * inv, h0, l0); split1h(acc[mi][nb][1] * inv, h1, l1);
            split1h(acc[mi][nb][2] * inv, h2, l2); split1h(acc[mi][nb][3] * inv, h3, l3);
            *(__half2*)(Ohi + o0) = __halves2half2(h0, h1);
            *(__half2*)(Olo + o0) = __halves2half2(l0, l1);
            *(__half2*)(Ohi + o1) = __halves2half2(h2, h3);
            *(__half2*)(Olo + o1) = __halves2half2(l2, l3);
        }
    }
}

// ===========================================================================
// Launch
// ===========================================================================
extern "C" void kernel_launch(void* const* d_in, const int* in_sizes, int n_in,
                              void* d_out, int out_size)
{
    const float* hidden = (const float*)d_in[0];
    const float* text   = (const float*)d_in[1];
    const float* Wq = (const float*)d_in[2];
    const float* bq = (const float*)d_in[3];
    const float* Wk = (const float*)d_in[4];
    const float* bk = (const float*)d_in[5];
    const float* Wv = (const float*)d_in[6];
    const float* bv = (const float*)d_in[7];
    const float* Wo = (const float*)d_in[8];
    const float* bo = (const float*)d_in[9];
    float* out = (float*)d_out;

    __half *txh, *txl, *hdh, *hdl, *Wt;
    __half *Qh, *Ql, *Kf, *Vf, *Uf, *Tf, *Ohi, *Olo;
    float *Pp, *scl, *Tp, *bkv;
    cudaGetSymbolAddress((void**)&txh, g_txh);
    cudaGetSymbolAddress((void**)&txl, g_txl);
    cudaGetSymbolAddress((void**)&hdh, g_hdh);
    cudaGetSymbolAddress((void**)&hdl, g_hdl);
    cudaGetSymbolAddress((void**)&Wt, g_Wt);
    cudaGetSymbolAddress((void**)&bkv, g_bkv);
    cudaGetSymbolAddress((void**)&Qh, g_Qh);
    cudaGetSymbolAddress((void**)&Ql, g_Ql);
    cudaGetSymbolAddress((void**)&Kf, g_Kf);
    cudaGetSymbolAddress((void**)&Vf, g_Vf);
    cudaGetSymbolAddress((void**)&Uf, g_Uf);
    cudaGetSymbolAddress((void**)&Pp, g_Pp);
    cudaGetSymbolAddress((void**)&scl, g_scale);
    cudaGetSymbolAddress((void**)&Tp, g_Tp);
    cudaGetSymbolAddress((void**)&Tf, g_Tf);
    cudaGetSymbolAddress((void**)&Ohi, g_Ohi);
    cudaGetSymbolAddress((void**)&Olo, g_Olo);

    cudaFuncSetAttribute(gemm_f16x2<0>, cudaFuncAttributeMaxDynamicSharedMemorySize, SMEM_GEMM);
    cudaFuncSetAttribute(gemm_f16x2<1>, cudaFuncAttributeMaxDynamicSharedMemorySize, SMEM_GEMM);
    cudaFuncSetAttribute(gemm_f16x2<3>, cudaFuncAttributeMaxDynamicSharedMemorySize, SMEM_GEMM);
    cudaFuncSetAttribute(attn_scores_exp, cudaFuncAttributeMaxDynamicSharedMemorySize, SMEM_SC);
    cudaFuncSetAttribute(attn_pv_mma, cudaFuncAttributeMaxDynamicSharedMemorySize, SMEM_PV);
    cudaFuncSetAttribute(attn_out_mma, cudaFuncAttributeMaxDynamicSharedMemorySize, SMEM_AO);

    const size_t WSZ = (size_t)DD * DD;

    // 1. input splits
    split_hl<<<(BB * LT * DD) / 1024, 256>>>(text, txh, txl, (size_t)BB * LT * DD);
    split_hl<<<(BB * LV * DD) / 1024, 256>>>(hidden, hdh, hdl, (size_t)BB * LV * DD);

    // 2. weight transpose + bias concat
    dim3 wt(32, 32);
    wtrans_h<<<wt, dim3(32, 8)>>>(Wq, Wt + 0 * WSZ);
    wtrans_h<<<wt, dim3(32, 8)>>>(Wk, Wt + 1 * WSZ);
    wtrans_h<<<wt, dim3(32, 8)>>>(Wv, Wt + 2 * WSZ);
    wtrans_h<<<wt, dim3(32, 8)>>>(Wo, Wt + 3 * WSZ);
    concat_bias<<<8, 256>>>(bk, bv, bkv);

    // 3. projections: Q (hi/lo out), fused K+V (single fp16 out)
    gemm_f16x2<1><<<dim3(DD / 128, (BB * LT) / 128), 256, SMEM_GEMM>>>(
        txh, txl, Wt + 0 * WSZ, bq, nullptr, Qh, Ql,
        BB * LT, DD, DD, DD, DD, DD, QSCALE);
    gemm_f16x2<3><<<dim3(2 * DD / 128, (BB * LV) / 128), 256, SMEM_GEMM>>>(
        hdh, hdl, Wt + 1 * WSZ, bkv, nullptr, Kf, Vf,
        BB * LV, 2 * DD, DD, DD, DD, DD, 1.0f);

    // 4. attention
    attn_scores_exp<<<dim3(LV / 128, HH, BB), 256, SMEM_SC>>>(Qh, Ql, Kf, Uf, Pp);
    reduce_scale<<<BB * HH * LT / 256, 256>>>(Pp, scl);
    attn_pv_mma<<<dim3(8, HH, BB), 256, SMEM_PV>>>(Uf, Vf, Tp);
    reduce_T<<<(BB * HH * LT * HD) / 256, 256>>>(Tp, scl, Tf);
    attn_out_mma<<<dim3(LV / 128, HH, BB), 256, SMEM_AO>>>(Uf, Tf, Ohi, Olo);

    // 5. output projection -> fp32 out
    gemm_f16x2<0><<<dim3(DD / 128, (BB * LV) / 128), 256, SMEM_GEMM>>>(
        Ohi, Olo, Wt + 3 * WSZ, bo, out, nullptr, nullptr,
        BB * LV, DD, DD, DD, DD, DD, 1.0f);
}

// round 8
// speedup vs baseline: 4.2258x; 1.1894x over previous
#include <cuda_runtime.h>
#include <cuda_fp16.h>
#include <cstdint>
#include <cstddef>

// Problem constants
#define BB 16
#define LT 128
#define LV 4096
#define DD 1024
#define HH 16
#define HD 64
static constexpr float QSCALE = 0.125f;   // 64^-0.5
static constexpr float TSCALE = 65536.f;  // keeps Tf in fp16 normal range

// ===========================================================================
// Scratch (device globals) — all single fp16
// ===========================================================================
__device__ __half g_txf[(size_t)BB * LT * DD];
__device__ __half g_hdf[(size_t)BB * LV * DD];
__device__ __half g_Wt[4][(size_t)DD * DD];        // W^T fp16 (N,K); 1=Wk,2=Wv adjacent
__device__ float  g_bkv[2 * DD];
__device__ __half g_Qf[(size_t)BB * LT * DD];
__device__ __half g_Kf[(size_t)BB * LV * DD];
__device__ __half g_Vf[(size_t)BB * LV * DD];
__device__ __half g_Uf[(size_t)BB * HH * LT * LV]; // exp(S) unnormalized
__device__ float  g_Pp[(size_t)BB * HH * LT * 32]; // row partial sums (32 s-tiles)
__device__ float  g_scale[(size_t)BB * HH * LT];   // 2^16 / D^2
__device__ float  g_Tp[8][(size_t)BB * HH * LT * HD];
__device__ __half g_Tf[(size_t)BB * HH * LT * HD]; // Y/D^2 * 2^16
__device__ __half g_Of[(size_t)BB * LV * DD];

// ===========================================================================
// PTX helpers (arch-portable)
// ===========================================================================
__device__ __forceinline__ uint32_t smem_u32(const void* p) {
    uint32_t a;
    asm("{ .reg .u64 t; cvta.to.shared.u64 t, %1; cvt.u32.u64 %0, t; }" : "=r"(a) : "l"(p));
    return a;
}
__device__ __forceinline__ void cp_async16(uint32_t dst, const void* src) {
    asm volatile("cp.async.cg.shared.global [%0], [%1], 16;" :: "r"(dst), "l"(src));
}
__device__ __forceinline__ void cp_commit() { asm volatile("cp.async.commit_group;"); }
template <int N>
__device__ __forceinline__ void cp_wait() { asm volatile("cp.async.wait_group %0;" :: "n"(N)); }

__device__ __forceinline__ void ldm_x4(uint32_t* r, uint32_t addr) {
    asm volatile("ldmatrix.sync.aligned.m8n8.x4.shared.b16 {%0,%1,%2,%3}, [%4];"
                 : "=r"(r[0]), "=r"(r[1]), "=r"(r[2]), "=r"(r[3]) : "r"(addr));
}
__device__ __forceinline__ void ldm_x4_t(uint32_t* r, uint32_t addr) {
    asm volatile("ldmatrix.sync.aligned.m8n8.x4.trans.shared.b16 {%0,%1,%2,%3}, [%4];"
                 : "=r"(r[0]), "=r"(r[1]), "=r"(r[2]), "=r"(r[3]) : "r"(addr));
}
__device__ __forceinline__ void mma_h(float* c, const uint32_t* a, const uint32_t* b) {
    asm volatile(
        "mma.sync.aligned.m16n8k16.row.col.f32.f16.f16.f32 "
        "{%0,%1,%2,%3}, {%4,%5,%6,%7}, {%8,%9}, {%0,%1,%2,%3};"
        : "+f"(c[0]), "+f"(c[1]), "+f"(c[2]), "+f"(c[3])
        : "r"(a[0]), "r"(a[1]), "r"(a[2]), "r"(a[3]), "r"(b[0]), "r"(b[1]));
}
__device__ __forceinline__ void mma_hv(float* c, const uint32_t* a, uint32_t b0, uint32_t b1) {
    asm volatile(
        "mma.sync.aligned.m16n8k16.row.col.f32.f16.f16.f32 "
        "{%0,%1,%2,%3}, {%4,%5,%6,%7}, {%8,%9}, {%0,%1,%2,%3};"
        : "+f"(c[0]), "+f"(c[1]), "+f"(c[2]), "+f"(c[3])
        : "r"(a[0]), "r"(a[1]), "r"(a[2]), "r"(a[3]), "r"(b0), "r"(b1));
}

// ===========================================================================
// fp32 -> fp16 convert (elementwise)
// ===========================================================================
__global__ __launch_bounds__(256) void conv_h(
    const float* __restrict__ in, __half* __restrict__ o, size_t n)
{
    size_t i = ((size_t)blockIdx.x * 256 + threadIdx.x) * 4;
    if (i >= n) return;
    float4 v = *(const float4*)(in + i);
    __half2* op = (__half2*)(o + i);
    op[0] = __halves2half2(__float2half_rn(v.x), __float2half_rn(v.y));
    op[1] = __halves2half2(__float2half_rn(v.z), __float2half_rn(v.w));
}

// ===========================================================================
// Weight transpose to fp16 + bias concat
// ===========================================================================
__global__ __launch_bounds__(256) void wtrans_h(
    const float* __restrict__ W, __half* __restrict__ Wt)
{
    __shared__ float t[32][33];
    int bx = blockIdx.x, by = blockIdx.y;
    int x = threadIdx.x, y = threadIdx.y;
#pragma unroll
    for (int i = 0; i < 32; i += 8)
        t[y + i][x] = W[(size_t)(by * 32 + y + i) * DD + bx * 32 + x];
    __syncthreads();
#pragma unroll
    for (int i = 0; i < 32; i += 8)
        Wt[(size_t)(bx * 32 + y + i) * DD + by * 32 + x] = __float2half_rn(t[x][y + i]);
}

__global__ __launch_bounds__(256) void concat_bias(
    const float* __restrict__ bk, const float* __restrict__ bv, float* __restrict__ b2)
{
    int i = blockIdx.x * 256 + threadIdx.x;
    if (i < DD) b2[i] = bk[i];
    else if (i < 2 * DD) b2[i] = bv[i - DD];
}

// ===========================================================================
// HMMA fp16 GEMM: C = alpha*(A @ B^T + bias)
// A: [M,K] fp16 (lda). B: [N,K] fp16 (ldb).
// Tile 128x128, BK=64, 8 warps 4x2 (warp 32x64), 3-stage cp.async.
// OUTMODE 0: fp32 C.  2: fp16 single (Ch).  3: fp16 split KV (Ch=K, Cl=V).
// ===========================================================================
#define ROWB 144                        // 64 fp16 = 128 B + 16 pad
#define TILE_T (128 * ROWB)             // 18432
#define STAGE_B (2 * TILE_T)            // 36864 (A, B)
#define SMEM_GEMM (3 * STAGE_B)         // 110592

template <int OUTMODE>
__global__ __launch_bounds__(256) void gemm_f16(
    const __half* __restrict__ A, const __half* __restrict__ B,
    const float* __restrict__ bias, float* __restrict__ C,
    __half* __restrict__ Ch, __half* __restrict__ Cl,
    int M, int N, int K, int lda, int ldb, int ldc, float alpha)
{
    extern __shared__ char smem[];
    const uint32_t sb = smem_u32(smem);
    const int tid = threadIdx.x;
    const int wid = tid >> 5, lane = tid & 31;
    const int m0 = blockIdx.y * 128, n0 = blockIdx.x * 128;
    const int wm = (wid >> 1) * 32;
    const int wn = (wid & 1) * 64;

    const char* gA[2] = { (const char*)(A + (size_t)m0 * lda),
                          (const char*)(B + (size_t)n0 * ldb) };
    const int glds[2] = { lda, ldb };

    float acc[2][8][4];
#pragma unroll
    for (int i = 0; i < 2; i++)
#pragma unroll
        for (int j = 0; j < 8; j++)
#pragma unroll
            for (int k = 0; k < 4; k++) acc[i][j][k] = 0.f;

    const int NT = K / 64;

    auto issue = [&](int kt, int s) {
        const uint32_t st0 = sb + s * STAGE_B;
#pragma unroll
        for (int t = 0; t < 2; t++) {
            const char* g = gA[t] + (size_t)kt * 128;   // 64 fp16 = 128 B
            const int ldbytes = glds[t] * 2;
            const uint32_t tb = st0 + t * TILE_T;
#pragma unroll
            for (int i = 0; i < 4; i++) {
                int id = tid + i * 256;       // 0..1023
                int r = id >> 3, c = id & 7;
                cp_async16(tb + r * ROWB + c * 16, g + (size_t)r * ldbytes + c * 16);
            }
        }
        cp_commit();
    };

    issue(0, 0);
    issue(1, 1);

    for (int kt = 0; kt < NT; kt++) {
        if (kt + 2 < NT) { issue(kt + 2, (kt + 2) % 3); cp_wait<2>(); }
        else if (kt + 1 < NT) cp_wait<1>();
        else cp_wait<0>();
        __syncthreads();

        const uint32_t st0 = sb + (kt % 3) * STAGE_B;
        const uint32_t Afs = st0;
        const uint32_t Bfs = st0 + TILE_T;

#pragma unroll
        for (int ks = 0; ks < 4; ks++) {
            const int k16 = ks * 16;
            uint32_t af[2][4];
#pragma unroll
            for (int mi = 0; mi < 2; mi++) {
                int row = wm + mi * 16 + (lane & 15);
                int col = k16 + ((lane >> 4) << 3);
                ldm_x4(af[mi], Afs + row * ROWB + col * 2);
            }
            uint32_t bf[4][4];
#pragma unroll
            for (int bi = 0; bi < 4; bi++) {
                int nrow = wn + bi * 16 + (lane & 7) + ((lane >> 4) << 3);
                int col = k16 + (((lane >> 3) & 1) << 3);
                ldm_x4(bf[bi], Bfs + nrow * ROWB + col * 2);
            }
#pragma unroll
            for (int mi = 0; mi < 2; mi++)
#pragma unroll
                for (int nb = 0; nb < 8; nb++)
                    mma_h(acc[mi][nb], af[mi], &bf[nb >> 1][(nb & 1) * 2]);
        }
        __syncthreads();
    }

    const int gid = lane >> 2, tig = lane & 3;
    __half* dst3 = (OUTMODE == 3) ? ((n0 < DD) ? Ch : Cl) : Ch;
    const int ncol3 = (OUTMODE == 3 && n0 >= DD) ? n0 - DD : n0;

#pragma unroll
    for (int mi = 0; mi < 2; mi++) {
        int r0 = m0 + wm + mi * 16 + gid;
#pragma unroll
        for (int nb = 0; nb < 8; nb++) {
            int c = n0 + wn + nb * 8 + tig * 2;
            float b0 = __ldg(&bias[c]), b1 = __ldg(&bias[c + 1]);
            float v00 = alpha * (acc[mi][nb][0] + b0);
            float v01 = alpha * (acc[mi][nb][1] + b1);
            float v10 = alpha * (acc[mi][nb][2] + b0);
            float v11 = alpha * (acc[mi][nb][3] + b1);
            if (OUTMODE == 0) {
                *(float2*)(C + (size_t)r0 * ldc + c) = make_float2(v00, v01);
                *(float2*)(C + (size_t)(r0 + 8) * ldc + c) = make_float2(v10, v11);
            } else {
                int cl = ncol3 + wn + nb * 8 + tig * 2;
                *(__half2*)(dst3 + (size_t)r0 * DD + cl) =
                    __halves2half2(__float2half_rn(v00), __float2half_rn(v01));
                *(__half2*)(dst3 + (size_t)(r0 + 8) * DD + cl) =
                    __halves2half2(__float2half_rn(v10), __float2half_rn(v11));
            }
        }
    }
}

// ===========================================================================
// Scores + exp fused: U = exp(Qf.Kf), fp16 out + per-row partial sums
// M=128 t, N=128 s-tile, K=64. grid (LV/128, HH, BB)
// ===========================================================================
#define SROWB 144
#define STILE (128 * SROWB)
#define SMEM_SC (2 * STILE)            // 36864

__global__ __launch_bounds__(256) void attn_scores_exp(
    const __half* __restrict__ Qf, const __half* __restrict__ Kf,
    __half* __restrict__ Uf, float* __restrict__ Pp)
{
    extern __shared__ char smem[];
    const uint32_t sb = smem_u32(smem);
    const int st = blockIdx.x, h = blockIdx.y, b = blockIdx.z;
    const int tid = threadIdx.x;
    const int wid = tid >> 5, lane = tid & 31;
    const int wm = (wid >> 1) * 32, wn = (wid & 1) * 64;

    const char* gp[2] = {
        (const char*)(Qf + ((size_t)b * LT) * DD + h * HD),
        (const char*)(Kf + ((size_t)b * LV + st * 128) * DD + h * HD) };

#pragma unroll
    for (int i = 0; i < 8; i++) {
        int id = tid + i * 256;
        int t = id >> 10, r = (id >> 3) & 127, c = id & 7;
        cp_async16(sb + t * STILE + r * SROWB + c * 16,
                   gp[t] + (size_t)r * DD * 2 + c * 16);
    }
    cp_commit();
    cp_wait<0>();
    __syncthreads();

    float acc[2][8][4];
#pragma unroll
    for (int i = 0; i < 2; i++)
#pragma unroll
        for (int j = 0; j < 8; j++)
#pragma unroll
            for (int k = 0; k < 4; k++) acc[i][j][k] = 0.f;

    const uint32_t Afs = sb, Bfs = sb + STILE;

#pragma unroll
    for (int ks = 0; ks < 4; ks++) {
        const int k16 = ks * 16;
        uint32_t af[2][4];
#pragma unroll
        for (int mi = 0; mi < 2; mi++) {
            int row = wm + mi * 16 + (lane & 15);
            int col = k16 + ((lane >> 4) << 3);
            ldm_x4(af[mi], Afs + row * SROWB + col * 2);
        }
        uint32_t bf[4][4];
#pragma unroll
        for (int bi = 0; bi < 4; bi++) {
            int nrow = wn + bi * 16 + (lane & 7) + ((lane >> 4) << 3);
            int col = k16 + (((lane >> 3) & 1) << 3);
            ldm_x4(bf[bi], Bfs + nrow * SROWB + col * 2);
        }
#pragma unroll
        for (int mi = 0; mi < 2; mi++)
#pragma unroll
            for (int nb = 0; nb < 8; nb++)
                mma_h(acc[mi][nb], af[mi], &bf[nb >> 1][(nb & 1) * 2]);
    }

    // epilogue: exp, write U, accumulate row partial sums for this 128-s tile
    __half* Ub = Uf + ((size_t)(b * HH + h) * LT) * LV + st * 128;
    const int gid = lane >> 2, tig = lane & 3;
    float ls[4] = {0.f, 0.f, 0.f, 0.f};
#pragma unroll
    for (int mi = 0; mi < 2; mi++) {
        int r0 = wm + mi * 16 + gid;
#pragma unroll
        for (int nb = 0; nb < 8; nb++) {
            int c = wn + nb * 8 + tig * 2;
            float u00 = __expf(acc[mi][nb][0]);
            float u01 = __expf(acc[mi][nb][1]);
            float u10 = __expf(acc[mi][nb][2]);
            float u11 = __expf(acc[mi][nb][3]);
            ls[mi * 2 + 0] += u00 + u01;
            ls[mi * 2 + 1] += u10 + u11;
            *(__half2*)(Ub + (size_t)r0 * LV + c) =
                __halves2half2(__float2half_rn(u00), __float2half_rn(u01));
            *(__half2*)(Ub + (size_t)(r0 + 8) * LV + c) =
                __halves2half2(__float2half_rn(u10), __float2half_rn(u11));
        }
    }
#pragma unroll
    for (int j = 0; j < 4; j++) {
        ls[j] += __shfl_xor_sync(0xFFFFFFFF, ls[j], 1);
        ls[j] += __shfl_xor_sync(0xFFFFFFFF, ls[j], 2);
    }
    __syncthreads();
    float* sums = (float*)smem;      // [128][2]
    if (tig == 0) {
#pragma unroll
        for (int j = 0; j < 4; j++) {
            int mi = j >> 1, half = j & 1;
            int row = wm + mi * 16 + gid + 8 * half;
            sums[row * 2 + (wid & 1)] = ls[j];
        }
    }
    __syncthreads();
    if (tid < 128) {
        float d = sums[tid * 2] + sums[tid * 2 + 1];
        Pp[(((size_t)(b * HH + h) * LT) + tid) * 32 + st] = d;
    }
}

// ===========================================================================
// Row scale: scale = 2^16 / D^2
// ===========================================================================
__global__ __launch_bounds__(256) void reduce_scale(
    const float* __restrict__ Pp, float* __restrict__ scale)
{
    int r = blockIdx.x * 256 + threadIdx.x;
    float d = 0.f;
#pragma unroll
    for (int j = 0; j < 32; j++) d += Pp[(size_t)r * 32 + j];
    scale[r] = TSCALE / (d * d);
}

// ===========================================================================
// PV: Ypart = Uf[128t, 512s] @ Vf[512s, 64d]. grid (8, HH, BB)
// ===========================================================================
#define PV_AROW 80
#define PV_ATILE (128 * PV_AROW)        // 10240
#define PV_BROW 144
#define PV_BTILE (32 * PV_BROW)         // 4608
#define PV_STAGE (PV_ATILE + PV_BTILE)  // 14848
#define SMEM_PV (2 * PV_STAGE)          // 29696

__global__ __launch_bounds__(256) void attn_pv_mma(
    const __half* __restrict__ Uf, const __half* __restrict__ Vf,
    float* __restrict__ Tp)
{
    extern __shared__ char smem[];
    const uint32_t sb = smem_u32(smem);
    const int seg = blockIdx.x, h = blockIdx.y, b = blockIdx.z;
    const int tid = threadIdx.x;
    const int wid = tid >> 5, lane = tid & 31;
    const int wm = (wid >> 1) * 32, wn = (wid & 1) * 32;

    const char* pA = (const char*)(Uf + ((size_t)(b * HH + h) * LT) * LV + seg * 512);
    const char* pB = (const char*)(Vf + ((size_t)b * LV + seg * 512) * DD + h * HD);

    auto issue = [&](int kt, int s) {
        const uint32_t st0 = sb + s * PV_STAGE;
#pragma unroll
        for (int i = 0; i < 2; i++) {
            int id = tid + i * 256;
            int r = id >> 2, c = id & 3;
            cp_async16(st0 + r * PV_AROW + c * 16,
                       pA + (size_t)r * LV * 2 + (size_t)kt * 64 + c * 16);
        }
        {
            int r = tid >> 3, c = tid & 7;
            cp_async16(st0 + PV_ATILE + r * PV_BROW + c * 16,
                       pB + ((size_t)kt * 32 + r) * DD * 2 + c * 16);
        }
        cp_commit();
    };

    float acc[2][4][4];
#pragma unroll
    for (int i = 0; i < 2; i++)
#pragma unroll
        for (int j = 0; j < 4; j++)
#pragma unroll
            for (int k = 0; k < 4; k++) acc[i][j][k] = 0.f;

    issue(0, 0);
    for (int kt = 0; kt < 16; kt++) {
        if (kt + 1 < 16) { issue(kt + 1, (kt + 1) & 1); cp_wait<1>(); }
        else cp_wait<0>();
        __syncthreads();

        const uint32_t st0 = sb + (kt & 1) * PV_STAGE;
        const uint32_t Aus = st0, Bfs = st0 + PV_ATILE;

#pragma unroll
        for (int ks = 0; ks < 2; ks++) {
            const int k16 = ks * 16;
            uint32_t au[2][4];
#pragma unroll
            for (int mi = 0; mi < 2; mi++) {
                int row = wm + mi * 16 + (lane & 15);
                int col = k16 + ((lane >> 4) << 3);
                ldm_x4(au[mi], Aus + row * PV_AROW + col * 2);
            }
            uint32_t bf[2][4];
#pragma unroll
            for (int bi = 0; bi < 2; bi++) {
                int srow = k16 + ((lane >> 4) << 3) + (lane & 7);
                int dcol = wn + bi * 16 + (((lane >> 3) & 1) << 3);
                ldm_x4_t(bf[bi], Bfs + srow * PV_BROW + dcol * 2);
            }
#pragma unroll
            for (int mi = 0; mi < 2; mi++)
#pragma unroll
                for (int nb = 0; nb < 4; nb++) {
                    const int bi = nb >> 1, j = nb & 1;
                    mma_hv(acc[mi][nb], au[mi], bf[bi][j], bf[bi][j + 2]);
                }
        }
        __syncthreads();
    }

    float* Tb = Tp + (size_t)seg * (BB * HH * LT * HD) + ((size_t)(b * HH + h) * LT) * HD;
    const int gid = lane >> 2, tig = lane & 3;
#pragma unroll
    for (int mi = 0; mi < 2; mi++) {
        int r0 = wm + mi * 16 + gid;
#pragma unroll
        for (int nb = 0; nb < 4; nb++) {
            int c = wn + nb * 8 + tig * 2;
            *(float2*)(Tb + (size_t)r0 * HD + c) = make_float2(acc[mi][nb][0], acc[mi][nb][1]);
            *(float2*)(Tb + (size_t)(r0 + 8) * HD + c) = make_float2(acc[mi][nb][2], acc[mi][nb][3]);
        }
    }
}

// reduce partials + apply 2^16/D^2
__global__ __launch_bounds__(256) void reduce_T(
    const float* __restrict__ Tp, const float* __restrict__ scale,
    __half* __restrict__ Tf)
{
    size_t i = (size_t)blockIdx.x * 256 + threadIdx.x;
    float s = 0.f;
#pragma unroll
    for (int g = 0; g < 8; g++) s += Tp[(size_t)g * (BB * HH * LT * HD) + i];
    Tf[i] = __float2half_rn(s * scale[i >> 6]);
}

// ===========================================================================
// OUT: O[128s, 64d] = 2^-16 * U^T[128s,128t] @ Tf[128t, 64d] -> fp16 single
// ===========================================================================
#define AO_AROW 272
#define AO_ATILE (32 * AO_AROW)         // 8704
#define AO_BROW 144
#define AO_BTILE (32 * AO_BROW)         // 4608
#define AO_STAGE (AO_ATILE + AO_BTILE)  // 13312
#define SMEM_AO (2 * AO_STAGE)          // 26624

__global__ __launch_bounds__(256) void attn_out_mma(
    const __half* __restrict__ Uf, const __half* __restrict__ Tf,
    __half* __restrict__ Of)
{
    extern __shared__ char smem[];
    const uint32_t sb = smem_u32(smem);
    const int st = blockIdx.x, h = blockIdx.y, b = blockIdx.z;
    const int tid = threadIdx.x;
    const int wid = tid >> 5, lane = tid & 31;
    const int wm = (wid >> 1) * 32, wn = (wid & 1) * 32;

    const char* pA = (const char*)(Uf + ((size_t)(b * HH + h) * LT) * LV + st * 128);
    const char* pB = (const char*)(Tf + ((size_t)(b * HH + h) * LT) * HD);

    auto issue = [&](int kt, int s) {
        const uint32_t st0 = sb + s * AO_STAGE;
#pragma unroll
        for (int i = 0; i < 2; i++) {
            int id = tid + i * 256;
            int r = id >> 4, c = id & 15;
            cp_async16(st0 + r * AO_AROW + c * 16,
                       pA + ((size_t)kt * 32 + r) * LV * 2 + c * 16);
        }
        {
            int r = tid >> 3, c = tid & 7;
            cp_async16(st0 + AO_ATILE + r * AO_BROW + c * 16,
                       pB + ((size_t)kt * 32 + r) * HD * 2 + c * 16);
        }
        cp_commit();
    };

    float acc[2][4][4];
#pragma unroll
    for (int i = 0; i < 2; i++)
#pragma unroll
        for (int j = 0; j < 4; j++)
#pragma unroll
            for (int k = 0; k < 4; k++) acc[i][j][k] = 0.f;

    issue(0, 0);
    for (int kt = 0; kt < 4; kt++) {
        if (kt + 1 < 4) { issue(kt + 1, (kt + 1) & 1); cp_wait<1>(); }
        else cp_wait<0>();
        __syncthreads();

        const uint32_t st0 = sb + (kt & 1) * AO_STAGE;
        const uint32_t Aus = st0, Bfs = st0 + AO_ATILE;

#pragma unroll
        for (int ks = 0; ks < 2; ks++) {
            const int k16 = ks * 16;
            uint32_t au[2][4];
#pragma unroll
            for (int mi = 0; mi < 2; mi++) {
                int trow = k16 + ((lane >> 4) << 3) + (lane & 7);
                int scol = wm + mi * 16 + (((lane >> 3) & 1) << 3);
                ldm_x4_t(au[mi], Aus + trow * AO_AROW + scol * 2);
            }
            uint32_t bf[2][4];
#pragma unroll
            for (int bi = 0; bi < 2; bi++) {
                int trow = k16 + ((lane >> 4) << 3) + (lane & 7);
                int dcol = wn + bi * 16 + (((lane >> 3) & 1) << 3);
                ldm_x4_t(bf[bi], Bfs + trow * AO_BROW + dcol * 2);
            }
#pragma unroll
            for (int mi = 0; mi < 2; mi++)
#pragma unroll
                for (int nb = 0; nb < 4; nb++) {
                    const int bi = nb >> 1, j = nb & 1;
                    mma_hv(acc[mi][nb], au[mi], bf[bi][j], bf[bi][j + 2]);
                }
        }
        __syncthreads();
    }

    const float inv = 1.f / TSCALE;
    const int gid = lane >> 2, tig = lane & 3;
#pragma unroll
    for (int mi = 0; mi < 2; mi++) {
        int srow = st * 128 + wm + mi * 16 + gid;
#pragma unroll
        for (int nb = 0; nb < 4; nb++) {
            int c = h * HD + wn + nb * 8 + tig * 2;
            size_t o0 = ((size_t)b * LV + srow) * DD + c;
            size_t o1 = ((size_t)b * LV + srow + 8) * DD + c;
            *(__half2*)(Of + o0) = __halves2half2(
                __float2half_rn(acc[mi][nb][0] * inv), __float2half_rn(acc[mi][nb][1] * inv));
            *(__half2*)(Of + o1) = __halves2half2(
                __float2half_rn(acc[mi][nb][2] * inv), __float2half_rn(acc[mi][nb][3] * inv));
        }
    }
}

// ===========================================================================
// Launch
// ===========================================================================
extern "C" void kernel_launch(void* const* d_in, const int* in_sizes, int n_in,
                              void* d_out, int out_size)
{
    const float* hidden = (const float*)d_in[0];
    const float* text   = (const float*)d_in[1];
    const float* Wq = (const float*)d_in[2];
    const float* bq = (const float*)d_in[3];
    const float* Wk = (const float*)d_in[4];
    const float* bk = (const float*)d_in[5];
    const float* Wv = (const float*)d_in[6];
    const float* bv = (const float*)d_in[7];
    const float* Wo = (const float*)d_in[8];
    const float* bo = (const float*)d_in[9];
    float* out = (float*)d_out;

    __half *txf, *hdf, *Wt, *Qf, *Kf, *Vf, *Uf, *Tf, *Of;
    float *Pp, *scl, *Tp, *bkv;
    cudaGetSymbolAddress((void**)&txf, g_txf);
    cudaGetSymbolAddress((void**)&hdf, g_hdf);
    cudaGetSymbolAddress((void**)&Wt, g_Wt);
    cudaGetSymbolAddress((void**)&bkv, g_bkv);
    cudaGetSymbolAddress((void**)&Qf, g_Qf);
    cudaGetSymbolAddress((void**)&Kf, g_Kf);
    cudaGetSymbolAddress((void**)&Vf, g_Vf);
    cudaGetSymbolAddress((void**)&Uf, g_Uf);
    cudaGetSymbolAddress((void**)&Pp, g_Pp);
    cudaGetSymbolAddress((void**)&scl, g_scale);
    cudaGetSymbolAddress((void**)&Tp, g_Tp);
    cudaGetSymbolAddress((void**)&Tf, g_Tf);
    cudaGetSymbolAddress((void**)&Of, g_Of);

    cudaFuncSetAttribute(gemm_f16<0>, cudaFuncAttributeMaxDynamicSharedMemorySize, SMEM_GEMM);
    cudaFuncSetAttribute(gemm_f16<2>, cudaFuncAttributeMaxDynamicSharedMemorySize, SMEM_GEMM);
    cudaFuncSetAttribute(gemm_f16<3>, cudaFuncAttributeMaxDynamicSharedMemorySize, SMEM_GEMM);
    cudaFuncSetAttribute(attn_scores_exp, cudaFuncAttributeMaxDynamicSharedMemorySize, SMEM_SC);
    cudaFuncSetAttribute(attn_pv_mma, cudaFuncAttributeMaxDynamicSharedMemorySize, SMEM_PV);
    cudaFuncSetAttribute(attn_out_mma, cudaFuncAttributeMaxDynamicSharedMemorySize, SMEM_AO);

    const size_t WSZ = (size_t)DD * DD;

    // 1. input converts
    conv_h<<<(BB * LT * DD) / 1024, 256>>>(text, txf, (size_t)BB * LT * DD);
    conv_h<<<(BB * LV * DD) / 1024, 256>>>(hidden, hdf, (size_t)BB * LV * DD);

    // 2. weight transpose + bias concat
    dim3 wt(32, 32);
    wtrans_h<<<wt, dim3(32, 8)>>>(Wq, Wt + 0 * WSZ);
    wtrans_h<<<wt, dim3(32, 8)>>>(Wk, Wt + 1 * WSZ);
    wtrans_h<<<wt, dim3(32, 8)>>>(Wv, Wt + 2 * WSZ);
    wtrans_h<<<wt, dim3(32, 8)>>>(Wo, Wt + 3 * WSZ);
    concat_bias<<<8, 256>>>(bk, bv, bkv);

    // 3. projections: Q (fp16 out), fused K+V (fp16 split out)
    gemm_f16<2><<<dim3(DD / 128, (BB * LT) / 128), 256, SMEM_GEMM>>>(
        txf, Wt + 0 * WSZ, bq, nullptr, Qf, nullptr,
        BB * LT, DD, DD, DD, DD, DD, QSCALE);
    gemm_f16<3><<<dim3(2 * DD / 128, (BB * LV) / 128), 256, SMEM_GEMM>>>(
        hdf, Wt + 1 * WSZ, bkv, nullptr, Kf, Vf,
        BB * LV, 2 * DD, DD, DD, DD, DD, 1.0f);

    // 4. attention
    attn_scores_exp<<<dim3(LV / 128, HH, BB), 256, SMEM_SC>>>(Qf, Kf, Uf, Pp);
    reduce_scale<<<BB * HH * LT / 256, 256>>>(Pp, scl);
    attn_pv_mma<<<dim3(8, HH, BB), 256, SMEM_PV>>>(Uf, Vf, Tp);
    reduce_T<<<(BB * HH * LT * HD) / 256, 256>>>(Tp, scl, Tf);
    attn_out_mma<<<dim3(LV / 128, HH, BB), 256, SMEM_AO>>>(Uf, Tf, Of);

    // 5. output projection -> fp32 out
    gemm_f16<0><<<dim3(DD / 128, (BB * LV) / 128), 256, SMEM_GEMM>>>(
        Of, Wt + 3 * WSZ, bo, out, nullptr, nullptr,
        BB * LV, DD, DD, DD, DD, DD, 1.0f);
}

// round 9
// speedup vs baseline: 5.9754x; 1.4140x over previous
#include <cuda_runtime.h>
#include <cuda_fp16.h>
#include <cstdint>
#include <cstddef>

// Problem constants
#define BB 16
#define LT 128
#define LV 4096
#define DD 1024
#define HH 16
#define HD 64
static constexpr float QSCALE = 0.125f;   // 64^-0.5
static constexpr float TSCALE = 65536.f;  // keeps Tf in fp16 normal range

// ===========================================================================
// Scratch (device globals) — all single fp16
// ===========================================================================
__device__ __half g_txf[(size_t)BB * LT * DD];
__device__ __half g_hdf[(size_t)BB * LV * DD];
__device__ __half g_Wt[4][(size_t)DD * DD];        // W^T fp16 (N,K); 1=Wk,2=Wv adjacent
__device__ float  g_bkv[2 * DD];
__device__ __half g_Qf[(size_t)BB * LT * DD];
__device__ __half g_Kf[(size_t)BB * LV * DD];
__device__ __half g_Vf[(size_t)BB * LV * DD];
__device__ __half g_Uf[(size_t)BB * HH * LT * LV]; // exp(S) unnormalized
__device__ float  g_Pp[(size_t)BB * HH * LT * 32]; // row partial sums (32 s-tiles)
__device__ float  g_scale[(size_t)BB * HH * LT];   // 2^16 / D^2
__device__ float  g_Tp[8][(size_t)BB * HH * LT * HD];
__device__ __half g_Tf[(size_t)BB * HH * LT * HD]; // Y/D^2 * 2^16
__device__ __half g_Of[(size_t)BB * LV * DD];

// ===========================================================================
// PTX helpers
// ===========================================================================
__device__ __forceinline__ uint32_t smem_u32(const void* p) {
    uint32_t a;
    asm("{ .reg .u64 t; cvta.to.shared.u64 t, %1; cvt.u32.u64 %0, t; }" : "=r"(a) : "l"(p));
    return a;
}
__device__ __forceinline__ void cp_async16(uint32_t dst, const void* src) {
    asm volatile("cp.async.cg.shared.global [%0], [%1], 16;" :: "r"(dst), "l"(src));
}
__device__ __forceinline__ void cp_commit() { asm volatile("cp.async.commit_group;"); }
template <int N>
__device__ __forceinline__ void cp_wait() { asm volatile("cp.async.wait_group %0;" :: "n"(N)); }

__device__ __forceinline__ void ldm_x4(uint32_t* r, uint32_t addr) {
    asm volatile("ldmatrix.sync.aligned.m8n8.x4.shared.b16 {%0,%1,%2,%3}, [%4];"
                 : "=r"(r[0]), "=r"(r[1]), "=r"(r[2]), "=r"(r[3]) : "r"(addr));
}
__device__ __forceinline__ void ldm_x4_t(uint32_t* r, uint32_t addr) {
    asm volatile("ldmatrix.sync.aligned.m8n8.x4.trans.shared.b16 {%0,%1,%2,%3}, [%4];"
                 : "=r"(r[0]), "=r"(r[1]), "=r"(r[2]), "=r"(r[3]) : "r"(addr));
}
__device__ __forceinline__ void mma_h(float* c, const uint32_t* a, const uint32_t* b) {
    asm volatile(
        "mma.sync.aligned.m16n8k16.row.col.f32.f16.f16.f32 "
        "{%0,%1,%2,%3}, {%4,%5,%6,%7}, {%8,%9}, {%0,%1,%2,%3};"
        : "+f"(c[0]), "+f"(c[1]), "+f"(c[2]), "+f"(c[3])
        : "r"(a[0]), "r"(a[1]), "r"(a[2]), "r"(a[3]), "r"(b[0]), "r"(b[1]));
}
__device__ __forceinline__ void mma_hv(float* c, const uint32_t* a, uint32_t b0, uint32_t b1) {
    asm volatile(
        "mma.sync.aligned.m16n8k16.row.col.f32.f16.f16.f32 "
        "{%0,%1,%2,%3}, {%4,%5,%6,%7}, {%8,%9}, {%0,%1,%2,%3};"
        : "+f"(c[0]), "+f"(c[1]), "+f"(c[2]), "+f"(c[3])
        : "r"(a[0]), "r"(a[1]), "r"(a[2]), "r"(a[3]), "r"(b0), "r"(b1));
}

// ===========================================================================
// fp32 -> fp16 convert
// ===========================================================================
__global__ __launch_bounds__(256) void conv_h(
    const float* __restrict__ in, __half* __restrict__ o, size_t n)
{
    size_t i = ((size_t)blockIdx.x * 256 + threadIdx.x) * 4;
    if (i >= n) return;
    float4 v = *(const float4*)(in + i);
    __half2* op = (__half2*)(o + i);
    op[0] = __halves2half2(__float2half_rn(v.x), __float2half_rn(v.y));
    op[1] = __halves2half2(__float2half_rn(v.z), __float2half_rn(v.w));
}

// ===========================================================================
// Weight transpose to fp16 + bias concat
// ===========================================================================
__global__ __launch_bounds__(256) void wtrans_h(
    const float* __restrict__ W, __half* __restrict__ Wt)
{
    __shared__ float t[32][33];
    int bx = blockIdx.x, by = blockIdx.y;
    int x = threadIdx.x, y = threadIdx.y;
#pragma unroll
    for (int i = 0; i < 32; i += 8)
        t[y + i][x] = W[(size_t)(by * 32 + y + i) * DD + bx * 32 + x];
    __syncthreads();
#pragma unroll
    for (int i = 0; i < 32; i += 8)
        Wt[(size_t)(bx * 32 + y + i) * DD + by * 32 + x] = __float2half_rn(t[x][y + i]);
}

__global__ __launch_bounds__(256) void concat_bias(
    const float* __restrict__ bk, const float* __restrict__ bv, float* __restrict__ b2)
{
    int i = blockIdx.x * 256 + threadIdx.x;
    if (i < DD) b2[i] = bk[i];
    else if (i < 2 * DD) b2[i] = bv[i - DD];
}

// ===========================================================================
// HMMA fp16 GEMM: C = alpha*(A @ B^T + bias)
// Tile 256x128, BK=64, 8 warps 4x2 (warp 64x64), 2-stage cp.async.
// OUTMODE 0: fp32 C.  2: fp16 single (Ch).  3: fp16 split KV (Ch=K, Cl=V).
// ===========================================================================
#define ROWB 144                        // 64 fp16 = 128 B + 16 pad
#define A_TILE (256 * ROWB)             // 36864
#define B_TILE (128 * ROWB)             // 18432
#define STAGE_B (A_TILE + B_TILE)       // 55296
#define SMEM_GEMM (2 * STAGE_B)         // 110592

template <int OUTMODE>
__global__ __launch_bounds__(256, 1) void gemm_f16(
    const __half* __restrict__ A, const __half* __restrict__ B,
    const float* __restrict__ bias, float* __restrict__ C,
    __half* __restrict__ Ch, __half* __restrict__ Cl,
    int M, int N, int K, int lda, int ldb, int ldc, float alpha)
{
    extern __shared__ char smem[];
    const uint32_t sb = smem_u32(smem);
    const int tid = threadIdx.x;
    const int wid = tid >> 5, lane = tid & 31;
    const int m0 = blockIdx.y * 256, n0 = blockIdx.x * 128;
    const int wm = (wid >> 1) * 64;
    const int wn = (wid & 1) * 64;

    const char* gAp = (const char*)(A + (size_t)m0 * lda);
    const char* gBp = (const char*)(B + (size_t)n0 * ldb);

    float acc[4][8][4];
#pragma unroll
    for (int i = 0; i < 4; i++)
#pragma unroll
        for (int j = 0; j < 8; j++)
#pragma unroll
            for (int k = 0; k < 4; k++) acc[i][j][k] = 0.f;

    const int NT = K / 64;

    auto issue = [&](int kt, int s) {
        const uint32_t st0 = sb + s * STAGE_B;
        const char* gA = gAp + (size_t)kt * 128;
        const char* gB = gBp + (size_t)kt * 128;
        const int ldab = lda * 2, ldbb = ldb * 2;
#pragma unroll
        for (int i = 0; i < 8; i++) {           // A: 2048 chunks
            int id = tid + i * 256;
            int r = id >> 3, c = id & 7;
            cp_async16(st0 + r * ROWB + c * 16, gA + (size_t)r * ldab + c * 16);
        }
#pragma unroll
        for (int i = 0; i < 4; i++) {           // B: 1024 chunks
            int id = tid + i * 256;
            int r = id >> 3, c = id & 7;
            cp_async16(st0 + A_TILE + r * ROWB + c * 16, gB + (size_t)r * ldbb + c * 16);
        }
        cp_commit();
    };

    issue(0, 0);

    for (int kt = 0; kt < NT; kt++) {
        if (kt + 1 < NT) { issue(kt + 1, (kt + 1) & 1); cp_wait<1>(); }
        else cp_wait<0>();
        __syncthreads();

        const uint32_t st0 = sb + (kt & 1) * STAGE_B;
        const uint32_t Afs = st0;
        const uint32_t Bfs = st0 + A_TILE;

#pragma unroll
        for (int ks = 0; ks < 4; ks++) {
            const int k16 = ks * 16;
            uint32_t af[4][4];
#pragma unroll
            for (int mi = 0; mi < 4; mi++) {
                int row = wm + mi * 16 + (lane & 15);
                int col = k16 + ((lane >> 4) << 3);
                ldm_x4(af[mi], Afs + row * ROWB + col * 2);
            }
            uint32_t bf[4][4];
#pragma unroll
            for (int bi = 0; bi < 4; bi++) {
                int nrow = wn + bi * 16 + (lane & 7) + ((lane >> 4) << 3);
                int col = k16 + (((lane >> 3) & 1) << 3);
                ldm_x4(bf[bi], Bfs + nrow * ROWB + col * 2);
            }
#pragma unroll
            for (int mi = 0; mi < 4; mi++)
#pragma unroll
                for (int nb = 0; nb < 8; nb++)
                    mma_h(acc[mi][nb], af[mi], &bf[nb >> 1][(nb & 1) * 2]);
        }
        __syncthreads();
    }

    const int gid = lane >> 2, tig = lane & 3;
    __half* dst3 = (OUTMODE == 3) ? ((n0 < DD) ? Ch : Cl) : Ch;
    const int nbase = (OUTMODE == 3 && n0 >= DD) ? n0 - DD : n0;

#pragma unroll
    for (int mi = 0; mi < 4; mi++) {
        int r0 = m0 + wm + mi * 16 + gid;
#pragma unroll
        for (int nb = 0; nb < 8; nb++) {
            int c = n0 + wn + nb * 8 + tig * 2;
            float b0 = __ldg(&bias[c]), b1 = __ldg(&bias[c + 1]);
            float v00 = alpha * (acc[mi][nb][0] + b0);
            float v01 = alpha * (acc[mi][nb][1] + b1);
            float v10 = alpha * (acc[mi][nb][2] + b0);
            float v11 = alpha * (acc[mi][nb][3] + b1);
            if (OUTMODE == 0) {
                *(float2*)(C + (size_t)r0 * ldc + c) = make_float2(v00, v01);
                *(float2*)(C + (size_t)(r0 + 8) * ldc + c) = make_float2(v10, v11);
            } else {
                int cl = nbase + wn + nb * 8 + tig * 2;
                *(__half2*)(dst3 + (size_t)r0 * DD + cl) =
                    __halves2half2(__float2half_rn(v00), __float2half_rn(v01));
                *(__half2*)(dst3 + (size_t)(r0 + 8) * DD + cl) =
                    __halves2half2(__float2half_rn(v10), __float2half_rn(v11));
            }
        }
    }
}

// ===========================================================================
// Scores + exp fused: U = exp(Qf.Kf), fp16 out + per-row partial sums
// M=128 t, N=128 s-tile, K=64. grid (LV/128, HH, BB)
// ===========================================================================
#define SROWB 144
#define STILE (128 * SROWB)
#define SMEM_SC (2 * STILE)            // 36864

__global__ __launch_bounds__(256) void attn_scores_exp(
    const __half* __restrict__ Qf, const __half* __restrict__ Kf,
    __half* __restrict__ Uf, float* __restrict__ Pp)
{
    extern __shared__ char smem[];
    const uint32_t sb = smem_u32(smem);
    const int st = blockIdx.x, h = blockIdx.y, b = blockIdx.z;
    const int tid = threadIdx.x;
    const int wid = tid >> 5, lane = tid & 31;
    const int wm = (wid >> 1) * 32, wn = (wid & 1) * 64;

    const char* gp[2] = {
        (const char*)(Qf + ((size_t)b * LT) * DD + h * HD),
        (const char*)(Kf + ((size_t)b * LV + st * 128) * DD + h * HD) };

#pragma unroll
    for (int i = 0; i < 8; i++) {
        int id = tid + i * 256;
        int t = id >> 10, r = (id >> 3) & 127, c = id & 7;
        cp_async16(sb + t * STILE + r * SROWB + c * 16,
                   gp[t] + (size_t)r * DD * 2 + c * 16);
    }
    cp_commit();
    cp_wait<0>();
    __syncthreads();

    float acc[2][8][4];
#pragma unroll
    for (int i = 0; i < 2; i++)
#pragma unroll
        for (int j = 0; j < 8; j++)
#pragma unroll
            for (int k = 0; k < 4; k++) acc[i][j][k] = 0.f;

    const uint32_t Afs = sb, Bfs = sb + STILE;

#pragma unroll
    for (int ks = 0; ks < 4; ks++) {
        const int k16 = ks * 16;
        uint32_t af[2][4];
#pragma unroll
        for (int mi = 0; mi < 2; mi++) {
            int row = wm + mi * 16 + (lane & 15);
            int col = k16 + ((lane >> 4) << 3);
            ldm_x4(af[mi], Afs + row * SROWB + col * 2);
        }
        uint32_t bf[4][4];
#pragma unroll
        for (int bi = 0; bi < 4; bi++) {
            int nrow = wn + bi * 16 + (lane & 7) + ((lane >> 4) << 3);
            int col = k16 + (((lane >> 3) & 1) << 3);
            ldm_x4(bf[bi], Bfs + nrow * SROWB + col * 2);
        }
#pragma unroll
        for (int mi = 0; mi < 2; mi++)
#pragma unroll
            for (int nb = 0; nb < 8; nb++)
                mma_h(acc[mi][nb], af[mi], &bf[nb >> 1][(nb & 1) * 2]);
    }

    __half* Ub = Uf + ((size_t)(b * HH + h) * LT) * LV + st * 128;
    const int gid = lane >> 2, tig = lane & 3;
    float ls[4] = {0.f, 0.f, 0.f, 0.f};
#pragma unroll
    for (int mi = 0; mi < 2; mi++) {
        int r0 = wm + mi * 16 + gid;
#pragma unroll
        for (int nb = 0; nb < 8; nb++) {
            int c = wn + nb * 8 + tig * 2;
            float u00 = __expf(acc[mi][nb][0]);
            float u01 = __expf(acc[mi][nb][1]);
            float u10 = __expf(acc[mi][nb][2]);
            float u11 = __expf(acc[mi][nb][3]);
            ls[mi * 2 + 0] += u00 + u01;
            ls[mi * 2 + 1] += u10 + u11;
            *(__half2*)(Ub + (size_t)r0 * LV + c) =
                __halves2half2(__float2half_rn(u00), __float2half_rn(u01));
            *(__half2*)(Ub + (size_t)(r0 + 8) * LV + c) =
                __halves2half2(__float2half_rn(u10), __float2half_rn(u11));
        }
    }
#pragma unroll
    for (int j = 0; j < 4; j++) {
        ls[j] += __shfl_xor_sync(0xFFFFFFFF, ls[j], 1);
        ls[j] += __shfl_xor_sync(0xFFFFFFFF, ls[j], 2);
    }
    __syncthreads();
    float* sums = (float*)smem;      // [128][2]
    if (tig == 0) {
#pragma unroll
        for (int j = 0; j < 4; j++) {
            int mi = j >> 1, half = j & 1;
            int row = wm + mi * 16 + gid + 8 * half;
            sums[row * 2 + (wid & 1)] = ls[j];
        }
    }
    __syncthreads();
    if (tid < 128) {
        float d = sums[tid * 2] + sums[tid * 2 + 1];
        Pp[(((size_t)(b * HH + h) * LT) + tid) * 32 + st] = d;
    }
}

// ===========================================================================
// Row scale: scale = 2^16 / D^2
// ===========================================================================
__global__ __launch_bounds__(256) void reduce_scale(
    const float* __restrict__ Pp, float* __restrict__ scale)
{
    int r = blockIdx.x * 256 + threadIdx.x;
    float d = 0.f;
#pragma unroll
    for (int j = 0; j < 32; j++) d += Pp[(size_t)r * 32 + j];
    scale[r] = TSCALE / (d * d);
}

// ===========================================================================
// PV: Ypart = Uf[128t, 512s] @ Vf[512s, 64d]. grid (8, HH, BB)
// ===========================================================================
#define PV_AROW 80
#define PV_ATILE (128 * PV_AROW)        // 10240
#define PV_BROW 144
#define PV_BTILE (32 * PV_BROW)         // 4608
#define PV_STAGE (PV_ATILE + PV_BTILE)  // 14848
#define SMEM_PV (2 * PV_STAGE)          // 29696

__global__ __launch_bounds__(256) void attn_pv_mma(
    const __half* __restrict__ Uf, const __half* __restrict__ Vf,
    float* __restrict__ Tp)
{
    extern __shared__ char smem[];
    const uint32_t sb = smem_u32(smem);
    const int seg = blockIdx.x, h = blockIdx.y, b = blockIdx.z;
    const int tid = threadIdx.x;
    const int wid = tid >> 5, lane = tid & 31;
    const int wm = (wid >> 1) * 32, wn = (wid & 1) * 32;

    const char* pA = (const char*)(Uf + ((size_t)(b * HH + h) * LT) * LV + seg * 512);
    const char* pB = (const char*)(Vf + ((size_t)b * LV + seg * 512) * DD + h * HD);

    auto issue = [&](int kt, int s) {
        const uint32_t st0 = sb + s * PV_STAGE;
#pragma unroll
        for (int i = 0; i < 2; i++) {
            int id = tid + i * 256;
            int r = id >> 2, c = id & 3;
            cp_async16(st0 + r * PV_AROW + c * 16,
                       pA + (size_t)r * LV * 2 + (size_t)kt * 64 + c * 16);
        }
        {
            int r = tid >> 3, c = tid & 7;
            cp_async16(st0 + PV_ATILE + r * PV_BROW + c * 16,
                       pB + ((size_t)kt * 32 + r) * DD * 2 + c * 16);
        }
        cp_commit();
    };

    float acc[2][4][4];
#pragma unroll
    for (int i = 0; i < 2; i++)
#pragma unroll
        for (int j = 0; j < 4; j++)
#pragma unroll
            for (int k = 0; k < 4; k++) acc[i][j][k] = 0.f;

    issue(0, 0);
    for (int kt = 0; kt < 16; kt++) {
        if (kt + 1 < 16) { issue(kt + 1, (kt + 1) & 1); cp_wait<1>(); }
        else cp_wait<0>();
        __syncthreads();

        const uint32_t st0 = sb + (kt & 1) * PV_STAGE;
        const uint32_t Aus = st0, Bfs = st0 + PV_ATILE;

#pragma unroll
        for (int ks = 0; ks < 2; ks++) {
            const int k16 = ks * 16;
            uint32_t au[2][4];
#pragma unroll
            for (int mi = 0; mi < 2; mi++) {
                int row = wm + mi * 16 + (lane & 15);
                int col = k16 + ((lane >> 4) << 3);
                ldm_x4(au[mi], Aus + row * PV_AROW + col * 2);
            }
            uint32_t bf[2][4];
#pragma unroll
            for (int bi = 0; bi < 2; bi++) {
                int srow = k16 + ((lane >> 4) << 3) + (lane & 7);
                int dcol = wn + bi * 16 + (((lane >> 3) & 1) << 3);
                ldm_x4_t(bf[bi], Bfs + srow * PV_BROW + dcol * 2);
            }
#pragma unroll
            for (int mi = 0; mi < 2; mi++)
#pragma unroll
                for (int nb = 0; nb < 4; nb++) {
                    const int bi = nb >> 1, j = nb & 1;
                    mma_hv(acc[mi][nb], au[mi], bf[bi][j], bf[bi][j + 2]);
                }
        }
        __syncthreads();
    }

    float* Tb = Tp + (size_t)seg * (BB * HH * LT * HD) + ((size_t)(b * HH + h) * LT) * HD;
    const int gid = lane >> 2, tig = lane & 3;
#pragma unroll
    for (int mi = 0; mi < 2; mi++) {
        int r0 = wm + mi * 16 + gid;
#pragma unroll
        for (int nb = 0; nb < 4; nb++) {
            int c = wn + nb * 8 + tig * 2;
            *(float2*)(Tb + (size_t)r0 * HD + c) = make_float2(acc[mi][nb][0], acc[mi][nb][1]);
            *(float2*)(Tb + (size_t)(r0 + 8) * HD + c) = make_float2(acc[mi][nb][2], acc[mi][nb][3]);
        }
    }
}

// reduce partials + apply 2^16/D^2
__global__ __launch_bounds__(256) void reduce_T(
    const float* __restrict__ Tp, const float* __restrict__ scale,
    __half* __restrict__ Tf)
{
    size_t i = (size_t)blockIdx.x * 256 + threadIdx.x;
    float s = 0.f;
#pragma unroll
    for (int g = 0; g < 8; g++) s += Tp[(size_t)g * (BB * HH * LT * HD) + i];
    Tf[i] = __float2half_rn(s * scale[i >> 6]);
}

// ===========================================================================
// OUT: O[128s, 64d] = 2^-16 * U^T[128s,128t] @ Tf[128t, 64d] -> fp16 single
// ===========================================================================
#define AO_AROW 272
#define AO_ATILE (32 * AO_AROW)         // 8704
#define AO_BROW 144
#define AO_BTILE (32 * AO_BROW)         // 4608
#define AO_STAGE (AO_ATILE + AO_BTILE)  // 13312
#define SMEM_AO (2 * AO_STAGE)          // 26624

__global__ __launch_bounds__(256) void attn_out_mma(
    const __half* __restrict__ Uf, const __half* __restrict__ Tf,
    __half* __restrict__ Of)
{
    extern __shared__ char smem[];
    const uint32_t sb = smem_u32(smem);
    const int st = blockIdx.x, h = blockIdx.y, b = blockIdx.z;
    const int tid = threadIdx.x;
    const int wid = tid >> 5, lane = tid & 31;
    const int wm = (wid >> 1) * 32, wn = (wid & 1) * 32;

    const char* pA = (const char*)(Uf + ((size_t)(b * HH + h) * LT) * LV + st * 128);
    const char* pB = (const char*)(Tf + ((size_t)(b * HH + h) * LT) * HD);

    auto issue = [&](int kt, int s) {
        const uint32_t st0 = sb + s * AO_STAGE;
#pragma unroll
        for (int i = 0; i < 2; i++) {
            int id = tid + i * 256;
            int r = id >> 4, c = id & 15;
            cp_async16(st0 + r * AO_AROW + c * 16,
                       pA + ((size_t)kt * 32 + r) * LV * 2 + c * 16);
        }
        {
            int r = tid >> 3, c = tid & 7;
            cp_async16(st0 + AO_ATILE + r * AO_BROW + c * 16,
                       pB + ((size_t)kt * 32 + r) * HD * 2 + c * 16);
        }
        cp_commit();
    };

    float acc[2][4][4];
#pragma unroll
    for (int i = 0; i < 2; i++)
#pragma unroll
        for (int j = 0; j < 4; j++)
#pragma unroll
            for (int k = 0; k < 4; k++) acc[i][j][k] = 0.f;

    issue(0, 0);
    for (int kt = 0; kt < 4; kt++) {
        if (kt + 1 < 4) { issue(kt + 1, (kt + 1) & 1); cp_wait<1>(); }
        else cp_wait<0>();
        __syncthreads();

        const uint32_t st0 = sb + (kt & 1) * AO_STAGE;
        const uint32_t Aus = st0, Bfs = st0 + AO_ATILE;

#pragma unroll
        for (int ks = 0; ks < 2; ks++) {
            const int k16 = ks * 16;
            uint32_t au[2][4];
#pragma unroll
            for (int mi = 0; mi < 2; mi++) {
                int trow = k16 + ((lane >> 4) << 3) + (lane & 7);
                int scol = wm + mi * 16 + (((lane >> 3) & 1) << 3);
                ldm_x4_t(au[mi], Aus + trow * AO_AROW + scol * 2);
            }
            uint32_t bf[2][4];
#pragma unroll
            for (int bi = 0; bi < 2; bi++) {
                int trow = k16 + ((lane >> 4) << 3) + (lane & 7);
                int dcol = wn + bi * 16 + (((lane >> 3) & 1) << 3);
                ldm_x4_t(bf[bi], Bfs + trow * AO_BROW + dcol * 2);
            }
#pragma unroll
            for (int mi = 0; mi < 2; mi++)
#pragma unroll
                for (int nb = 0; nb < 4; nb++) {
                    const int bi = nb >> 1, j = nb & 1;
                    mma_hv(acc[mi][nb], au[mi], bf[bi][j], bf[bi][j + 2]);
                }
        }
        __syncthreads();
    }

    const float inv = 1.f / TSCALE;
    const int gid = lane >> 2, tig = lane & 3;
#pragma unroll
    for (int mi = 0; mi < 2; mi++) {
        int srow = st * 128 + wm + mi * 16 + gid;
#pragma unroll
        for (int nb = 0; nb < 4; nb++) {
            int c = h * HD + wn + nb * 8 + tig * 2;
            size_t o0 = ((size_t)b * LV + srow) * DD + c;
            size_t o1 = ((size_t)b * LV + srow + 8) * DD + c;
            *(__half2*)(Of + o0) = __halves2half2(
                __float2half_rn(acc[mi][nb][0] * inv), __float2half_rn(acc[mi][nb][1] * inv));
            *(__half2*)(Of + o1) = __halves2half2(
                __float2half_rn(acc[mi][nb][2] * inv), __float2half_rn(acc[mi][nb][3] * inv));
        }
    }
}

// ===========================================================================
// Launch
// ===========================================================================
extern "C" void kernel_launch(void* const* d_in, const int* in_sizes, int n_in,
                              void* d_out, int out_size)
{
    const float* hidden = (const float*)d_in[0];
    const float* text   = (const float*)d_in[1];
    const float* Wq = (const float*)d_in[2];
    const float* bq = (const float*)d_in[3];
    const float* Wk = (const float*)d_in[4];
    const float* bk = (const float*)d_in[5];
    const float* Wv = (const float*)d_in[6];
    const float* bv = (const float*)d_in[7];
    const float* Wo = (const float*)d_in[8];
    const float* bo = (const float*)d_in[9];
    float* out = (float*)d_out;

    __half *txf, *hdf, *Wt, *Qf, *Kf, *Vf, *Uf, *Tf, *Of;
    float *Pp, *scl, *Tp, *bkv;
    cudaGetSymbolAddress((void**)&txf, g_txf);
    cudaGetSymbolAddress((void**)&hdf, g_hdf);
    cudaGetSymbolAddress((void**)&Wt, g_Wt);
    cudaGetSymbolAddress((void**)&bkv, g_bkv);
    cudaGetSymbolAddress((void**)&Qf, g_Qf);
    cudaGetSymbolAddress((void**)&Kf, g_Kf);
    cudaGetSymbolAddress((void**)&Vf, g_Vf);
    cudaGetSymbolAddress((void**)&Uf, g_Uf);
    cudaGetSymbolAddress((void**)&Pp, g_Pp);
    cudaGetSymbolAddress((void**)&scl, g_scale);
    cudaGetSymbolAddress((void**)&Tp, g_Tp);
    cudaGetSymbolAddress((void**)&Tf, g_Tf);
    cudaGetSymbolAddress((void**)&Of, g_Of);

    cudaFuncSetAttribute(gemm_f16<0>, cudaFuncAttributeMaxDynamicSharedMemorySize, SMEM_GEMM);
    cudaFuncSetAttribute(gemm_f16<2>, cudaFuncAttributeMaxDynamicSharedMemorySize, SMEM_GEMM);
    cudaFuncSetAttribute(gemm_f16<3>, cudaFuncAttributeMaxDynamicSharedMemorySize, SMEM_GEMM);
    cudaFuncSetAttribute(attn_scores_exp, cudaFuncAttributeMaxDynamicSharedMemorySize, SMEM_SC);
    cudaFuncSetAttribute(attn_pv_mma, cudaFuncAttributeMaxDynamicSharedMemorySize, SMEM_PV);
    cudaFuncSetAttribute(attn_out_mma, cudaFuncAttributeMaxDynamicSharedMemorySize, SMEM_AO);

    const size_t WSZ = (size_t)DD * DD;

    // 1. input converts
    conv_h<<<(BB * LT * DD) / 1024, 256>>>(text, txf, (size_t)BB * LT * DD);
    conv_h<<<(BB * LV * DD) / 1024, 256>>>(hidden, hdf, (size_t)BB * LV * DD);

    // 2. weight transpose + bias concat
    dim3 wt(32, 32);
    wtrans_h<<<wt, dim3(32, 8)>>>(Wq, Wt + 0 * WSZ);
    wtrans_h<<<wt, dim3(32, 8)>>>(Wk, Wt + 1 * WSZ);
    wtrans_h<<<wt, dim3(32, 8)>>>(Wv, Wt + 2 * WSZ);
    wtrans_h<<<wt, dim3(32, 8)>>>(Wo, Wt + 3 * WSZ);
    concat_bias<<<8, 256>>>(bk, bv, bkv);

    // 3. projections: Q (fp16 out), fused K+V (fp16 split out). 256-row tiles.
    gemm_f16<2><<<dim3(DD / 128, (BB * LT) / 256), 256, SMEM_GEMM>>>(
        txf, Wt + 0 * WSZ, bq, nullptr, Qf, nullptr,
        BB * LT, DD, DD, DD, DD, DD, QSCALE);
    gemm_f16<3><<<dim3(2 * DD / 128, (BB * LV) / 256), 256, SMEM_GEMM>>>(
        hdf, Wt + 1 * WSZ, bkv, nullptr, Kf, Vf,
        BB * LV, 2 * DD, DD, DD, DD, DD, 1.0f);

    // 4. attention
    attn_scores_exp<<<dim3(LV / 128, HH, BB), 256, SMEM_SC>>>(Qf, Kf, Uf, Pp);
    reduce_scale<<<BB * HH * LT / 256, 256>>>(Pp, scl);
    attn_pv_mma<<<dim3(8, HH, BB), 256, SMEM_PV>>>(Uf, Vf, Tp);
    reduce_T<<<(BB * HH * LT * HD) / 256, 256>>>(Tp, scl, Tf);
    attn_out_mma<<<dim3(LV / 128, HH, BB), 256, SMEM_AO>>>(Uf, Tf, Of);

    // 5. output projection -> fp32 out
    gemm_f16<0><<<dim3(DD / 128, (BB * LV) / 256), 256, SMEM_GEMM>>>(
        Of, Wt + 3 * WSZ, bo, out, nullptr, nullptr,
        BB * LV, DD, DD, DD, DD, DD, 1.0f);
}